// round 10
// baseline (speedup 1.0000x reference)
#include <cuda_runtime.h>
#include <cuda_bf16.h>
#include <math.h>
#include <stdint.h>

#define HIDDEN 2048
#define NH 8
#define NKV 2
#define HD 256
#define BATCH 2
#define SEQ 2048
#define MTOT (BATCH*SEQ)            // 4096
#define QDIM (NH*HD)                // 2048
#define KVDIM (NKV*HD)              // 512
#define WPROWS (QDIM + 2*KVDIM)     // 3072

// ======================= PTX helpers =======================================
__device__ __forceinline__ uint32_t smem_to_u32(const void* p) {
    uint32_t a;
    asm("{ .reg .u64 t; cvta.to.shared.u64 t, %1; cvt.u32.u64 %0, t; }" : "=r"(a) : "l"(p));
    return a;
}
__device__ __forceinline__ void cp16(uint32_t dst, const void* src) {
    asm volatile("cp.async.cg.shared.global [%0], [%1], 16;" :: "r"(dst), "l"(src));
}
__device__ __forceinline__ void cp_commit() { asm volatile("cp.async.commit_group;" ::: "memory"); }
template<int N> __device__ __forceinline__ void cp_wait() {
    asm volatile("cp.async.wait_group %0;" :: "n"(N) : "memory");
}
#define LDSM_X4(r, addr) \
    asm volatile("ldmatrix.sync.aligned.m8n8.x4.shared.b16 {%0,%1,%2,%3}, [%4];" \
        : "=r"((r)[0]), "=r"((r)[1]), "=r"((r)[2]), "=r"((r)[3]) : "r"(addr))

__device__ __forceinline__ void mma16816(float* d, const uint32_t* a, uint32_t b0, uint32_t b1) {
    asm volatile("mma.sync.aligned.m16n8k16.row.col.f32.bf16.bf16.f32 "
        "{%0,%1,%2,%3}, {%4,%5,%6,%7}, {%8,%9}, {%0,%1,%2,%3};"
        : "+f"(d[0]), "+f"(d[1]), "+f"(d[2]), "+f"(d[3])
        : "r"(a[0]), "r"(a[1]), "r"(a[2]), "r"(a[3]), "r"(b0), "r"(b1));
}

// ======================= scratch (device globals) ==========================
__device__ __align__(16) __nv_bfloat16 g_hshi[(size_t)MTOT*HIDDEN], g_hslo[(size_t)MTOT*HIDDEN];
__device__ __align__(16) __nv_bfloat16 g_wphi[(size_t)WPROWS*HIDDEN], g_wplo[(size_t)WPROWS*HIDDEN];
__device__ __align__(16) __nv_bfloat16 g_wohi[(size_t)HIDDEN*QDIM], g_wolo[(size_t)HIDDEN*QDIM];
__device__ __align__(16) float g_qf[(size_t)MTOT*QDIM];
__device__ __align__(16) float g_kf[(size_t)BATCH*NKV*SEQ*HD];
__device__ __align__(16) float g_vf[(size_t)BATCH*NKV*SEQ*HD];
__device__ __align__(16) __nv_bfloat16 g_qhi[(size_t)MTOT*QDIM], g_qlo[(size_t)MTOT*QDIM];
__device__ __align__(16) __nv_bfloat16 g_khi[(size_t)BATCH*NKV*SEQ*HD], g_klo[(size_t)BATCH*NKV*SEQ*HD];
__device__ __align__(16) __nv_bfloat16 g_vthi[(size_t)BATCH*NKV*HD*SEQ], g_vtlo[(size_t)BATCH*NKV*HD*SEQ];
__device__ __align__(16) __nv_bfloat16 g_ahi[(size_t)MTOT*QDIM], g_alo[(size_t)MTOT*QDIM];
__device__ double g_invfreq[HD/2];
__device__ float g_cos[SEQ*(HD/2)];
__device__ float g_sin[SEQ*(HD/2)];

// ======================= small kernels =====================================
__global__ void k_invfreq() {
    int i = threadIdx.x;
    if (i < HD/2) g_invfreq[i] = pow(10000.0, -2.0 * (double)i / (double)HD);
}
__global__ void k_ropetab() {
    int s = blockIdx.x, i = threadIdx.x;
    double ang = (double)s * g_invfreq[i];
    const double twopi = 6.283185307179586476925286766559;
    ang -= floor(ang / twopi) * twopi;
    float c, sn;
    sincosf((float)ang, &sn, &c);
    g_cos[s*(HD/2)+i] = c;
    g_sin[s*(HD/2)+i] = sn;
}

__device__ __forceinline__ void split1(float x, unsigned short& h, unsigned short& l) {
    __nv_bfloat16 hb = __float2bfloat16(x);
    float r = x - __bfloat162float(hb);
    __nv_bfloat16 lb = __float2bfloat16(r);
    h = __bfloat16_as_ushort(hb);
    l = __bfloat16_as_ushort(lb);
}

// rope + split fused
__global__ void k_rope_split(const float* __restrict__ src,
                             __nv_bfloat16* __restrict__ hi,
                             __nv_bfloat16* __restrict__ lo) {
    int r = blockIdx.x, i = threadIdx.x;
    int s = r & (SEQ-1);
    float c = g_cos[s*(HD/2)+i], sn = g_sin[s*(HD/2)+i];
    const float* row = src + (size_t)r * HD;
    float x1 = row[i], x2 = row[i + HD/2];
    float o1 = x1*c - x2*sn;
    float o2 = x2*c + x1*sn;
    unsigned short h, l;
    split1(o1, h, l);
    hi[(size_t)r*HD + i] = __ushort_as_bfloat16(h);
    lo[(size_t)r*HD + i] = __ushort_as_bfloat16(l);
    split1(o2, h, l);
    hi[(size_t)r*HD + i + HD/2] = __ushort_as_bfloat16(h);
    lo[(size_t)r*HD + i + HD/2] = __ushort_as_bfloat16(l);
}

// ---- fused split of hs + Wq + Wk + Wv + Wo in ONE launch -------------------
#define N4_HS (MTOT*HIDDEN/4)
#define N4_WQ (QDIM*HIDDEN/4)
#define N4_WK (KVDIM*HIDDEN/4)
#define N4_WV (KVDIM*HIDDEN/4)
#define N4_WO (HIDDEN*QDIM/4)
#define N4_TOTAL (N4_HS+N4_WQ+N4_WK+N4_WV+N4_WO)

__global__ void k_split_all(const float4* __restrict__ hs, const float4* __restrict__ wq,
                            const float4* __restrict__ wk, const float4* __restrict__ wv,
                            const float4* __restrict__ wo) {
    int i = blockIdx.x * 256 + threadIdx.x;
    const float4* src;
    uint2 *dh, *dl;
    int j;
    if (i < N4_HS) {
        j = i; src = hs;
        dh = (uint2*)g_hshi; dl = (uint2*)g_hslo;
    } else if (i < N4_HS + N4_WQ) {
        j = i - N4_HS; src = wq;
        dh = (uint2*)g_wphi; dl = (uint2*)g_wplo;
    } else if (i < N4_HS + N4_WQ + N4_WK) {
        j = i - (N4_HS + N4_WQ); src = wk;
        dh = (uint2*)g_wphi + (size_t)QDIM*HIDDEN/4;
        dl = (uint2*)g_wplo + (size_t)QDIM*HIDDEN/4;
    } else if (i < N4_HS + N4_WQ + N4_WK + N4_WV) {
        j = i - (N4_HS + N4_WQ + N4_WK); src = wv;
        dh = (uint2*)g_wphi + (size_t)(QDIM+KVDIM)*HIDDEN/4;
        dl = (uint2*)g_wplo + (size_t)(QDIM+KVDIM)*HIDDEN/4;
    } else {
        j = i - (N4_HS + N4_WQ + N4_WK + N4_WV); src = wo;
        dh = (uint2*)g_wohi; dl = (uint2*)g_wolo;
    }
    float4 v = src[j];
    unsigned short h0,h1,h2,h3,l0,l1,l2,l3;
    split1(v.x,h0,l0); split1(v.y,h1,l1); split1(v.z,h2,l2); split1(v.w,h3,l3);
    uint2 H, L;
    H.x = (uint32_t)h0 | ((uint32_t)h1 << 16); H.y = (uint32_t)h2 | ((uint32_t)h3 << 16);
    L.x = (uint32_t)l0 | ((uint32_t)l1 << 16); L.y = (uint32_t)l2 | ((uint32_t)l3 << 16);
    dh[j] = H; dl[j] = L;
}

// transpose v [z][s][d] -> vT [z][d][s] with split
__global__ void k_vT() {
    __shared__ float t[32][33];
    int z = blockIdx.z;
    int d0 = blockIdx.x * 32, s0 = blockIdx.y * 32;
    int tx = threadIdx.x, ty = threadIdx.y;
    t[ty][tx] = g_vf[((size_t)z*SEQ + s0 + ty)*HD + d0 + tx];
    __syncthreads();
    float x = t[tx][ty];
    size_t o = ((size_t)z*HD + d0 + ty)*SEQ + s0 + tx;
    unsigned short h, l;
    split1(x, h, l);
    g_vthi[o] = __ushort_as_bfloat16(h);
    g_vtlo[o] = __ushort_as_bfloat16(l);
}

// ======================= mma.sync GEMM (proj / out), BK=64 ==================
// CTA 128x256, 8 warps 2m x 4n (warp 64x64), occ 1.
// Inner loop: batch all 16 LDSM per kk, then 3 sweeps (hh, hl, lh) of 32 mma
// each -> same-accumulator touches separated by 31 independent mma.
#define RS 72                         // row stride bf16 (144B)
#define MAT_A (128*RS*2)              // 18432
#define MAT_B (256*RS*2)              // 36864
#define OFF_AH 0
#define OFF_AL MAT_A
#define OFF_BH (2*MAT_A)
#define OFF_BL (2*MAT_A + MAT_B)
#define STAGE_BYTES (2*MAT_A + 2*MAT_B)   // 110592
#define DYN_SMEM (2*STAGE_BYTES)          // 221184

__device__ __forceinline__ void load_chunk(
    const __nv_bfloat16* __restrict__ Ah, const __nv_bfloat16* __restrict__ Al, int lda,
    const __nv_bfloat16* __restrict__ Bh, const __nv_bfloat16* __restrict__ Bl, int ldb,
    int k0, uint32_t stage)
{
    int t = threadIdx.x;
    #pragma unroll
    for (int i = 0; i < 4; i++) {
        int v = t + (i << 8);
        int row = v >> 3, g = v & 7;
        uint32_t doff = (uint32_t)row * (RS*2) + (uint32_t)(g << 4);
        const size_t ra = (size_t)row * lda + k0 + g*8;
        cp16(stage + OFF_AH + doff, Ah + ra);
        cp16(stage + OFF_AL + doff, Al + ra);
    }
    #pragma unroll
    for (int i = 0; i < 8; i++) {
        int v = t + (i << 8);
        int row = v >> 3, g = v & 7;
        uint32_t doff = (uint32_t)row * (RS*2) + (uint32_t)(g << 4);
        const size_t rb = (size_t)row * ldb + k0 + g*8;
        cp16(stage + OFF_BH + doff, Bh + rb);
        cp16(stage + OFF_BL + doff, Bl + rb);
    }
}

template<class Epi>
__device__ __forceinline__ void gemm_body(
    const __nv_bfloat16* __restrict__ Ahi, const __nv_bfloat16* __restrict__ Alo, int lda,
    const __nv_bfloat16* __restrict__ Bhi, const __nv_bfloat16* __restrict__ Blo, int ldb,
    int K, Epi epi)
{
    extern __shared__ char dsm[];
    const uint32_t sbase = smem_to_u32(dsm);
    const int tid = threadIdx.x;
    const int wid = tid >> 5, lane = tid & 31;
    const int wm = wid & 1, wn = wid >> 1;        // 2m x 4n
    const int m0 = blockIdx.y * 128, n0 = blockIdx.x * 256;

    const __nv_bfloat16* A0 = Ahi + (size_t)m0 * lda;
    const __nv_bfloat16* A1 = Alo + (size_t)m0 * lda;
    const __nv_bfloat16* B0 = Bhi + (size_t)n0 * ldb;
    const __nv_bfloat16* B1 = Blo + (size_t)n0 * ldb;

    float acc[4][8][4];
    #pragma unroll
    for (int a = 0; a < 4; a++)
        #pragma unroll
        for (int b = 0; b < 8; b++)
            #pragma unroll
            for (int c = 0; c < 4; c++) acc[a][b][c] = 0.0f;

    const int nc = K >> 6;
    load_chunk(A0, A1, lda, B0, B1, ldb, 0, sbase);
    cp_commit();

    for (int c = 0; c < nc; c++) {
        cp_wait<0>();
        __syncthreads();
        if (c + 1 < nc) {
            load_chunk(A0, A1, lda, B0, B1, ldb, (c+1) << 6,
                       sbase + (uint32_t)((c+1) & 1) * STAGE_BYTES);
            cp_commit();
        }
        const uint32_t sb = sbase + (uint32_t)(c & 1) * STAGE_BYTES;
        #pragma unroll
        for (int kk = 0; kk < 4; kk++) {
            uint32_t ah[4][4], al[4][4], bh[4][4], bl[4][4];
            // batch all fragment loads
            #pragma unroll
            for (int mt = 0; mt < 4; mt++) {
                int row = wm*64 + mt*16 + (lane & 15);
                uint32_t off = (uint32_t)row*(RS*2) + (uint32_t)kk*32 + ((lane >> 4) << 4);
                LDSM_X4(ah[mt], sb + OFF_AH + off);
                LDSM_X4(al[mt], sb + OFF_AL + off);
            }
            #pragma unroll
            for (int nt = 0; nt < 4; nt++) {
                int g = lane >> 3;
                int row = wn*64 + nt*16 + ((g >> 1) << 3) + (lane & 7);
                uint32_t off = (uint32_t)row*(RS*2) + (uint32_t)kk*32 + ((g & 1) << 4);
                LDSM_X4(bh[nt], sb + OFF_BH + off);
                LDSM_X4(bl[nt], sb + OFF_BL + off);
            }
            // pass 1: hi*hi
            #pragma unroll
            for (int nt = 0; nt < 4; nt++)
                #pragma unroll
                for (int mt = 0; mt < 4; mt++) {
                    mma16816(acc[mt][nt*2+0], ah[mt], bh[nt][0], bh[nt][1]);
                    mma16816(acc[mt][nt*2+1], ah[mt], bh[nt][2], bh[nt][3]);
                }
            // pass 2: hi*lo
            #pragma unroll
            for (int nt = 0; nt < 4; nt++)
                #pragma unroll
                for (int mt = 0; mt < 4; mt++) {
                    mma16816(acc[mt][nt*2+0], ah[mt], bl[nt][0], bl[nt][1]);
                    mma16816(acc[mt][nt*2+1], ah[mt], bl[nt][2], bl[nt][3]);
                }
            // pass 3: lo*hi
            #pragma unroll
            for (int nt = 0; nt < 4; nt++)
                #pragma unroll
                for (int mt = 0; mt < 4; mt++) {
                    mma16816(acc[mt][nt*2+0], al[mt], bh[nt][0], bh[nt][1]);
                    mma16816(acc[mt][nt*2+1], al[mt], bh[nt][2], bh[nt][3]);
                }
        }
    }

    #pragma unroll
    for (int mt = 0; mt < 4; mt++)
        #pragma unroll
        for (int nj = 0; nj < 8; nj++)
            #pragma unroll
            for (int e = 0; e < 4; e++) {
                int m = m0 + wm*64 + mt*16 + (lane >> 2) + ((e >> 1) << 3);
                int n = n0 + wn*64 + nj*8 + ((lane & 3) << 1) + (e & 1);
                epi(m, n, acc[mt][nj][e]);
            }
}

struct EpiProjFused {
    __device__ __forceinline__ void operator()(int m, int n, float v) const {
        int b = m >> 11, s = m & (SEQ-1);
        if (n < QDIM) {
            int h = n >> 8, d = n & (HD-1);
            g_qf[(((size_t)b*NH + h)*SEQ + s)*HD + d] = v;
        } else if (n < QDIM + KVDIM) {
            int nn = n - QDIM;
            int h = nn >> 8, d = nn & (HD-1);
            g_kf[(((size_t)b*NKV + h)*SEQ + s)*HD + d] = v;
        } else {
            int nn = n - QDIM - KVDIM;
            int h = nn >> 8, d = nn & (HD-1);
            g_vf[(((size_t)b*NKV + h)*SEQ + s)*HD + d] = v;
        }
    }
};
struct EpiPlain {
    float* C; int ldc;
    __device__ __forceinline__ void operator()(int m, int n, float v) const {
        C[(size_t)m*ldc + n] = v;
    }
};

__global__ void __launch_bounds__(256, 1) g_proj() {
    gemm_body(g_hshi, g_hslo, HIDDEN, g_wphi, g_wplo, HIDDEN, HIDDEN, EpiProjFused{});
}
__global__ void __launch_bounds__(256, 1) g_out(float* __restrict__ out) {
    gemm_body(g_ahi, g_alo, QDIM, g_wohi, g_wolo, QDIM, QDIM, EpiPlain{out, HIDDEN});
}

// ======================= flash attention ===================================
#define FL_QK_STAGE 40960
#define FL_V_BASE   81920
#define FL_V_STAGE  40960
#define FL_SMEM     163840

__device__ __forceinline__ void fl_load_qk(
    const __nv_bfloat16* __restrict__ Qh, const __nv_bfloat16* __restrict__ Ql,
    const __nv_bfloat16* __restrict__ Kh, const __nv_bfloat16* __restrict__ Kl,
    int s0, int c, uint32_t stage)
{
    int tid = threadIdx.x;
    #pragma unroll
    for (int i = 0; i < 8; i++) {
        const int mat = i >> 1;                     // 0 Qh, 1 Ql, 2 Kh, 3 Kl
        int w = ((i & 1) << 8) + tid;
        int row = w >> 2, g = w & 3;
        uint32_t dst = stage + (uint32_t)mat*10240 + (uint32_t)row*80 + (uint32_t)(g << 4);
        size_t col = (size_t)(c*32 + g*8);
        if (mat == 0)      cp16(dst, Qh + (size_t)row*HD + col);
        else if (mat == 1) cp16(dst, Ql + (size_t)row*HD + col);
        else if (mat == 2) cp16(dst, Kh + (size_t)(s0 + row)*HD + col);
        else               cp16(dst, Kl + (size_t)(s0 + row)*HD + col);
    }
}
__device__ __forceinline__ void fl_load_v(
    const __nv_bfloat16* __restrict__ Vh, const __nv_bfloat16* __restrict__ Vl,
    int s0, int sl, uint32_t stage)
{
    int tid = threadIdx.x;
    #pragma unroll
    for (int i = 0; i < 8; i++) {
        const int mat = i >> 2;                     // 0 Vh, 1 Vl
        int w = ((i & 3) << 8) + tid;
        int row = w >> 2, g = w & 3;                // row 0..255 (d)
        uint32_t dst = stage + (uint32_t)mat*20480 + (uint32_t)row*80 + (uint32_t)(g << 4);
        size_t col = (size_t)(s0 + sl*32 + g*8);
        if (mat == 0) cp16(dst, Vh + (size_t)row*SEQ + col);
        else          cp16(dst, Vl + (size_t)row*SEQ + col);
    }
}

__global__ void __launch_bounds__(256, 1) g_flash() {
    extern __shared__ char dsm[];
    const uint32_t sb = smem_to_u32(dsm);
    const int tid = threadIdx.x, wid = tid >> 5, lane = tid & 31;
    const int qt = blockIdx.x, z = blockIdx.y;
    const int b = z >> 3, h = z & 7, kv = h >> 2;
    const int q0 = qt * 128;

    const __nv_bfloat16* Qh = g_qhi + (size_t)z*SEQ*HD + (size_t)q0*HD;
    const __nv_bfloat16* Ql = g_qlo + (size_t)z*SEQ*HD + (size_t)q0*HD;
    const __nv_bfloat16* Kh = g_khi + (size_t)(b*NKV+kv)*SEQ*HD;
    const __nv_bfloat16* Kl = g_klo + (size_t)(b*NKV+kv)*SEQ*HD;
    const __nv_bfloat16* Vh = g_vthi + (size_t)(b*NKV+kv)*HD*SEQ;
    const __nv_bfloat16* Vl = g_vtlo + (size_t)(b*NKV+kv)*HD*SEQ;

    float acc_o[32][4];
    #pragma unroll
    for (int i = 0; i < 32; i++)
        #pragma unroll
        for (int e = 0; e < 4; e++) acc_o[i][e] = 0.0f;
    float rm[2] = {-1e30f, -1e30f};
    float rl[2] = {0.0f, 0.0f};

    fl_load_qk(Qh, Ql, Kh, Kl, 0, 0, sb);
    cp_commit();

    for (int kt = 0; kt < 16; kt++) {
        const int s0 = kt * 128;
        float acc_s[16][4];
        #pragma unroll
        for (int i = 0; i < 16; i++)
            #pragma unroll
            for (int e = 0; e < 4; e++) acc_s[i][e] = 0.0f;

        // ---- S phase: 8 d-chunks; interleave 4 accumulators per nt2-pair ----
        for (int c = 0; c < 8; c++) {
            cp_wait<0>();
            __syncthreads();
            if (c < 7) fl_load_qk(Qh, Ql, Kh, Kl, s0, c+1, sb + (uint32_t)((c+1)&1)*FL_QK_STAGE);
            else       fl_load_v(Vh, Vl, s0, 0, sb + FL_V_BASE);
            cp_commit();
            const uint32_t qkb = sb + (uint32_t)(c & 1) * FL_QK_STAGE;
            #pragma unroll
            for (int kk = 0; kk < 2; kk++) {
                uint32_t qh[4], ql[4];
                uint32_t a_off = (uint32_t)(wid*16 + (lane & 15))*80 + (uint32_t)kk*32 + ((lane >> 4) << 4);
                LDSM_X4(qh, qkb + a_off);
                LDSM_X4(ql, qkb + 10240 + a_off);
                int g = lane >> 3;
                uint32_t c_off = (uint32_t)kk*32 + ((g & 1) << 4);
                #pragma unroll
                for (int p2 = 0; p2 < 4; p2++) {       // nt2 pairs
                    int nt2 = p2 * 2;
                    int rowa = nt2*16 + ((g >> 1) << 3) + (lane & 7);
                    int rowb = (nt2+1)*16 + ((g >> 1) << 3) + (lane & 7);
                    uint32_t kh_a[4], kl_a[4], kh_b[4], kl_b[4];
                    LDSM_X4(kh_a, qkb + 20480 + (uint32_t)rowa*80 + c_off);
                    LDSM_X4(kl_a, qkb + 30720 + (uint32_t)rowa*80 + c_off);
                    LDSM_X4(kh_b, qkb + 20480 + (uint32_t)rowb*80 + c_off);
                    LDSM_X4(kl_b, qkb + 30720 + (uint32_t)rowb*80 + c_off);
                    float* a0 = acc_s[2*nt2+0];
                    float* a1 = acc_s[2*nt2+1];
                    float* a2 = acc_s[2*nt2+2];
                    float* a3 = acc_s[2*nt2+3];
                    mma16816(a0, qh, kh_a[0], kh_a[1]);
                    mma16816(a1, qh, kh_a[2], kh_a[3]);
                    mma16816(a2, qh, kh_b[0], kh_b[1]);
                    mma16816(a3, qh, kh_b[2], kh_b[3]);
                    mma16816(a0, qh, kl_a[0], kl_a[1]);
                    mma16816(a1, qh, kl_a[2], kl_a[3]);
                    mma16816(a2, qh, kl_b[0], kl_b[1]);
                    mma16816(a3, qh, kl_b[2], kl_b[3]);
                    mma16816(a0, ql, kh_a[0], kh_a[1]);
                    mma16816(a1, ql, kh_a[2], kh_a[3]);
                    mma16816(a2, ql, kh_b[0], kh_b[1]);
                    mma16816(a3, ql, kh_b[2], kh_b[3]);
                }
            }
        }

        // ---- softmax (register-resident) ----
        float mnew[2] = {-1e30f, -1e30f};
        #pragma unroll
        for (int nt = 0; nt < 16; nt++)
            #pragma unroll
            for (int e = 0; e < 4; e++) {
                float s = acc_s[nt][e];
                float y = s * 0.00125f;
                float y2 = y * y;
                float capped = s * 0.0625f * (1.0f - y2*(0.33333333f - y2*0.13333333f));
                acc_s[nt][e] = capped;
                mnew[e >> 1] = fmaxf(mnew[e >> 1], capped);
            }
        #pragma unroll
        for (int o = 1; o <= 2; o <<= 1) {
            mnew[0] = fmaxf(mnew[0], __shfl_xor_sync(0xFFFFFFFFu, mnew[0], o));
            mnew[1] = fmaxf(mnew[1], __shfl_xor_sync(0xFFFFFFFFu, mnew[1], o));
        }
        float mt[2], al[2];
        #pragma unroll
        for (int j = 0; j < 2; j++) {
            mt[j] = fmaxf(rm[j], mnew[j]);
            al[j] = __expf(rm[j] - mt[j]);
            rm[j] = mt[j];
        }
        uint32_t ph[8][4], pl[8][4];
        float sum[2] = {0.0f, 0.0f};
        #pragma unroll
        for (int g2 = 0; g2 < 8; g2++) {
            unsigned short hh[8], ll[8];
            #pragma unroll
            for (int half = 0; half < 2; half++) {
                int nt = 2*g2 + half;
                #pragma unroll
                for (int e = 0; e < 4; e++) {
                    float p = __expf(acc_s[nt][e] - mt[e >> 1]);
                    sum[e >> 1] += p;
                    split1(p, hh[half*4+e], ll[half*4+e]);
                }
            }
            ph[g2][0] = (uint32_t)hh[0] | ((uint32_t)hh[1] << 16);
            ph[g2][1] = (uint32_t)hh[2] | ((uint32_t)hh[3] << 16);
            ph[g2][2] = (uint32_t)hh[4] | ((uint32_t)hh[5] << 16);
            ph[g2][3] = (uint32_t)hh[6] | ((uint32_t)hh[7] << 16);
            pl[g2][0] = (uint32_t)ll[0] | ((uint32_t)ll[1] << 16);
            pl[g2][1] = (uint32_t)ll[2] | ((uint32_t)ll[3] << 16);
            pl[g2][2] = (uint32_t)ll[4] | ((uint32_t)ll[5] << 16);
            pl[g2][3] = (uint32_t)ll[6] | ((uint32_t)ll[7] << 16);
        }
        #pragma unroll
        for (int o = 1; o <= 2; o <<= 1) {
            sum[0] += __shfl_xor_sync(0xFFFFFFFFu, sum[0], o);
            sum[1] += __shfl_xor_sync(0xFFFFFFFFu, sum[1], o);
        }
        rl[0] = rl[0]*al[0] + sum[0];
        rl[1] = rl[1]*al[1] + sum[1];
        #pragma unroll
        for (int nt = 0; nt < 32; nt++)
            #pragma unroll
            for (int e = 0; e < 4; e++) acc_o[nt][e] *= al[e >> 1];

        // ---- PV phase: interleave 4 accumulators per nt2-pair ----
        for (int sl = 0; sl < 4; sl++) {
            cp_wait<0>();
            __syncthreads();
            if (sl < 3)       fl_load_v(Vh, Vl, s0, sl+1, sb + FL_V_BASE + (uint32_t)((sl+1)&1)*FL_V_STAGE);
            else if (kt < 15) fl_load_qk(Qh, Ql, Kh, Kl, s0 + 128, 0, sb);
            cp_commit();
            const uint32_t vb = sb + FL_V_BASE + (uint32_t)(sl & 1) * FL_V_STAGE;
            #pragma unroll
            for (int kk = 0; kk < 2; kk++) {
                const int g2 = sl*2 + kk;
                int g = lane >> 3;
                uint32_t c_off = (uint32_t)kk*32 + ((g & 1) << 4);
                #pragma unroll
                for (int p2 = 0; p2 < 8; p2++) {       // nt2 pairs
                    int nt2 = p2 * 2;
                    int rowa = nt2*16 + ((g >> 1) << 3) + (lane & 7);
                    int rowb = (nt2+1)*16 + ((g >> 1) << 3) + (lane & 7);
                    uint32_t vh_a[4], vl_a[4], vh_b[4], vl_b[4];
                    LDSM_X4(vh_a, vb + (uint32_t)rowa*80 + c_off);
                    LDSM_X4(vl_a, vb + 20480 + (uint32_t)rowa*80 + c_off);
                    LDSM_X4(vh_b, vb + (uint32_t)rowb*80 + c_off);
                    LDSM_X4(vl_b, vb + 20480 + (uint32_t)rowb*80 + c_off);
                    float* a0 = acc_o[2*nt2+0];
                    float* a1 = acc_o[2*nt2+1];
                    float* a2 = acc_o[2*nt2+2];
                    float* a3 = acc_o[2*nt2+3];
                    mma16816(a0, ph[g2], vh_a[0], vh_a[1]);
                    mma16816(a1, ph[g2], vh_a[2], vh_a[3]);
                    mma16816(a2, ph[g2], vh_b[0], vh_b[1]);
                    mma16816(a3, ph[g2], vh_b[2], vh_b[3]);
                    mma16816(a0, ph[g2], vl_a[0], vl_a[1]);
                    mma16816(a1, ph[g2], vl_a[2], vl_a[3]);
                    mma16816(a2, ph[g2], vl_b[0], vl_b[1]);
                    mma16816(a3, ph[g2], vl_b[2], vl_b[3]);
                    mma16816(a0, pl[g2], vh_a[0], vh_a[1]);
                    mma16816(a1, pl[g2], vh_a[2], vh_a[3]);
                    mma16816(a2, pl[g2], vh_b[0], vh_b[1]);
                    mma16816(a3, pl[g2], vh_b[2], vh_b[3]);
                }
            }
        }
    }

    // ---- epilogue ----
    float inv[2] = {1.0f / rl[0], 1.0f / rl[1]};
    #pragma unroll
    for (int nt = 0; nt < 32; nt++)
        #pragma unroll
        for (int j = 0; j < 2; j++) {
            int rloc = wid*16 + (lane >> 2) + j*8;
            size_t m = (size_t)b*SEQ + q0 + rloc;
            int d = nt*8 + (lane & 3)*2;
            size_t o = m*QDIM + h*HD + d;
            float v0 = acc_o[nt][2*j+0] * inv[j];
            float v1 = acc_o[nt][2*j+1] * inv[j];
            unsigned short h0, l0, h1, l1;
            split1(v0, h0, l0);
            split1(v1, h1, l1);
            *(uint32_t*)(g_ahi + o) = (uint32_t)h0 | ((uint32_t)h1 << 16);
            *(uint32_t*)(g_alo + o) = (uint32_t)l0 | ((uint32_t)l1 << 16);
        }
}

// ======================= launch ============================================
extern "C" void kernel_launch(void* const* d_in, const int* in_sizes, int n_in,
                              void* d_out, int out_size) {
    const float* hs = (const float*)d_in[0];
    const float* Wq = (const float*)d_in[1];
    const float* Wk = (const float*)d_in[2];
    const float* Wv = (const float*)d_in[3];
    const float* Wo = (const float*)d_in[4];
    float* out = (float*)d_out;
    (void)in_sizes; (void)n_in; (void)out_size;

    cudaFuncSetAttribute(g_proj,  cudaFuncAttributeMaxDynamicSharedMemorySize, DYN_SMEM);
    cudaFuncSetAttribute(g_out,   cudaFuncAttributeMaxDynamicSharedMemorySize, DYN_SMEM);
    cudaFuncSetAttribute(g_flash, cudaFuncAttributeMaxDynamicSharedMemorySize, FL_SMEM);

    // launch 1: fused split of all fp32 inputs
    k_split_all<<<N4_TOTAL/256, 256>>>((const float4*)hs, (const float4*)Wq,
                                       (const float4*)Wk, (const float4*)Wv,
                                       (const float4*)Wo);
    // launches 2-3: rope tables
    k_invfreq<<<1, 128>>>();
    k_ropetab<<<SEQ, 128>>>();

    // launch 4: fused QKV projection (profiled slot)
    g_proj<<<dim3(WPROWS/256, MTOT/128), 256, DYN_SMEM>>>();

    // rope + split, vT
    float *qf_p, *kf_p;
    cudaGetSymbolAddress((void**)&qf_p, g_qf);
    cudaGetSymbolAddress((void**)&kf_p, g_kf);
    __nv_bfloat16 *qhi_p, *qlo_p, *khi_p, *klo_p;
    cudaGetSymbolAddress((void**)&qhi_p, g_qhi); cudaGetSymbolAddress((void**)&qlo_p, g_qlo);
    cudaGetSymbolAddress((void**)&khi_p, g_khi); cudaGetSymbolAddress((void**)&klo_p, g_klo);
    k_rope_split<<<BATCH*NH*SEQ, 128>>>(qf_p, qhi_p, qlo_p);
    k_rope_split<<<BATCH*NKV*SEQ, 128>>>(kf_p, khi_p, klo_p);
    k_vT<<<dim3(HD/32, SEQ/32, BATCH*NKV), dim3(32, 32)>>>();

    // fused attention
    g_flash<<<dim3(SEQ/128, BATCH*NH), 256, FL_SMEM>>>();

    // output projection
    g_out<<<dim3(HIDDEN/256, MTOT/128), 256, DYN_SMEM>>>(out);
}

// round 11
// speedup vs baseline: 1.0755x; 1.0755x over previous
#include <cuda_runtime.h>
#include <cuda_bf16.h>
#include <cuda_fp16.h>
#include <math.h>
#include <stdint.h>

#define HIDDEN 2048
#define NH 8
#define NKV 2
#define HD 256
#define BATCH 2
#define SEQ 2048
#define MTOT (BATCH*SEQ)            // 4096
#define QDIM (NH*HD)                // 2048
#define KVDIM (NKV*HD)              // 512
#define WPROWS (QDIM + 2*KVDIM)     // 3072

// ======================= PTX helpers =======================================
__device__ __forceinline__ uint32_t smem_to_u32(const void* p) {
    uint32_t a;
    asm("{ .reg .u64 t; cvta.to.shared.u64 t, %1; cvt.u32.u64 %0, t; }" : "=r"(a) : "l"(p));
    return a;
}
__device__ __forceinline__ void cp16(uint32_t dst, const void* src) {
    asm volatile("cp.async.cg.shared.global [%0], [%1], 16;" :: "r"(dst), "l"(src));
}
__device__ __forceinline__ void cp_commit() { asm volatile("cp.async.commit_group;" ::: "memory"); }
template<int N> __device__ __forceinline__ void cp_wait() {
    asm volatile("cp.async.wait_group %0;" :: "n"(N) : "memory");
}
#define LDSM_X4(r, addr) \
    asm volatile("ldmatrix.sync.aligned.m8n8.x4.shared.b16 {%0,%1,%2,%3}, [%4];" \
        : "=r"((r)[0]), "=r"((r)[1]), "=r"((r)[2]), "=r"((r)[3]) : "r"(addr))

__device__ __forceinline__ void mma16816(float* d, const uint32_t* a, uint32_t b0, uint32_t b1) {
    asm volatile("mma.sync.aligned.m16n8k16.row.col.f32.bf16.bf16.f32 "
        "{%0,%1,%2,%3}, {%4,%5,%6,%7}, {%8,%9}, {%0,%1,%2,%3};"
        : "+f"(d[0]), "+f"(d[1]), "+f"(d[2]), "+f"(d[3])
        : "r"(a[0]), "r"(a[1]), "r"(a[2]), "r"(a[3]), "r"(b0), "r"(b1));
}
__device__ __forceinline__ void mma16816h(float* d, const uint32_t* a, uint32_t b0, uint32_t b1) {
    asm volatile("mma.sync.aligned.m16n8k16.row.col.f32.f16.f16.f32 "
        "{%0,%1,%2,%3}, {%4,%5,%6,%7}, {%8,%9}, {%0,%1,%2,%3};"
        : "+f"(d[0]), "+f"(d[1]), "+f"(d[2]), "+f"(d[3])
        : "r"(a[0]), "r"(a[1]), "r"(a[2]), "r"(a[3]), "r"(b0), "r"(b1));
}

// ======================= scratch (device globals) ==========================
__device__ __align__(16) __nv_bfloat16 g_hshi[(size_t)MTOT*HIDDEN], g_hslo[(size_t)MTOT*HIDDEN];
__device__ __align__(16) __nv_bfloat16 g_wphi[(size_t)WPROWS*HIDDEN], g_wplo[(size_t)WPROWS*HIDDEN];
__device__ __align__(16) __nv_bfloat16 g_wohi[(size_t)HIDDEN*QDIM], g_wolo[(size_t)HIDDEN*QDIM];
__device__ __align__(16) float g_qf[(size_t)MTOT*QDIM];
__device__ __align__(16) float g_kf[(size_t)BATCH*NKV*SEQ*HD];
__device__ __align__(16) float g_vf[(size_t)BATCH*NKV*SEQ*HD];
__device__ __align__(16) __nv_bfloat16 g_qhi[(size_t)MTOT*QDIM], g_qlo[(size_t)MTOT*QDIM];
__device__ __align__(16) __nv_bfloat16 g_khi[(size_t)BATCH*NKV*SEQ*HD], g_klo[(size_t)BATCH*NKV*SEQ*HD];
__device__ __align__(16) __half g_vthi[(size_t)BATCH*NKV*HD*SEQ], g_vtlo[(size_t)BATCH*NKV*HD*SEQ];
__device__ __align__(16) __nv_bfloat16 g_ahi[(size_t)MTOT*QDIM], g_alo[(size_t)MTOT*QDIM];
__device__ double g_invfreq[HD/2];
__device__ float g_cos[SEQ*(HD/2)];
__device__ float g_sin[SEQ*(HD/2)];

// ======================= small kernels =====================================
__global__ void k_invfreq() {
    int i = threadIdx.x;
    if (i < HD/2) g_invfreq[i] = pow(10000.0, -2.0 * (double)i / (double)HD);
}
__global__ void k_ropetab() {
    int s = blockIdx.x, i = threadIdx.x;
    double ang = (double)s * g_invfreq[i];
    const double twopi = 6.283185307179586476925286766559;
    ang -= floor(ang / twopi) * twopi;
    float c, sn;
    sincosf((float)ang, &sn, &c);
    g_cos[s*(HD/2)+i] = c;
    g_sin[s*(HD/2)+i] = sn;
}

__device__ __forceinline__ void split1(float x, unsigned short& h, unsigned short& l) {
    __nv_bfloat16 hb = __float2bfloat16(x);
    float r = x - __bfloat162float(hb);
    __nv_bfloat16 lb = __float2bfloat16(r);
    h = __bfloat16_as_ushort(hb);
    l = __bfloat16_as_ushort(lb);
}
__device__ __forceinline__ void split1h(float x, __half& h, __half& l) {
    h = __float2half_rn(x);
    l = __float2half_rn(x - __half2float(h));
}

// rope + split fused
__global__ void k_rope_split(const float* __restrict__ src,
                             __nv_bfloat16* __restrict__ hi,
                             __nv_bfloat16* __restrict__ lo) {
    int r = blockIdx.x, i = threadIdx.x;
    int s = r & (SEQ-1);
    float c = g_cos[s*(HD/2)+i], sn = g_sin[s*(HD/2)+i];
    const float* row = src + (size_t)r * HD;
    float x1 = row[i], x2 = row[i + HD/2];
    float o1 = x1*c - x2*sn;
    float o2 = x2*c + x1*sn;
    unsigned short h, l;
    split1(o1, h, l);
    hi[(size_t)r*HD + i] = __ushort_as_bfloat16(h);
    lo[(size_t)r*HD + i] = __ushort_as_bfloat16(l);
    split1(o2, h, l);
    hi[(size_t)r*HD + i + HD/2] = __ushort_as_bfloat16(h);
    lo[(size_t)r*HD + i + HD/2] = __ushort_as_bfloat16(l);
}

// ---- fused split of hs + Wq + Wk + Wv + Wo in ONE launch -------------------
#define N4_HS (MTOT*HIDDEN/4)
#define N4_WQ (QDIM*HIDDEN/4)
#define N4_WK (KVDIM*HIDDEN/4)
#define N4_WV (KVDIM*HIDDEN/4)
#define N4_WO (HIDDEN*QDIM/4)
#define N4_TOTAL (N4_HS+N4_WQ+N4_WK+N4_WV+N4_WO)

__global__ void k_split_all(const float4* __restrict__ hs, const float4* __restrict__ wq,
                            const float4* __restrict__ wk, const float4* __restrict__ wv,
                            const float4* __restrict__ wo) {
    int i = blockIdx.x * 256 + threadIdx.x;
    const float4* src;
    uint2 *dh, *dl;
    int j;
    if (i < N4_HS) {
        j = i; src = hs;
        dh = (uint2*)g_hshi; dl = (uint2*)g_hslo;
    } else if (i < N4_HS + N4_WQ) {
        j = i - N4_HS; src = wq;
        dh = (uint2*)g_wphi; dl = (uint2*)g_wplo;
    } else if (i < N4_HS + N4_WQ + N4_WK) {
        j = i - (N4_HS + N4_WQ); src = wk;
        dh = (uint2*)g_wphi + (size_t)QDIM*HIDDEN/4;
        dl = (uint2*)g_wplo + (size_t)QDIM*HIDDEN/4;
    } else if (i < N4_HS + N4_WQ + N4_WK + N4_WV) {
        j = i - (N4_HS + N4_WQ + N4_WK); src = wv;
        dh = (uint2*)g_wphi + (size_t)(QDIM+KVDIM)*HIDDEN/4;
        dl = (uint2*)g_wplo + (size_t)(QDIM+KVDIM)*HIDDEN/4;
    } else {
        j = i - (N4_HS + N4_WQ + N4_WK + N4_WV); src = wo;
        dh = (uint2*)g_wohi; dl = (uint2*)g_wolo;
    }
    float4 v = src[j];
    unsigned short h0,h1,h2,h3,l0,l1,l2,l3;
    split1(v.x,h0,l0); split1(v.y,h1,l1); split1(v.z,h2,l2); split1(v.w,h3,l3);
    uint2 H, L;
    H.x = (uint32_t)h0 | ((uint32_t)h1 << 16); H.y = (uint32_t)h2 | ((uint32_t)h3 << 16);
    L.x = (uint32_t)l0 | ((uint32_t)l1 << 16); L.y = (uint32_t)l2 | ((uint32_t)l3 << 16);
    dh[j] = H; dl[j] = L;
}

// transpose v [z][s][d] -> vT [z][d][s] with fp16 split
__global__ void k_vT() {
    __shared__ float t[32][33];
    int z = blockIdx.z;
    int d0 = blockIdx.x * 32, s0 = blockIdx.y * 32;
    int tx = threadIdx.x, ty = threadIdx.y;
    t[ty][tx] = g_vf[((size_t)z*SEQ + s0 + ty)*HD + d0 + tx];
    __syncthreads();
    float x = t[tx][ty];
    size_t o = ((size_t)z*HD + d0 + ty)*SEQ + s0 + tx;
    __half h, l;
    split1h(x, h, l);
    g_vthi[o] = h;
    g_vtlo[o] = l;
}

// ======================= mma.sync GEMM (proj / out), BK=64 ==================
#define RS 72                         // row stride bf16 (144B)
#define MAT_A (128*RS*2)              // 18432
#define MAT_B (256*RS*2)              // 36864
#define OFF_AH 0
#define OFF_AL MAT_A
#define OFF_BH (2*MAT_A)
#define OFF_BL (2*MAT_A + MAT_B)
#define STAGE_BYTES (2*MAT_A + 2*MAT_B)   // 110592
#define DYN_SMEM (2*STAGE_BYTES)          // 221184

__device__ __forceinline__ void load_chunk(
    const __nv_bfloat16* __restrict__ Ah, const __nv_bfloat16* __restrict__ Al, int lda,
    const __nv_bfloat16* __restrict__ Bh, const __nv_bfloat16* __restrict__ Bl, int ldb,
    int k0, uint32_t stage)
{
    int t = threadIdx.x;
    #pragma unroll
    for (int i = 0; i < 4; i++) {
        int v = t + (i << 8);
        int row = v >> 3, g = v & 7;
        uint32_t doff = (uint32_t)row * (RS*2) + (uint32_t)(g << 4);
        const size_t ra = (size_t)row * lda + k0 + g*8;
        cp16(stage + OFF_AH + doff, Ah + ra);
        cp16(stage + OFF_AL + doff, Al + ra);
    }
    #pragma unroll
    for (int i = 0; i < 8; i++) {
        int v = t + (i << 8);
        int row = v >> 3, g = v & 7;
        uint32_t doff = (uint32_t)row * (RS*2) + (uint32_t)(g << 4);
        const size_t rb = (size_t)row * ldb + k0 + g*8;
        cp16(stage + OFF_BH + doff, Bh + rb);
        cp16(stage + OFF_BL + doff, Bl + rb);
    }
}

template<class Epi>
__device__ __forceinline__ void gemm_body(
    const __nv_bfloat16* __restrict__ Ahi, const __nv_bfloat16* __restrict__ Alo, int lda,
    const __nv_bfloat16* __restrict__ Bhi, const __nv_bfloat16* __restrict__ Blo, int ldb,
    int K, Epi epi)
{
    extern __shared__ char dsm[];
    const uint32_t sbase = smem_to_u32(dsm);
    const int tid = threadIdx.x;
    const int wid = tid >> 5, lane = tid & 31;
    const int wm = wid & 1, wn = wid >> 1;        // 2m x 4n
    const int m0 = blockIdx.y * 128, n0 = blockIdx.x * 256;

    const __nv_bfloat16* A0 = Ahi + (size_t)m0 * lda;
    const __nv_bfloat16* A1 = Alo + (size_t)m0 * lda;
    const __nv_bfloat16* B0 = Bhi + (size_t)n0 * ldb;
    const __nv_bfloat16* B1 = Blo + (size_t)n0 * ldb;

    float acc[4][8][4];
    #pragma unroll
    for (int a = 0; a < 4; a++)
        #pragma unroll
        for (int b = 0; b < 8; b++)
            #pragma unroll
            for (int c = 0; c < 4; c++) acc[a][b][c] = 0.0f;

    const int nc = K >> 6;
    load_chunk(A0, A1, lda, B0, B1, ldb, 0, sbase);
    cp_commit();

    for (int c = 0; c < nc; c++) {
        cp_wait<0>();
        __syncthreads();
        if (c + 1 < nc) {
            load_chunk(A0, A1, lda, B0, B1, ldb, (c+1) << 6,
                       sbase + (uint32_t)((c+1) & 1) * STAGE_BYTES);
            cp_commit();
        }
        const uint32_t sb = sbase + (uint32_t)(c & 1) * STAGE_BYTES;
        #pragma unroll
        for (int kk = 0; kk < 4; kk++) {
            uint32_t ah[4][4], al[4][4];
            #pragma unroll
            for (int mt = 0; mt < 4; mt++) {
                int row = wm*64 + mt*16 + (lane & 15);
                uint32_t off = (uint32_t)row*(RS*2) + (uint32_t)kk*32 + ((lane >> 4) << 4);
                LDSM_X4(ah[mt], sb + OFF_AH + off);
                LDSM_X4(al[mt], sb + OFF_AL + off);
            }
            #pragma unroll
            for (int nt = 0; nt < 4; nt++) {
                uint32_t bh[4], bl[4];
                int g = lane >> 3;
                int row = wn*64 + nt*16 + ((g >> 1) << 3) + (lane & 7);
                uint32_t off = (uint32_t)row*(RS*2) + (uint32_t)kk*32 + ((g & 1) << 4);
                LDSM_X4(bh, sb + OFF_BH + off);
                LDSM_X4(bl, sb + OFF_BL + off);
                #pragma unroll
                for (int mt = 0; mt < 4; mt++) {
                    mma16816(acc[mt][nt*2+0], ah[mt], bh[0], bh[1]);
                    mma16816(acc[mt][nt*2+0], ah[mt], bl[0], bl[1]);
                    mma16816(acc[mt][nt*2+0], al[mt], bh[0], bh[1]);
                    mma16816(acc[mt][nt*2+1], ah[mt], bh[2], bh[3]);
                    mma16816(acc[mt][nt*2+1], ah[mt], bl[2], bl[3]);
                    mma16816(acc[mt][nt*2+1], al[mt], bh[2], bh[3]);
                }
            }
        }
    }

    #pragma unroll
    for (int mt = 0; mt < 4; mt++)
        #pragma unroll
        for (int nj = 0; nj < 8; nj++)
            #pragma unroll
            for (int e = 0; e < 4; e++) {
                int m = m0 + wm*64 + mt*16 + (lane >> 2) + ((e >> 1) << 3);
                int n = n0 + wn*64 + nj*8 + ((lane & 3) << 1) + (e & 1);
                epi(m, n, acc[mt][nj][e]);
            }
}

struct EpiProjFused {
    __device__ __forceinline__ void operator()(int m, int n, float v) const {
        int b = m >> 11, s = m & (SEQ-1);
        if (n < QDIM) {
            int h = n >> 8, d = n & (HD-1);
            g_qf[(((size_t)b*NH + h)*SEQ + s)*HD + d] = v;
        } else if (n < QDIM + KVDIM) {
            int nn = n - QDIM;
            int h = nn >> 8, d = nn & (HD-1);
            g_kf[(((size_t)b*NKV + h)*SEQ + s)*HD + d] = v;
        } else {
            int nn = n - QDIM - KVDIM;
            int h = nn >> 8, d = nn & (HD-1);
            g_vf[(((size_t)b*NKV + h)*SEQ + s)*HD + d] = v;
        }
    }
};
struct EpiPlain {
    float* C; int ldc;
    __device__ __forceinline__ void operator()(int m, int n, float v) const {
        C[(size_t)m*ldc + n] = v;
    }
};

__global__ void __launch_bounds__(256, 1) g_proj() {
    gemm_body(g_hshi, g_hslo, HIDDEN, g_wphi, g_wplo, HIDDEN, HIDDEN, EpiProjFused{});
}
__global__ void __launch_bounds__(256, 1) g_out(float* __restrict__ out) {
    gemm_body(g_ahi, g_alo, QDIM, g_wohi, g_wolo, QDIM, QDIM, EpiPlain{out, HIDDEN});
}

// ======================= flash attention ===================================
#define FL_QK_STAGE 40960
#define FL_V_BASE   81920
#define FL_V_STAGE  40960
#define FL_SMEM     163840

__device__ __forceinline__ void fl_load_qk(
    const __nv_bfloat16* __restrict__ Qh, const __nv_bfloat16* __restrict__ Ql,
    const __nv_bfloat16* __restrict__ Kh, const __nv_bfloat16* __restrict__ Kl,
    int s0, int c, uint32_t stage)
{
    int tid = threadIdx.x;
    #pragma unroll
    for (int i = 0; i < 8; i++) {
        const int mat = i >> 1;                     // 0 Qh, 1 Ql, 2 Kh, 3 Kl
        int w = ((i & 1) << 8) + tid;
        int row = w >> 2, g = w & 3;
        uint32_t dst = stage + (uint32_t)mat*10240 + (uint32_t)row*80 + (uint32_t)(g << 4);
        size_t col = (size_t)(c*32 + g*8);
        if (mat == 0)      cp16(dst, Qh + (size_t)row*HD + col);
        else if (mat == 1) cp16(dst, Ql + (size_t)row*HD + col);
        else if (mat == 2) cp16(dst, Kh + (size_t)(s0 + row)*HD + col);
        else               cp16(dst, Kl + (size_t)(s0 + row)*HD + col);
    }
}
__device__ __forceinline__ void fl_load_v(
    const __half* __restrict__ Vh, const __half* __restrict__ Vl,
    int s0, int sl, uint32_t stage)
{
    int tid = threadIdx.x;
    #pragma unroll
    for (int i = 0; i < 8; i++) {
        const int mat = i >> 2;                     // 0 Vh, 1 Vl
        int w = ((i & 3) << 8) + tid;
        int row = w >> 2, g = w & 3;                // row 0..255 (d)
        uint32_t dst = stage + (uint32_t)mat*20480 + (uint32_t)row*80 + (uint32_t)(g << 4);
        size_t col = (size_t)(s0 + sl*32 + g*8);
        if (mat == 0) cp16(dst, Vh + (size_t)row*SEQ + col);
        else          cp16(dst, Vl + (size_t)row*SEQ + col);
    }
}

__global__ void __launch_bounds__(256, 1) g_flash() {
    extern __shared__ char dsm[];
    const uint32_t sb = smem_to_u32(dsm);
    const int tid = threadIdx.x, wid = tid >> 5, lane = tid & 31;
    const int qt = blockIdx.x, z = blockIdx.y;
    const int b = z >> 3, h = z & 7, kv = h >> 2;
    const int q0 = qt * 128;

    const __nv_bfloat16* Qh = g_qhi + (size_t)z*SEQ*HD + (size_t)q0*HD;
    const __nv_bfloat16* Ql = g_qlo + (size_t)z*SEQ*HD + (size_t)q0*HD;
    const __nv_bfloat16* Kh = g_khi + (size_t)(b*NKV+kv)*SEQ*HD;
    const __nv_bfloat16* Kl = g_klo + (size_t)(b*NKV+kv)*SEQ*HD;
    const __half* Vh = g_vthi + (size_t)(b*NKV+kv)*HD*SEQ;
    const __half* Vl = g_vtlo + (size_t)(b*NKV+kv)*HD*SEQ;

    float acc_o[32][4];
    #pragma unroll
    for (int i = 0; i < 32; i++)
        #pragma unroll
        for (int e = 0; e < 4; e++) acc_o[i][e] = 0.0f;
    float rm[2] = {-1e30f, -1e30f};
    float rl[2] = {0.0f, 0.0f};

    fl_load_qk(Qh, Ql, Kh, Kl, 0, 0, sb);
    cp_commit();

    for (int kt = 0; kt < 16; kt++) {
        const int s0 = kt * 128;
        float acc_s[16][4];
        #pragma unroll
        for (int i = 0; i < 16; i++)
            #pragma unroll
            for (int e = 0; e < 4; e++) acc_s[i][e] = 0.0f;

        // ---- S phase: 8 d-chunks (bf16 3-product, unchanged) ----
        for (int c = 0; c < 8; c++) {
            cp_wait<0>();
            __syncthreads();
            if (c < 7) fl_load_qk(Qh, Ql, Kh, Kl, s0, c+1, sb + (uint32_t)((c+1)&1)*FL_QK_STAGE);
            else       fl_load_v(Vh, Vl, s0, 0, sb + FL_V_BASE);
            cp_commit();
            const uint32_t qkb = sb + (uint32_t)(c & 1) * FL_QK_STAGE;
            #pragma unroll
            for (int kk = 0; kk < 2; kk++) {
                uint32_t qh[4], ql[4];
                uint32_t a_off = (uint32_t)(wid*16 + (lane & 15))*80 + (uint32_t)kk*32 + ((lane >> 4) << 4);
                LDSM_X4(qh, qkb + a_off);
                LDSM_X4(ql, qkb + 10240 + a_off);
                int g = lane >> 3;
                uint32_t c_off = (uint32_t)kk*32 + ((g & 1) << 4);
                #pragma unroll
                for (int nt2 = 0; nt2 < 8; nt2++) {
                    int row = nt2*16 + ((g >> 1) << 3) + (lane & 7);
                    uint32_t kh[4], kl[4];
                    LDSM_X4(kh, qkb + 20480 + (uint32_t)row*80 + c_off);
                    LDSM_X4(kl, qkb + 30720 + (uint32_t)row*80 + c_off);
                    mma16816(acc_s[2*nt2],   qh, kh[0], kh[1]);
                    mma16816(acc_s[2*nt2],   qh, kl[0], kl[1]);
                    mma16816(acc_s[2*nt2],   ql, kh[0], kh[1]);
                    mma16816(acc_s[2*nt2+1], qh, kh[2], kh[3]);
                    mma16816(acc_s[2*nt2+1], qh, kl[2], kl[3]);
                    mma16816(acc_s[2*nt2+1], ql, kh[2], kh[3]);
                }
            }
        }

        // ---- softmax (register-resident); P as single fp16 ----
        float mnew[2] = {-1e30f, -1e30f};
        #pragma unroll
        for (int nt = 0; nt < 16; nt++)
            #pragma unroll
            for (int e = 0; e < 4; e++) {
                float s = acc_s[nt][e];
                float y = s * 0.00125f;
                float y2 = y * y;
                float capped = s * 0.0625f * (1.0f - y2*(0.33333333f - y2*0.13333333f));
                acc_s[nt][e] = capped;
                mnew[e >> 1] = fmaxf(mnew[e >> 1], capped);
            }
        #pragma unroll
        for (int o = 1; o <= 2; o <<= 1) {
            mnew[0] = fmaxf(mnew[0], __shfl_xor_sync(0xFFFFFFFFu, mnew[0], o));
            mnew[1] = fmaxf(mnew[1], __shfl_xor_sync(0xFFFFFFFFu, mnew[1], o));
        }
        float mt[2], al[2];
        #pragma unroll
        for (int j = 0; j < 2; j++) {
            mt[j] = fmaxf(rm[j], mnew[j]);
            al[j] = __expf(rm[j] - mt[j]);
            rm[j] = mt[j];
        }
        uint32_t ph[8][4];
        float sum[2] = {0.0f, 0.0f};
        #pragma unroll
        for (int g2 = 0; g2 < 8; g2++) {
            unsigned short hh[8];
            #pragma unroll
            for (int half = 0; half < 2; half++) {
                int nt = 2*g2 + half;
                #pragma unroll
                for (int e = 0; e < 4; e++) {
                    float p = __expf(acc_s[nt][e] - mt[e >> 1]);
                    sum[e >> 1] += p;
                    hh[half*4+e] = __half_as_ushort(__float2half_rn(p));
                }
            }
            ph[g2][0] = (uint32_t)hh[0] | ((uint32_t)hh[1] << 16);
            ph[g2][1] = (uint32_t)hh[2] | ((uint32_t)hh[3] << 16);
            ph[g2][2] = (uint32_t)hh[4] | ((uint32_t)hh[5] << 16);
            ph[g2][3] = (uint32_t)hh[6] | ((uint32_t)hh[7] << 16);
        }
        #pragma unroll
        for (int o = 1; o <= 2; o <<= 1) {
            sum[0] += __shfl_xor_sync(0xFFFFFFFFu, sum[0], o);
            sum[1] += __shfl_xor_sync(0xFFFFFFFFu, sum[1], o);
        }
        rl[0] = rl[0]*al[0] + sum[0];
        rl[1] = rl[1]*al[1] + sum[1];
        #pragma unroll
        for (int nt = 0; nt < 32; nt++)
            #pragma unroll
            for (int e = 0; e < 4; e++) acc_o[nt][e] *= al[e >> 1];

        // ---- PV phase: fp16, 2 products (P x Vhi + P x Vlo) ----
        for (int sl = 0; sl < 4; sl++) {
            cp_wait<0>();
            __syncthreads();
            if (sl < 3)       fl_load_v(Vh, Vl, s0, sl+1, sb + FL_V_BASE + (uint32_t)((sl+1)&1)*FL_V_STAGE);
            else if (kt < 15) fl_load_qk(Qh, Ql, Kh, Kl, s0 + 128, 0, sb);
            cp_commit();
            const uint32_t vb = sb + FL_V_BASE + (uint32_t)(sl & 1) * FL_V_STAGE;
            #pragma unroll
            for (int kk = 0; kk < 2; kk++) {
                const int g2 = sl*2 + kk;
                int g = lane >> 3;
                uint32_t c_off = (uint32_t)kk*32 + ((g & 1) << 4);
                #pragma unroll
                for (int nt2 = 0; nt2 < 16; nt2++) {
                    int row = nt2*16 + ((g >> 1) << 3) + (lane & 7);
                    uint32_t vh[4], vl[4];
                    LDSM_X4(vh, vb + (uint32_t)row*80 + c_off);
                    LDSM_X4(vl, vb + 20480 + (uint32_t)row*80 + c_off);
                    mma16816h(acc_o[2*nt2],   ph[g2], vh[0], vh[1]);
                    mma16816h(acc_o[2*nt2],   ph[g2], vl[0], vl[1]);
                    mma16816h(acc_o[2*nt2+1], ph[g2], vh[2], vh[3]);
                    mma16816h(acc_o[2*nt2+1], ph[g2], vl[2], vl[3]);
                }
            }
        }
    }

    // ---- epilogue ----
    float inv[2] = {1.0f / rl[0], 1.0f / rl[1]};
    #pragma unroll
    for (int nt = 0; nt < 32; nt++)
        #pragma unroll
        for (int j = 0; j < 2; j++) {
            int rloc = wid*16 + (lane >> 2) + j*8;
            size_t m = (size_t)b*SEQ + q0 + rloc;
            int d = nt*8 + (lane & 3)*2;
            size_t o = m*QDIM + h*HD + d;
            float v0 = acc_o[nt][2*j+0] * inv[j];
            float v1 = acc_o[nt][2*j+1] * inv[j];
            unsigned short h0, l0, h1, l1;
            split1(v0, h0, l0);
            split1(v1, h1, l1);
            *(uint32_t*)(g_ahi + o) = (uint32_t)h0 | ((uint32_t)h1 << 16);
            *(uint32_t*)(g_alo + o) = (uint32_t)l0 | ((uint32_t)l1 << 16);
        }
}

// ======================= launch ============================================
extern "C" void kernel_launch(void* const* d_in, const int* in_sizes, int n_in,
                              void* d_out, int out_size) {
    const float* hs = (const float*)d_in[0];
    const float* Wq = (const float*)d_in[1];
    const float* Wk = (const float*)d_in[2];
    const float* Wv = (const float*)d_in[3];
    const float* Wo = (const float*)d_in[4];
    float* out = (float*)d_out;
    (void)in_sizes; (void)n_in; (void)out_size;

    cudaFuncSetAttribute(g_proj,  cudaFuncAttributeMaxDynamicSharedMemorySize, DYN_SMEM);
    cudaFuncSetAttribute(g_out,   cudaFuncAttributeMaxDynamicSharedMemorySize, DYN_SMEM);
    cudaFuncSetAttribute(g_flash, cudaFuncAttributeMaxDynamicSharedMemorySize, FL_SMEM);

    // launch 1: fused split of all fp32 inputs
    k_split_all<<<N4_TOTAL/256, 256>>>((const float4*)hs, (const float4*)Wq,
                                       (const float4*)Wk, (const float4*)Wv,
                                       (const float4*)Wo);
    // launches 2-3: rope tables
    k_invfreq<<<1, 128>>>();
    k_ropetab<<<SEQ, 128>>>();

    // launch 4: fused QKV projection (profiled slot)
    g_proj<<<dim3(WPROWS/256, MTOT/128), 256, DYN_SMEM>>>();

    // rope + split, vT
    float *qf_p, *kf_p;
    cudaGetSymbolAddress((void**)&qf_p, g_qf);
    cudaGetSymbolAddress((void**)&kf_p, g_kf);
    __nv_bfloat16 *qhi_p, *qlo_p, *khi_p, *klo_p;
    cudaGetSymbolAddress((void**)&qhi_p, g_qhi); cudaGetSymbolAddress((void**)&qlo_p, g_qlo);
    cudaGetSymbolAddress((void**)&khi_p, g_khi); cudaGetSymbolAddress((void**)&klo_p, g_klo);
    k_rope_split<<<BATCH*NH*SEQ, 128>>>(qf_p, qhi_p, qlo_p);
    k_rope_split<<<BATCH*NKV*SEQ, 128>>>(kf_p, khi_p, klo_p);
    k_vT<<<dim3(HD/32, SEQ/32, BATCH*NKV), dim3(32, 32)>>>();

    // fused attention
    g_flash<<<dim3(SEQ/128, BATCH*NH), 256, FL_SMEM>>>();

    // output projection
    g_out<<<dim3(HIDDEN/256, MTOT/128), 256, DYN_SMEM>>>(out);
}

// round 12
// speedup vs baseline: 1.2643x; 1.1755x over previous
#include <cuda_runtime.h>
#include <cuda_bf16.h>
#include <cuda_fp16.h>
#include <math.h>
#include <stdint.h>

#define HIDDEN 2048
#define NH 8
#define NKV 2
#define HD 256
#define BATCH 2
#define SEQ 2048
#define MTOT (BATCH*SEQ)            // 4096
#define QDIM (NH*HD)                // 2048
#define KVDIM (NKV*HD)              // 512
#define WPROWS (QDIM + 2*KVDIM)     // 3072

// ======================= PTX helpers =======================================
__device__ __forceinline__ uint32_t smem_to_u32(const void* p) {
    uint32_t a;
    asm("{ .reg .u64 t; cvta.to.shared.u64 t, %1; cvt.u32.u64 %0, t; }" : "=r"(a) : "l"(p));
    return a;
}
__device__ __forceinline__ void cp16(uint32_t dst, const void* src) {
    asm volatile("cp.async.cg.shared.global [%0], [%1], 16;" :: "r"(dst), "l"(src));
}
__device__ __forceinline__ void cp_commit() { asm volatile("cp.async.commit_group;" ::: "memory"); }
template<int N> __device__ __forceinline__ void cp_wait() {
    asm volatile("cp.async.wait_group %0;" :: "n"(N) : "memory");
}
#define LDSM_X4(r, addr) \
    asm volatile("ldmatrix.sync.aligned.m8n8.x4.shared.b16 {%0,%1,%2,%3}, [%4];" \
        : "=r"((r)[0]), "=r"((r)[1]), "=r"((r)[2]), "=r"((r)[3]) : "r"(addr))

__device__ __forceinline__ void mma16816(float* d, const uint32_t* a, uint32_t b0, uint32_t b1) {
    asm volatile("mma.sync.aligned.m16n8k16.row.col.f32.bf16.bf16.f32 "
        "{%0,%1,%2,%3}, {%4,%5,%6,%7}, {%8,%9}, {%0,%1,%2,%3};"
        : "+f"(d[0]), "+f"(d[1]), "+f"(d[2]), "+f"(d[3])
        : "r"(a[0]), "r"(a[1]), "r"(a[2]), "r"(a[3]), "r"(b0), "r"(b1));
}
__device__ __forceinline__ void mma16816h(float* d, const uint32_t* a, uint32_t b0, uint32_t b1) {
    asm volatile("mma.sync.aligned.m16n8k16.row.col.f32.f16.f16.f32 "
        "{%0,%1,%2,%3}, {%4,%5,%6,%7}, {%8,%9}, {%0,%1,%2,%3};"
        : "+f"(d[0]), "+f"(d[1]), "+f"(d[2]), "+f"(d[3])
        : "r"(a[0]), "r"(a[1]), "r"(a[2]), "r"(a[3]), "r"(b0), "r"(b1));
}

// ======================= scratch (device globals) ==========================
__device__ __align__(16) __half g_hsh[(size_t)MTOT*HIDDEN];                        // hs single fp16
__device__ __align__(16) __half g_wph[(size_t)WPROWS*HIDDEN], g_wpl[(size_t)WPROWS*HIDDEN];
__device__ __align__(16) __half g_woh[(size_t)HIDDEN*QDIM],  g_wol[(size_t)HIDDEN*QDIM];
__device__ __align__(16) float g_qf[(size_t)MTOT*QDIM];
__device__ __align__(16) float g_kf[(size_t)BATCH*NKV*SEQ*HD];
__device__ __align__(16) float g_vf[(size_t)BATCH*NKV*SEQ*HD];
__device__ __align__(16) __nv_bfloat16 g_qhi[(size_t)MTOT*QDIM], g_qlo[(size_t)MTOT*QDIM];
__device__ __align__(16) __nv_bfloat16 g_khi[(size_t)BATCH*NKV*SEQ*HD], g_klo[(size_t)BATCH*NKV*SEQ*HD];
__device__ __align__(16) __half g_vthi[(size_t)BATCH*NKV*HD*SEQ], g_vtlo[(size_t)BATCH*NKV*HD*SEQ];
__device__ __align__(16) __half g_ah[(size_t)MTOT*QDIM];                           // attn single fp16
__device__ double g_invfreq[HD/2];
__device__ float g_cos[SEQ*(HD/2)];
__device__ float g_sin[SEQ*(HD/2)];

// ======================= small kernels =====================================
__global__ void k_invfreq() {
    int i = threadIdx.x;
    if (i < HD/2) g_invfreq[i] = pow(10000.0, -2.0 * (double)i / (double)HD);
}
__global__ void k_ropetab() {
    int s = blockIdx.x, i = threadIdx.x;
    double ang = (double)s * g_invfreq[i];
    const double twopi = 6.283185307179586476925286766559;
    ang -= floor(ang / twopi) * twopi;
    float c, sn;
    sincosf((float)ang, &sn, &c);
    g_cos[s*(HD/2)+i] = c;
    g_sin[s*(HD/2)+i] = sn;
}

__device__ __forceinline__ void split1(float x, unsigned short& h, unsigned short& l) {
    __nv_bfloat16 hb = __float2bfloat16(x);
    float r = x - __bfloat162float(hb);
    __nv_bfloat16 lb = __float2bfloat16(r);
    h = __bfloat16_as_ushort(hb);
    l = __bfloat16_as_ushort(lb);
}
__device__ __forceinline__ void split1h(float x, unsigned short& h, unsigned short& l) {
    __half hh = __float2half_rn(x);
    __half ll = __float2half_rn(x - __half2float(hh));
    h = __half_as_ushort(hh);
    l = __half_as_ushort(ll);
}

// rope + bf16 split fused (Q/K for S phase)
__global__ void k_rope_split(const float* __restrict__ src,
                             __nv_bfloat16* __restrict__ hi,
                             __nv_bfloat16* __restrict__ lo) {
    int r = blockIdx.x, i = threadIdx.x;
    int s = r & (SEQ-1);
    float c = g_cos[s*(HD/2)+i], sn = g_sin[s*(HD/2)+i];
    const float* row = src + (size_t)r * HD;
    float x1 = row[i], x2 = row[i + HD/2];
    float o1 = x1*c - x2*sn;
    float o2 = x2*c + x1*sn;
    unsigned short h, l;
    split1(o1, h, l);
    hi[(size_t)r*HD + i] = __ushort_as_bfloat16(h);
    lo[(size_t)r*HD + i] = __ushort_as_bfloat16(l);
    split1(o2, h, l);
    hi[(size_t)r*HD + i + HD/2] = __ushort_as_bfloat16(h);
    lo[(size_t)r*HD + i + HD/2] = __ushort_as_bfloat16(l);
}

// ---- fused conversion: hs -> single fp16; W -> fp16 hi/lo, ONE launch ------
#define N4_HS (MTOT*HIDDEN/4)
#define N4_WQ (QDIM*HIDDEN/4)
#define N4_WK (KVDIM*HIDDEN/4)
#define N4_WV (KVDIM*HIDDEN/4)
#define N4_WO (HIDDEN*QDIM/4)
#define N4_TOTAL (N4_HS+N4_WQ+N4_WK+N4_WV+N4_WO)

__global__ void k_split_all(const float4* __restrict__ hs, const float4* __restrict__ wq,
                            const float4* __restrict__ wk, const float4* __restrict__ wv,
                            const float4* __restrict__ wo) {
    int i = blockIdx.x * 256 + threadIdx.x;
    if (i < N4_HS) {
        float4 v = hs[i];
        uint2 H;
        H.x = (uint32_t)__half_as_ushort(__float2half_rn(v.x)) |
              ((uint32_t)__half_as_ushort(__float2half_rn(v.y)) << 16);
        H.y = (uint32_t)__half_as_ushort(__float2half_rn(v.z)) |
              ((uint32_t)__half_as_ushort(__float2half_rn(v.w)) << 16);
        ((uint2*)g_hsh)[i] = H;
        return;
    }
    const float4* src;
    uint2 *dh, *dl;
    int j;
    if (i < N4_HS + N4_WQ) {
        j = i - N4_HS; src = wq;
        dh = (uint2*)g_wph; dl = (uint2*)g_wpl;
    } else if (i < N4_HS + N4_WQ + N4_WK) {
        j = i - (N4_HS + N4_WQ); src = wk;
        dh = (uint2*)g_wph + (size_t)QDIM*HIDDEN/4;
        dl = (uint2*)g_wpl + (size_t)QDIM*HIDDEN/4;
    } else if (i < N4_HS + N4_WQ + N4_WK + N4_WV) {
        j = i - (N4_HS + N4_WQ + N4_WK); src = wv;
        dh = (uint2*)g_wph + (size_t)(QDIM+KVDIM)*HIDDEN/4;
        dl = (uint2*)g_wpl + (size_t)(QDIM+KVDIM)*HIDDEN/4;
    } else {
        j = i - (N4_HS + N4_WQ + N4_WK + N4_WV); src = wo;
        dh = (uint2*)g_woh; dl = (uint2*)g_wol;
    }
    float4 v = src[j];
    unsigned short h0,h1,h2,h3,l0,l1,l2,l3;
    split1h(v.x,h0,l0); split1h(v.y,h1,l1); split1h(v.z,h2,l2); split1h(v.w,h3,l3);
    uint2 H, L;
    H.x = (uint32_t)h0 | ((uint32_t)h1 << 16); H.y = (uint32_t)h2 | ((uint32_t)h3 << 16);
    L.x = (uint32_t)l0 | ((uint32_t)l1 << 16); L.y = (uint32_t)l2 | ((uint32_t)l3 << 16);
    dh[j] = H; dl[j] = L;
}

// transpose v [z][s][d] -> vT [z][d][s] with fp16 split
__global__ void k_vT() {
    __shared__ float t[32][33];
    int z = blockIdx.z;
    int d0 = blockIdx.x * 32, s0 = blockIdx.y * 32;
    int tx = threadIdx.x, ty = threadIdx.y;
    t[ty][tx] = g_vf[((size_t)z*SEQ + s0 + ty)*HD + d0 + tx];
    __syncthreads();
    float x = t[tx][ty];
    size_t o = ((size_t)z*HD + d0 + ty)*SEQ + s0 + tx;
    unsigned short h, l;
    split1h(x, h, l);
    g_vthi[o] = __ushort_as_half(h);
    g_vtlo[o] = __ushort_as_half(l);
}

// ======================= fp16 2-product GEMM (proj / out) ===================
// A single fp16, B fp16 hi/lo. CTA 128x256, BK=64, 8 warps 2m x 4n, occ 1.
#define RS 72                         // row stride elems (144B), 9 granules
#define MAT_A (128*RS*2)              // 18432
#define MAT_B (256*RS*2)              // 36864
#define OFF_A  0
#define OFF_BH MAT_A
#define OFF_BL (MAT_A + MAT_B)
#define STAGE_BYTES (MAT_A + 2*MAT_B)     // 92160
#define DYN_SMEM (2*STAGE_BYTES)          // 184320

__device__ __forceinline__ void load_chunk(
    const __half* __restrict__ A, int lda,
    const __half* __restrict__ Bh, const __half* __restrict__ Bl, int ldb,
    int k0, uint32_t stage)
{
    int t = threadIdx.x;
    #pragma unroll
    for (int i = 0; i < 4; i++) {            // A: 128 rows x 8 granules
        int v = t + (i << 8);
        int row = v >> 3, g = v & 7;
        uint32_t doff = (uint32_t)row * (RS*2) + (uint32_t)(g << 4);
        cp16(stage + OFF_A + doff, A + (size_t)row * lda + k0 + g*8);
    }
    #pragma unroll
    for (int i = 0; i < 8; i++) {            // B: 256 rows x 8 granules, 2 mats
        int v = t + (i << 8);
        int row = v >> 3, g = v & 7;
        uint32_t doff = (uint32_t)row * (RS*2) + (uint32_t)(g << 4);
        const size_t rb = (size_t)row * ldb + k0 + g*8;
        cp16(stage + OFF_BH + doff, Bh + rb);
        cp16(stage + OFF_BL + doff, Bl + rb);
    }
}

template<class Epi>
__device__ __forceinline__ void gemm_body(
    const __half* __restrict__ A, int lda,
    const __half* __restrict__ Bhi, const __half* __restrict__ Blo, int ldb,
    int K, Epi epi)
{
    extern __shared__ char dsm[];
    const uint32_t sbase = smem_to_u32(dsm);
    const int tid = threadIdx.x;
    const int wid = tid >> 5, lane = tid & 31;
    const int wm = wid & 1, wn = wid >> 1;        // 2m x 4n
    const int m0 = blockIdx.y * 128, n0 = blockIdx.x * 256;

    const __half* A0 = A + (size_t)m0 * lda;
    const __half* B0 = Bhi + (size_t)n0 * ldb;
    const __half* B1 = Blo + (size_t)n0 * ldb;

    float acc[4][8][4];
    #pragma unroll
    for (int a = 0; a < 4; a++)
        #pragma unroll
        for (int b = 0; b < 8; b++)
            #pragma unroll
            for (int c = 0; c < 4; c++) acc[a][b][c] = 0.0f;

    const int nc = K >> 6;
    load_chunk(A0, lda, B0, B1, ldb, 0, sbase);
    cp_commit();

    for (int c = 0; c < nc; c++) {
        cp_wait<0>();
        __syncthreads();
        if (c + 1 < nc) {
            load_chunk(A0, lda, B0, B1, ldb, (c+1) << 6,
                       sbase + (uint32_t)((c+1) & 1) * STAGE_BYTES);
            cp_commit();
        }
        const uint32_t sb = sbase + (uint32_t)(c & 1) * STAGE_BYTES;
        #pragma unroll
        for (int kk = 0; kk < 4; kk++) {
            uint32_t ah[4][4];
            #pragma unroll
            for (int mt = 0; mt < 4; mt++) {
                int row = wm*64 + mt*16 + (lane & 15);
                uint32_t off = (uint32_t)row*(RS*2) + (uint32_t)kk*32 + ((lane >> 4) << 4);
                LDSM_X4(ah[mt], sb + OFF_A + off);
            }
            #pragma unroll
            for (int nt = 0; nt < 4; nt++) {
                uint32_t bh[4], bl[4];
                int g = lane >> 3;
                int row = wn*64 + nt*16 + ((g >> 1) << 3) + (lane & 7);
                uint32_t off = (uint32_t)row*(RS*2) + (uint32_t)kk*32 + ((g & 1) << 4);
                LDSM_X4(bh, sb + OFF_BH + off);
                LDSM_X4(bl, sb + OFF_BL + off);
                #pragma unroll
                for (int mt = 0; mt < 4; mt++) {
                    mma16816h(acc[mt][nt*2+0], ah[mt], bh[0], bh[1]);
                    mma16816h(acc[mt][nt*2+0], ah[mt], bl[0], bl[1]);
                    mma16816h(acc[mt][nt*2+1], ah[mt], bh[2], bh[3]);
                    mma16816h(acc[mt][nt*2+1], ah[mt], bl[2], bl[3]);
                }
            }
        }
    }

    #pragma unroll
    for (int mt = 0; mt < 4; mt++)
        #pragma unroll
        for (int nj = 0; nj < 8; nj++)
            #pragma unroll
            for (int e = 0; e < 4; e++) {
                int m = m0 + wm*64 + mt*16 + (lane >> 2) + ((e >> 1) << 3);
                int n = n0 + wn*64 + nj*8 + ((lane & 3) << 1) + (e & 1);
                epi(m, n, acc[mt][nj][e]);
            }
}

struct EpiProjFused {
    __device__ __forceinline__ void operator()(int m, int n, float v) const {
        int b = m >> 11, s = m & (SEQ-1);
        if (n < QDIM) {
            int h = n >> 8, d = n & (HD-1);
            g_qf[(((size_t)b*NH + h)*SEQ + s)*HD + d] = v;
        } else if (n < QDIM + KVDIM) {
            int nn = n - QDIM;
            int h = nn >> 8, d = nn & (HD-1);
            g_kf[(((size_t)b*NKV + h)*SEQ + s)*HD + d] = v;
        } else {
            int nn = n - QDIM - KVDIM;
            int h = nn >> 8, d = nn & (HD-1);
            g_vf[(((size_t)b*NKV + h)*SEQ + s)*HD + d] = v;
        }
    }
};
struct EpiPlain {
    float* C; int ldc;
    __device__ __forceinline__ void operator()(int m, int n, float v) const {
        C[(size_t)m*ldc + n] = v;
    }
};

__global__ void __launch_bounds__(256, 1) g_proj() {
    gemm_body(g_hsh, HIDDEN, g_wph, g_wpl, HIDDEN, HIDDEN, EpiProjFused{});
}
__global__ void __launch_bounds__(256, 1) g_out(float* __restrict__ out) {
    gemm_body(g_ah, QDIM, g_woh, g_wol, QDIM, QDIM, EpiPlain{out, HIDDEN});
}

// ======================= flash attention ===================================
#define FL_QK_STAGE 40960
#define FL_V_BASE   81920
#define FL_V_STAGE  40960
#define FL_SMEM     163840

__device__ __forceinline__ void fl_load_qk(
    const __nv_bfloat16* __restrict__ Qh, const __nv_bfloat16* __restrict__ Ql,
    const __nv_bfloat16* __restrict__ Kh, const __nv_bfloat16* __restrict__ Kl,
    int s0, int c, uint32_t stage)
{
    int tid = threadIdx.x;
    #pragma unroll
    for (int i = 0; i < 8; i++) {
        const int mat = i >> 1;                     // 0 Qh, 1 Ql, 2 Kh, 3 Kl
        int w = ((i & 1) << 8) + tid;
        int row = w >> 2, g = w & 3;
        uint32_t dst = stage + (uint32_t)mat*10240 + (uint32_t)row*80 + (uint32_t)(g << 4);
        size_t col = (size_t)(c*32 + g*8);
        if (mat == 0)      cp16(dst, Qh + (size_t)row*HD + col);
        else if (mat == 1) cp16(dst, Ql + (size_t)row*HD + col);
        else if (mat == 2) cp16(dst, Kh + (size_t)(s0 + row)*HD + col);
        else               cp16(dst, Kl + (size_t)(s0 + row)*HD + col);
    }
}
__device__ __forceinline__ void fl_load_v(
    const __half* __restrict__ Vh, const __half* __restrict__ Vl,
    int s0, int sl, uint32_t stage)
{
    int tid = threadIdx.x;
    #pragma unroll
    for (int i = 0; i < 8; i++) {
        const int mat = i >> 2;                     // 0 Vh, 1 Vl
        int w = ((i & 3) << 8) + tid;
        int row = w >> 2, g = w & 3;                // row 0..255 (d)
        uint32_t dst = stage + (uint32_t)mat*20480 + (uint32_t)row*80 + (uint32_t)(g << 4);
        size_t col = (size_t)(s0 + sl*32 + g*8);
        if (mat == 0) cp16(dst, Vh + (size_t)row*SEQ + col);
        else          cp16(dst, Vl + (size_t)row*SEQ + col);
    }
}

__global__ void __launch_bounds__(256, 1) g_flash() {
    extern __shared__ char dsm[];
    const uint32_t sb = smem_to_u32(dsm);
    const int tid = threadIdx.x, wid = tid >> 5, lane = tid & 31;
    const int qt = blockIdx.x, z = blockIdx.y;
    const int b = z >> 3, h = z & 7, kv = h >> 2;
    const int q0 = qt * 128;

    const __nv_bfloat16* Qh = g_qhi + (size_t)z*SEQ*HD + (size_t)q0*HD;
    const __nv_bfloat16* Ql = g_qlo + (size_t)z*SEQ*HD + (size_t)q0*HD;
    const __nv_bfloat16* Kh = g_khi + (size_t)(b*NKV+kv)*SEQ*HD;
    const __nv_bfloat16* Kl = g_klo + (size_t)(b*NKV+kv)*SEQ*HD;
    const __half* Vh = g_vthi + (size_t)(b*NKV+kv)*HD*SEQ;
    const __half* Vl = g_vtlo + (size_t)(b*NKV+kv)*HD*SEQ;

    float acc_o[32][4];
    #pragma unroll
    for (int i = 0; i < 32; i++)
        #pragma unroll
        for (int e = 0; e < 4; e++) acc_o[i][e] = 0.0f;
    float rm[2] = {-1e30f, -1e30f};
    float rl[2] = {0.0f, 0.0f};

    fl_load_qk(Qh, Ql, Kh, Kl, 0, 0, sb);
    cp_commit();

    for (int kt = 0; kt < 16; kt++) {
        const int s0 = kt * 128;
        float acc_s[16][4];
        #pragma unroll
        for (int i = 0; i < 16; i++)
            #pragma unroll
            for (int e = 0; e < 4; e++) acc_s[i][e] = 0.0f;

        // ---- S phase: 8 d-chunks (bf16 3-product) ----
        for (int c = 0; c < 8; c++) {
            cp_wait<0>();
            __syncthreads();
            if (c < 7) fl_load_qk(Qh, Ql, Kh, Kl, s0, c+1, sb + (uint32_t)((c+1)&1)*FL_QK_STAGE);
            else       fl_load_v(Vh, Vl, s0, 0, sb + FL_V_BASE);
            cp_commit();
            const uint32_t qkb = sb + (uint32_t)(c & 1) * FL_QK_STAGE;
            #pragma unroll
            for (int kk = 0; kk < 2; kk++) {
                uint32_t qh[4], ql[4];
                uint32_t a_off = (uint32_t)(wid*16 + (lane & 15))*80 + (uint32_t)kk*32 + ((lane >> 4) << 4);
                LDSM_X4(qh, qkb + a_off);
                LDSM_X4(ql, qkb + 10240 + a_off);
                int g = lane >> 3;
                uint32_t c_off = (uint32_t)kk*32 + ((g & 1) << 4);
                #pragma unroll
                for (int nt2 = 0; nt2 < 8; nt2++) {
                    int row = nt2*16 + ((g >> 1) << 3) + (lane & 7);
                    uint32_t kh[4], kl[4];
                    LDSM_X4(kh, qkb + 20480 + (uint32_t)row*80 + c_off);
                    LDSM_X4(kl, qkb + 30720 + (uint32_t)row*80 + c_off);
                    mma16816(acc_s[2*nt2],   qh, kh[0], kh[1]);
                    mma16816(acc_s[2*nt2],   qh, kl[0], kl[1]);
                    mma16816(acc_s[2*nt2],   ql, kh[0], kh[1]);
                    mma16816(acc_s[2*nt2+1], qh, kh[2], kh[3]);
                    mma16816(acc_s[2*nt2+1], qh, kl[2], kl[3]);
                    mma16816(acc_s[2*nt2+1], ql, kh[2], kh[3]);
                }
            }
        }

        // ---- softmax (register-resident); P as single fp16 ----
        float mnew[2] = {-1e30f, -1e30f};
        #pragma unroll
        for (int nt = 0; nt < 16; nt++)
            #pragma unroll
            for (int e = 0; e < 4; e++) {
                float s = acc_s[nt][e];
                float y = s * 0.00125f;
                float y2 = y * y;
                float capped = s * 0.0625f * (1.0f - y2*(0.33333333f - y2*0.13333333f));
                acc_s[nt][e] = capped;
                mnew[e >> 1] = fmaxf(mnew[e >> 1], capped);
            }
        #pragma unroll
        for (int o = 1; o <= 2; o <<= 1) {
            mnew[0] = fmaxf(mnew[0], __shfl_xor_sync(0xFFFFFFFFu, mnew[0], o));
            mnew[1] = fmaxf(mnew[1], __shfl_xor_sync(0xFFFFFFFFu, mnew[1], o));
        }
        float mt[2], al[2];
        #pragma unroll
        for (int j = 0; j < 2; j++) {
            mt[j] = fmaxf(rm[j], mnew[j]);
            al[j] = __expf(rm[j] - mt[j]);
            rm[j] = mt[j];
        }
        uint32_t ph[8][4];
        float sum[2] = {0.0f, 0.0f};
        #pragma unroll
        for (int g2 = 0; g2 < 8; g2++) {
            unsigned short hh[8];
            #pragma unroll
            for (int half = 0; half < 2; half++) {
                int nt = 2*g2 + half;
                #pragma unroll
                for (int e = 0; e < 4; e++) {
                    float p = __expf(acc_s[nt][e] - mt[e >> 1]);
                    sum[e >> 1] += p;
                    hh[half*4+e] = __half_as_ushort(__float2half_rn(p));
                }
            }
            ph[g2][0] = (uint32_t)hh[0] | ((uint32_t)hh[1] << 16);
            ph[g2][1] = (uint32_t)hh[2] | ((uint32_t)hh[3] << 16);
            ph[g2][2] = (uint32_t)hh[4] | ((uint32_t)hh[5] << 16);
            ph[g2][3] = (uint32_t)hh[6] | ((uint32_t)hh[7] << 16);
        }
        #pragma unroll
        for (int o = 1; o <= 2; o <<= 1) {
            sum[0] += __shfl_xor_sync(0xFFFFFFFFu, sum[0], o);
            sum[1] += __shfl_xor_sync(0xFFFFFFFFu, sum[1], o);
        }
        rl[0] = rl[0]*al[0] + sum[0];
        rl[1] = rl[1]*al[1] + sum[1];
        #pragma unroll
        for (int nt = 0; nt < 32; nt++)
            #pragma unroll
            for (int e = 0; e < 4; e++) acc_o[nt][e] *= al[e >> 1];

        // ---- PV phase: fp16, 2 products ----
        for (int sl = 0; sl < 4; sl++) {
            cp_wait<0>();
            __syncthreads();
            if (sl < 3)       fl_load_v(Vh, Vl, s0, sl+1, sb + FL_V_BASE + (uint32_t)((sl+1)&1)*FL_V_STAGE);
            else if (kt < 15) fl_load_qk(Qh, Ql, Kh, Kl, s0 + 128, 0, sb);
            cp_commit();
            const uint32_t vb = sb + FL_V_BASE + (uint32_t)(sl & 1) * FL_V_STAGE;
            #pragma unroll
            for (int kk = 0; kk < 2; kk++) {
                const int g2 = sl*2 + kk;
                int g = lane >> 3;
                uint32_t c_off = (uint32_t)kk*32 + ((g & 1) << 4);
                #pragma unroll
                for (int nt2 = 0; nt2 < 16; nt2++) {
                    int row = nt2*16 + ((g >> 1) << 3) + (lane & 7);
                    uint32_t vh[4], vl[4];
                    LDSM_X4(vh, vb + (uint32_t)row*80 + c_off);
                    LDSM_X4(vl, vb + 20480 + (uint32_t)row*80 + c_off);
                    mma16816h(acc_o[2*nt2],   ph[g2], vh[0], vh[1]);
                    mma16816h(acc_o[2*nt2],   ph[g2], vl[0], vl[1]);
                    mma16816h(acc_o[2*nt2+1], ph[g2], vh[2], vh[3]);
                    mma16816h(acc_o[2*nt2+1], ph[g2], vl[2], vl[3]);
                }
            }
        }
    }

    // ---- epilogue: normalize + single fp16 store ----
    float inv[2] = {1.0f / rl[0], 1.0f / rl[1]};
    #pragma unroll
    for (int nt = 0; nt < 32; nt++)
        #pragma unroll
        for (int j = 0; j < 2; j++) {
            int rloc = wid*16 + (lane >> 2) + j*8;
            size_t m = (size_t)b*SEQ + q0 + rloc;
            int d = nt*8 + (lane & 3)*2;
            size_t o = m*QDIM + h*HD + d;
            float v0 = acc_o[nt][2*j+0] * inv[j];
            float v1 = acc_o[nt][2*j+1] * inv[j];
            uint32_t pack = (uint32_t)__half_as_ushort(__float2half_rn(v0)) |
                            ((uint32_t)__half_as_ushort(__float2half_rn(v1)) << 16);
            *(uint32_t*)(g_ah + o) = pack;
        }
}

// ======================= launch ============================================
extern "C" void kernel_launch(void* const* d_in, const int* in_sizes, int n_in,
                              void* d_out, int out_size) {
    const float* hs = (const float*)d_in[0];
    const float* Wq = (const float*)d_in[1];
    const float* Wk = (const float*)d_in[2];
    const float* Wv = (const float*)d_in[3];
    const float* Wo = (const float*)d_in[4];
    float* out = (float*)d_out;
    (void)in_sizes; (void)n_in; (void)out_size;

    cudaFuncSetAttribute(g_proj,  cudaFuncAttributeMaxDynamicSharedMemorySize, DYN_SMEM);
    cudaFuncSetAttribute(g_out,   cudaFuncAttributeMaxDynamicSharedMemorySize, DYN_SMEM);
    cudaFuncSetAttribute(g_flash, cudaFuncAttributeMaxDynamicSharedMemorySize, FL_SMEM);

    // launch 1: fused conversion of all fp32 inputs
    k_split_all<<<N4_TOTAL/256, 256>>>((const float4*)hs, (const float4*)Wq,
                                       (const float4*)Wk, (const float4*)Wv,
                                       (const float4*)Wo);
    // launches 2-3: rope tables
    k_invfreq<<<1, 128>>>();
    k_ropetab<<<SEQ, 128>>>();

    // launch 4: fused QKV projection (profiled slot)
    g_proj<<<dim3(WPROWS/256, MTOT/128), 256, DYN_SMEM>>>();

    // rope + split, vT
    float *qf_p, *kf_p;
    cudaGetSymbolAddress((void**)&qf_p, g_qf);
    cudaGetSymbolAddress((void**)&kf_p, g_kf);
    __nv_bfloat16 *qhi_p, *qlo_p, *khi_p, *klo_p;
    cudaGetSymbolAddress((void**)&qhi_p, g_qhi); cudaGetSymbolAddress((void**)&qlo_p, g_qlo);
    cudaGetSymbolAddress((void**)&khi_p, g_khi); cudaGetSymbolAddress((void**)&klo_p, g_klo);
    k_rope_split<<<BATCH*NH*SEQ, 128>>>(qf_p, qhi_p, qlo_p);
    k_rope_split<<<BATCH*NKV*SEQ, 128>>>(kf_p, khi_p, klo_p);
    k_vT<<<dim3(HD/32, SEQ/32, BATCH*NKV), dim3(32, 32)>>>();

    // fused attention
    g_flash<<<dim3(SEQ/128, BATCH*NH), 256, FL_SMEM>>>();

    // output projection
    g_out<<<dim3(HIDDEN/256, MTOT/128), 256, DYN_SMEM>>>(out);
}

// round 13
// speedup vs baseline: 1.3866x; 1.0967x over previous
#include <cuda_runtime.h>
#include <cuda_bf16.h>
#include <cuda_fp16.h>
#include <math.h>
#include <stdint.h>

#define HIDDEN 2048
#define NH 8
#define NKV 2
#define HD 256
#define BATCH 2
#define SEQ 2048
#define MTOT (BATCH*SEQ)            // 4096
#define QDIM (NH*HD)                // 2048
#define KVDIM (NKV*HD)              // 512
#define WPROWS (QDIM + 2*KVDIM)     // 3072

// ======================= PTX helpers =======================================
__device__ __forceinline__ uint32_t smem_to_u32(const void* p) {
    uint32_t a;
    asm("{ .reg .u64 t; cvta.to.shared.u64 t, %1; cvt.u32.u64 %0, t; }" : "=r"(a) : "l"(p));
    return a;
}
__device__ __forceinline__ void cp16(uint32_t dst, const void* src) {
    asm volatile("cp.async.cg.shared.global [%0], [%1], 16;" :: "r"(dst), "l"(src));
}
__device__ __forceinline__ void cp_commit() { asm volatile("cp.async.commit_group;" ::: "memory"); }
template<int N> __device__ __forceinline__ void cp_wait() {
    asm volatile("cp.async.wait_group %0;" :: "n"(N) : "memory");
}
#define LDSM_X4(r, addr) \
    asm volatile("ldmatrix.sync.aligned.m8n8.x4.shared.b16 {%0,%1,%2,%3}, [%4];" \
        : "=r"((r)[0]), "=r"((r)[1]), "=r"((r)[2]), "=r"((r)[3]) : "r"(addr))

__device__ __forceinline__ void mma16816h(float* d, const uint32_t* a, uint32_t b0, uint32_t b1) {
    asm volatile("mma.sync.aligned.m16n8k16.row.col.f32.f16.f16.f32 "
        "{%0,%1,%2,%3}, {%4,%5,%6,%7}, {%8,%9}, {%0,%1,%2,%3};"
        : "+f"(d[0]), "+f"(d[1]), "+f"(d[2]), "+f"(d[3])
        : "r"(a[0]), "r"(a[1]), "r"(a[2]), "r"(a[3]), "r"(b0), "r"(b1));
}

// ======================= scratch (device globals) ==========================
__device__ __align__(16) __half g_hsh[(size_t)MTOT*HIDDEN];                        // hs single fp16
__device__ __align__(16) __half g_wph[(size_t)WPROWS*HIDDEN], g_wpl[(size_t)WPROWS*HIDDEN];
__device__ __align__(16) __half g_woh[(size_t)HIDDEN*QDIM],  g_wol[(size_t)HIDDEN*QDIM];
__device__ __align__(16) float g_qf[(size_t)MTOT*QDIM];
__device__ __align__(16) float g_kf[(size_t)BATCH*NKV*SEQ*HD];
__device__ __align__(16) float g_vf[(size_t)BATCH*NKV*SEQ*HD];
__device__ __align__(16) __half g_qh[(size_t)MTOT*QDIM];                           // q single fp16
__device__ __align__(16) __half g_kh[(size_t)BATCH*NKV*SEQ*HD], g_kl[(size_t)BATCH*NKV*SEQ*HD];
__device__ __align__(16) __half g_vthi[(size_t)BATCH*NKV*HD*SEQ], g_vtlo[(size_t)BATCH*NKV*HD*SEQ];
__device__ __align__(16) __half g_ah[(size_t)MTOT*QDIM];                           // attn single fp16
__device__ double g_invfreq[HD/2];
__device__ float g_cos[SEQ*(HD/2)];
__device__ float g_sin[SEQ*(HD/2)];

// ======================= small kernels =====================================
__global__ void k_invfreq() {
    int i = threadIdx.x;
    if (i < HD/2) g_invfreq[i] = pow(10000.0, -2.0 * (double)i / (double)HD);
}
__global__ void k_ropetab() {
    int s = blockIdx.x, i = threadIdx.x;
    double ang = (double)s * g_invfreq[i];
    const double twopi = 6.283185307179586476925286766559;
    ang -= floor(ang / twopi) * twopi;
    float c, sn;
    sincosf((float)ang, &sn, &c);
    g_cos[s*(HD/2)+i] = c;
    g_sin[s*(HD/2)+i] = sn;
}

__device__ __forceinline__ void split1h(float x, unsigned short& h, unsigned short& l) {
    __half hh = __float2half_rn(x);
    __half ll = __float2half_rn(x - __half2float(hh));
    h = __half_as_ushort(hh);
    l = __half_as_ushort(ll);
}

// rope + single fp16 (Q)
__global__ void k_rope_q(const float* __restrict__ src, __half* __restrict__ dst) {
    int r = blockIdx.x, i = threadIdx.x;
    int s = r & (SEQ-1);
    float c = g_cos[s*(HD/2)+i], sn = g_sin[s*(HD/2)+i];
    const float* row = src + (size_t)r * HD;
    float x1 = row[i], x2 = row[i + HD/2];
    dst[(size_t)r*HD + i]        = __float2half_rn(x1*c - x2*sn);
    dst[(size_t)r*HD + i + HD/2] = __float2half_rn(x2*c + x1*sn);
}
// rope + fp16 hi/lo split (K)
__global__ void k_rope_k(const float* __restrict__ src,
                         __half* __restrict__ hi, __half* __restrict__ lo) {
    int r = blockIdx.x, i = threadIdx.x;
    int s = r & (SEQ-1);
    float c = g_cos[s*(HD/2)+i], sn = g_sin[s*(HD/2)+i];
    const float* row = src + (size_t)r * HD;
    float x1 = row[i], x2 = row[i + HD/2];
    float o1 = x1*c - x2*sn;
    float o2 = x2*c + x1*sn;
    unsigned short h, l;
    split1h(o1, h, l);
    hi[(size_t)r*HD + i] = __ushort_as_half(h);
    lo[(size_t)r*HD + i] = __ushort_as_half(l);
    split1h(o2, h, l);
    hi[(size_t)r*HD + i + HD/2] = __ushort_as_half(h);
    lo[(size_t)r*HD + i + HD/2] = __ushort_as_half(l);
}

// ---- fused conversion: hs -> single fp16; W -> fp16 hi/lo, ONE launch ------
#define N4_HS (MTOT*HIDDEN/4)
#define N4_WQ (QDIM*HIDDEN/4)
#define N4_WK (KVDIM*HIDDEN/4)
#define N4_WV (KVDIM*HIDDEN/4)
#define N4_WO (HIDDEN*QDIM/4)
#define N4_TOTAL (N4_HS+N4_WQ+N4_WK+N4_WV+N4_WO)

__global__ void k_split_all(const float4* __restrict__ hs, const float4* __restrict__ wq,
                            const float4* __restrict__ wk, const float4* __restrict__ wv,
                            const float4* __restrict__ wo) {
    int i = blockIdx.x * 256 + threadIdx.x;
    if (i < N4_HS) {
        float4 v = hs[i];
        uint2 H;
        H.x = (uint32_t)__half_as_ushort(__float2half_rn(v.x)) |
              ((uint32_t)__half_as_ushort(__float2half_rn(v.y)) << 16);
        H.y = (uint32_t)__half_as_ushort(__float2half_rn(v.z)) |
              ((uint32_t)__half_as_ushort(__float2half_rn(v.w)) << 16);
        ((uint2*)g_hsh)[i] = H;
        return;
    }
    const float4* src;
    uint2 *dh, *dl;
    int j;
    if (i < N4_HS + N4_WQ) {
        j = i - N4_HS; src = wq;
        dh = (uint2*)g_wph; dl = (uint2*)g_wpl;
    } else if (i < N4_HS + N4_WQ + N4_WK) {
        j = i - (N4_HS + N4_WQ); src = wk;
        dh = (uint2*)g_wph + (size_t)QDIM*HIDDEN/4;
        dl = (uint2*)g_wpl + (size_t)QDIM*HIDDEN/4;
    } else if (i < N4_HS + N4_WQ + N4_WK + N4_WV) {
        j = i - (N4_HS + N4_WQ + N4_WK); src = wv;
        dh = (uint2*)g_wph + (size_t)(QDIM+KVDIM)*HIDDEN/4;
        dl = (uint2*)g_wpl + (size_t)(QDIM+KVDIM)*HIDDEN/4;
    } else {
        j = i - (N4_HS + N4_WQ + N4_WK + N4_WV); src = wo;
        dh = (uint2*)g_woh; dl = (uint2*)g_wol;
    }
    float4 v = src[j];
    unsigned short h0,h1,h2,h3,l0,l1,l2,l3;
    split1h(v.x,h0,l0); split1h(v.y,h1,l1); split1h(v.z,h2,l2); split1h(v.w,h3,l3);
    uint2 H, L;
    H.x = (uint32_t)h0 | ((uint32_t)h1 << 16); H.y = (uint32_t)h2 | ((uint32_t)h3 << 16);
    L.x = (uint32_t)l0 | ((uint32_t)l1 << 16); L.y = (uint32_t)l2 | ((uint32_t)l3 << 16);
    dh[j] = H; dl[j] = L;
}

// transpose v [z][s][d] -> vT [z][d][s] with fp16 split
__global__ void k_vT() {
    __shared__ float t[32][33];
    int z = blockIdx.z;
    int d0 = blockIdx.x * 32, s0 = blockIdx.y * 32;
    int tx = threadIdx.x, ty = threadIdx.y;
    t[ty][tx] = g_vf[((size_t)z*SEQ + s0 + ty)*HD + d0 + tx];
    __syncthreads();
    float x = t[tx][ty];
    size_t o = ((size_t)z*HD + d0 + ty)*SEQ + s0 + tx;
    unsigned short h, l;
    split1h(x, h, l);
    g_vthi[o] = __ushort_as_half(h);
    g_vtlo[o] = __ushort_as_half(l);
}

// ======================= fp16 2-product GEMM (proj / out) ===================
#define RS 72                         // row stride elems (144B), 9 granules
#define MAT_A (128*RS*2)              // 18432
#define MAT_B (256*RS*2)              // 36864
#define OFF_A  0
#define OFF_BH MAT_A
#define OFF_BL (MAT_A + MAT_B)
#define STAGE_BYTES (MAT_A + 2*MAT_B)     // 92160
#define DYN_SMEM (2*STAGE_BYTES)          // 184320

__device__ __forceinline__ void load_chunk(
    const __half* __restrict__ A, int lda,
    const __half* __restrict__ Bh, const __half* __restrict__ Bl, int ldb,
    int k0, uint32_t stage)
{
    int t = threadIdx.x;
    #pragma unroll
    for (int i = 0; i < 4; i++) {
        int v = t + (i << 8);
        int row = v >> 3, g = v & 7;
        uint32_t doff = (uint32_t)row * (RS*2) + (uint32_t)(g << 4);
        cp16(stage + OFF_A + doff, A + (size_t)row * lda + k0 + g*8);
    }
    #pragma unroll
    for (int i = 0; i < 8; i++) {
        int v = t + (i << 8);
        int row = v >> 3, g = v & 7;
        uint32_t doff = (uint32_t)row * (RS*2) + (uint32_t)(g << 4);
        const size_t rb = (size_t)row * ldb + k0 + g*8;
        cp16(stage + OFF_BH + doff, Bh + rb);
        cp16(stage + OFF_BL + doff, Bl + rb);
    }
}

template<class Epi>
__device__ __forceinline__ void gemm_body(
    const __half* __restrict__ A, int lda,
    const __half* __restrict__ Bhi, const __half* __restrict__ Blo, int ldb,
    int K, Epi epi)
{
    extern __shared__ char dsm[];
    const uint32_t sbase = smem_to_u32(dsm);
    const int tid = threadIdx.x;
    const int wid = tid >> 5, lane = tid & 31;
    const int wm = wid & 1, wn = wid >> 1;        // 2m x 4n
    const int m0 = blockIdx.y * 128, n0 = blockIdx.x * 256;

    const __half* A0 = A + (size_t)m0 * lda;
    const __half* B0 = Bhi + (size_t)n0 * ldb;
    const __half* B1 = Blo + (size_t)n0 * ldb;

    float acc[4][8][4];
    #pragma unroll
    for (int a = 0; a < 4; a++)
        #pragma unroll
        for (int b = 0; b < 8; b++)
            #pragma unroll
            for (int c = 0; c < 4; c++) acc[a][b][c] = 0.0f;

    const int nc = K >> 6;
    load_chunk(A0, lda, B0, B1, ldb, 0, sbase);
    cp_commit();

    for (int c = 0; c < nc; c++) {
        cp_wait<0>();
        __syncthreads();
        if (c + 1 < nc) {
            load_chunk(A0, lda, B0, B1, ldb, (c+1) << 6,
                       sbase + (uint32_t)((c+1) & 1) * STAGE_BYTES);
            cp_commit();
        }
        const uint32_t sb = sbase + (uint32_t)(c & 1) * STAGE_BYTES;
        #pragma unroll
        for (int kk = 0; kk < 4; kk++) {
            uint32_t ah[4][4];
            #pragma unroll
            for (int mt = 0; mt < 4; mt++) {
                int row = wm*64 + mt*16 + (lane & 15);
                uint32_t off = (uint32_t)row*(RS*2) + (uint32_t)kk*32 + ((lane >> 4) << 4);
                LDSM_X4(ah[mt], sb + OFF_A + off);
            }
            #pragma unroll
            for (int nt = 0; nt < 4; nt++) {
                uint32_t bh[4], bl[4];
                int g = lane >> 3;
                int row = wn*64 + nt*16 + ((g >> 1) << 3) + (lane & 7);
                uint32_t off = (uint32_t)row*(RS*2) + (uint32_t)kk*32 + ((g & 1) << 4);
                LDSM_X4(bh, sb + OFF_BH + off);
                LDSM_X4(bl, sb + OFF_BL + off);
                #pragma unroll
                for (int mt = 0; mt < 4; mt++) {
                    mma16816h(acc[mt][nt*2+0], ah[mt], bh[0], bh[1]);
                    mma16816h(acc[mt][nt*2+0], ah[mt], bl[0], bl[1]);
                    mma16816h(acc[mt][nt*2+1], ah[mt], bh[2], bh[3]);
                    mma16816h(acc[mt][nt*2+1], ah[mt], bl[2], bl[3]);
                }
            }
        }
    }

    #pragma unroll
    for (int mt = 0; mt < 4; mt++)
        #pragma unroll
        for (int nj = 0; nj < 8; nj++)
            #pragma unroll
            for (int e = 0; e < 4; e++) {
                int m = m0 + wm*64 + mt*16 + (lane >> 2) + ((e >> 1) << 3);
                int n = n0 + wn*64 + nj*8 + ((lane & 3) << 1) + (e & 1);
                epi(m, n, acc[mt][nj][e]);
            }
}

struct EpiProjFused {
    __device__ __forceinline__ void operator()(int m, int n, float v) const {
        int b = m >> 11, s = m & (SEQ-1);
        if (n < QDIM) {
            int h = n >> 8, d = n & (HD-1);
            g_qf[(((size_t)b*NH + h)*SEQ + s)*HD + d] = v;
        } else if (n < QDIM + KVDIM) {
            int nn = n - QDIM;
            int h = nn >> 8, d = nn & (HD-1);
            g_kf[(((size_t)b*NKV + h)*SEQ + s)*HD + d] = v;
        } else {
            int nn = n - QDIM - KVDIM;
            int h = nn >> 8, d = nn & (HD-1);
            g_vf[(((size_t)b*NKV + h)*SEQ + s)*HD + d] = v;
        }
    }
};
struct EpiPlain {
    float* C; int ldc;
    __device__ __forceinline__ void operator()(int m, int n, float v) const {
        C[(size_t)m*ldc + n] = v;
    }
};

__global__ void __launch_bounds__(256, 1) g_proj() {
    gemm_body(g_hsh, HIDDEN, g_wph, g_wpl, HIDDEN, HIDDEN, EpiProjFused{});
}
__global__ void __launch_bounds__(256, 1) g_out(float* __restrict__ out) {
    gemm_body(g_ah, QDIM, g_woh, g_wol, QDIM, QDIM, EpiPlain{out, HIDDEN});
}

// ======================= flash attention ===================================
// S phase: Q single fp16 (1 mat) + K fp16 hi/lo (2 mats) -> 3 mats/stage.
#define FL_QK_STAGE 30720
#define FL_V_BASE   61440
#define FL_V_STAGE  40960
#define FL_SMEM     143360

__device__ __forceinline__ void fl_load_qk(
    const __half* __restrict__ Q,
    const __half* __restrict__ Kh, const __half* __restrict__ Kl,
    int s0, int c, uint32_t stage)
{
    int tid = threadIdx.x;
    #pragma unroll
    for (int i = 0; i < 6; i++) {
        const int mat = i >> 1;                     // 0 Q, 1 Kh, 2 Kl
        int w = ((i & 1) << 8) + tid;
        int row = w >> 2, g = w & 3;
        uint32_t dst = stage + (uint32_t)mat*10240 + (uint32_t)row*80 + (uint32_t)(g << 4);
        size_t col = (size_t)(c*32 + g*8);
        if (mat == 0)      cp16(dst, Q + (size_t)row*HD + col);
        else if (mat == 1) cp16(dst, Kh + (size_t)(s0 + row)*HD + col);
        else               cp16(dst, Kl + (size_t)(s0 + row)*HD + col);
    }
}
__device__ __forceinline__ void fl_load_v(
    const __half* __restrict__ Vh, const __half* __restrict__ Vl,
    int s0, int sl, uint32_t stage)
{
    int tid = threadIdx.x;
    #pragma unroll
    for (int i = 0; i < 8; i++) {
        const int mat = i >> 2;                     // 0 Vh, 1 Vl
        int w = ((i & 3) << 8) + tid;
        int row = w >> 2, g = w & 3;                // row 0..255 (d)
        uint32_t dst = stage + (uint32_t)mat*20480 + (uint32_t)row*80 + (uint32_t)(g << 4);
        size_t col = (size_t)(s0 + sl*32 + g*8);
        if (mat == 0) cp16(dst, Vh + (size_t)row*SEQ + col);
        else          cp16(dst, Vl + (size_t)row*SEQ + col);
    }
}

__global__ void __launch_bounds__(256, 1) g_flash() {
    extern __shared__ char dsm[];
    const uint32_t sb = smem_to_u32(dsm);
    const int tid = threadIdx.x, wid = tid >> 5, lane = tid & 31;
    const int qt = blockIdx.x, z = blockIdx.y;
    const int b = z >> 3, h = z & 7, kv = h >> 2;
    const int q0 = qt * 128;

    const __half* Q  = g_qh + (size_t)z*SEQ*HD + (size_t)q0*HD;
    const __half* Kh = g_kh + (size_t)(b*NKV+kv)*SEQ*HD;
    const __half* Kl = g_kl + (size_t)(b*NKV+kv)*SEQ*HD;
    const __half* Vh = g_vthi + (size_t)(b*NKV+kv)*HD*SEQ;
    const __half* Vl = g_vtlo + (size_t)(b*NKV+kv)*HD*SEQ;

    float acc_o[32][4];
    #pragma unroll
    for (int i = 0; i < 32; i++)
        #pragma unroll
        for (int e = 0; e < 4; e++) acc_o[i][e] = 0.0f;
    float rm[2] = {-1e30f, -1e30f};
    float rl[2] = {0.0f, 0.0f};

    fl_load_qk(Q, Kh, Kl, 0, 0, sb);
    cp_commit();

    for (int kt = 0; kt < 16; kt++) {
        const int s0 = kt * 128;
        float acc_s[16][4];
        #pragma unroll
        for (int i = 0; i < 16; i++)
            #pragma unroll
            for (int e = 0; e < 4; e++) acc_s[i][e] = 0.0f;

        // ---- S phase: 8 d-chunks (fp16, 2 products: Q x Khi + Q x Klo) ----
        for (int c = 0; c < 8; c++) {
            cp_wait<0>();
            __syncthreads();
            if (c < 7) fl_load_qk(Q, Kh, Kl, s0, c+1, sb + (uint32_t)((c+1)&1)*FL_QK_STAGE);
            else       fl_load_v(Vh, Vl, s0, 0, sb + FL_V_BASE);
            cp_commit();
            const uint32_t qkb = sb + (uint32_t)(c & 1) * FL_QK_STAGE;
            #pragma unroll
            for (int kk = 0; kk < 2; kk++) {
                uint32_t qf[4];
                uint32_t a_off = (uint32_t)(wid*16 + (lane & 15))*80 + (uint32_t)kk*32 + ((lane >> 4) << 4);
                LDSM_X4(qf, qkb + a_off);
                int g = lane >> 3;
                uint32_t c_off = (uint32_t)kk*32 + ((g & 1) << 4);
                #pragma unroll
                for (int nt2 = 0; nt2 < 8; nt2++) {
                    int row = nt2*16 + ((g >> 1) << 3) + (lane & 7);
                    uint32_t kh[4], kl[4];
                    LDSM_X4(kh, qkb + 10240 + (uint32_t)row*80 + c_off);
                    LDSM_X4(kl, qkb + 20480 + (uint32_t)row*80 + c_off);
                    mma16816h(acc_s[2*nt2],   qf, kh[0], kh[1]);
                    mma16816h(acc_s[2*nt2],   qf, kl[0], kl[1]);
                    mma16816h(acc_s[2*nt2+1], qf, kh[2], kh[3]);
                    mma16816h(acc_s[2*nt2+1], qf, kl[2], kl[3]);
                }
            }
        }

        // ---- softmax (register-resident); P as single fp16 ----
        float mnew[2] = {-1e30f, -1e30f};
        #pragma unroll
        for (int nt = 0; nt < 16; nt++)
            #pragma unroll
            for (int e = 0; e < 4; e++) {
                float s = acc_s[nt][e];
                float y = s * 0.00125f;
                float y2 = y * y;
                float capped = s * 0.0625f * (1.0f - y2*(0.33333333f - y2*0.13333333f));
                acc_s[nt][e] = capped;
                mnew[e >> 1] = fmaxf(mnew[e >> 1], capped);
            }
        #pragma unroll
        for (int o = 1; o <= 2; o <<= 1) {
            mnew[0] = fmaxf(mnew[0], __shfl_xor_sync(0xFFFFFFFFu, mnew[0], o));
            mnew[1] = fmaxf(mnew[1], __shfl_xor_sync(0xFFFFFFFFu, mnew[1], o));
        }
        float mt[2], al[2];
        #pragma unroll
        for (int j = 0; j < 2; j++) {
            mt[j] = fmaxf(rm[j], mnew[j]);
            al[j] = __expf(rm[j] - mt[j]);
            rm[j] = mt[j];
        }
        uint32_t ph[8][4];
        float sum[2] = {0.0f, 0.0f};
        #pragma unroll
        for (int g2 = 0; g2 < 8; g2++) {
            unsigned short hh[8];
            #pragma unroll
            for (int half = 0; half < 2; half++) {
                int nt = 2*g2 + half;
                #pragma unroll
                for (int e = 0; e < 4; e++) {
                    float p = __expf(acc_s[nt][e] - mt[e >> 1]);
                    sum[e >> 1] += p;
                    hh[half*4+e] = __half_as_ushort(__float2half_rn(p));
                }
            }
            ph[g2][0] = (uint32_t)hh[0] | ((uint32_t)hh[1] << 16);
            ph[g2][1] = (uint32_t)hh[2] | ((uint32_t)hh[3] << 16);
            ph[g2][2] = (uint32_t)hh[4] | ((uint32_t)hh[5] << 16);
            ph[g2][3] = (uint32_t)hh[6] | ((uint32_t)hh[7] << 16);
        }
        #pragma unroll
        for (int o = 1; o <= 2; o <<= 1) {
            sum[0] += __shfl_xor_sync(0xFFFFFFFFu, sum[0], o);
            sum[1] += __shfl_xor_sync(0xFFFFFFFFu, sum[1], o);
        }
        rl[0] = rl[0]*al[0] + sum[0];
        rl[1] = rl[1]*al[1] + sum[1];
        #pragma unroll
        for (int nt = 0; nt < 32; nt++)
            #pragma unroll
            for (int e = 0; e < 4; e++) acc_o[nt][e] *= al[e >> 1];

        // ---- PV phase: fp16, 2 products ----
        for (int sl = 0; sl < 4; sl++) {
            cp_wait<0>();
            __syncthreads();
            if (sl < 3)       fl_load_v(Vh, Vl, s0, sl+1, sb + FL_V_BASE + (uint32_t)((sl+1)&1)*FL_V_STAGE);
            else if (kt < 15) fl_load_qk(Q, Kh, Kl, s0 + 128, 0, sb);
            cp_commit();
            const uint32_t vb = sb + FL_V_BASE + (uint32_t)(sl & 1) * FL_V_STAGE;
            #pragma unroll
            for (int kk = 0; kk < 2; kk++) {
                const int g2 = sl*2 + kk;
                int g = lane >> 3;
                uint32_t c_off = (uint32_t)kk*32 + ((g & 1) << 4);
                #pragma unroll
                for (int nt2 = 0; nt2 < 16; nt2++) {
                    int row = nt2*16 + ((g >> 1) << 3) + (lane & 7);
                    uint32_t vh[4], vl[4];
                    LDSM_X4(vh, vb + (uint32_t)row*80 + c_off);
                    LDSM_X4(vl, vb + 20480 + (uint32_t)row*80 + c_off);
                    mma16816h(acc_o[2*nt2],   ph[g2], vh[0], vh[1]);
                    mma16816h(acc_o[2*nt2],   ph[g2], vl[0], vl[1]);
                    mma16816h(acc_o[2*nt2+1], ph[g2], vh[2], vh[3]);
                    mma16816h(acc_o[2*nt2+1], ph[g2], vl[2], vl[3]);
                }
            }
        }
    }

    // ---- epilogue: normalize + single fp16 store ----
    float inv[2] = {1.0f / rl[0], 1.0f / rl[1]};
    #pragma unroll
    for (int nt = 0; nt < 32; nt++)
        #pragma unroll
        for (int j = 0; j < 2; j++) {
            int rloc = wid*16 + (lane >> 2) + j*8;
            size_t m = (size_t)b*SEQ + q0 + rloc;
            int d = nt*8 + (lane & 3)*2;
            size_t o = m*QDIM + h*HD + d;
            float v0 = acc_o[nt][2*j+0] * inv[j];
            float v1 = acc_o[nt][2*j+1] * inv[j];
            uint32_t pack = (uint32_t)__half_as_ushort(__float2half_rn(v0)) |
                            ((uint32_t)__half_as_ushort(__float2half_rn(v1)) << 16);
            *(uint32_t*)(g_ah + o) = pack;
        }
}

// ======================= launch ============================================
extern "C" void kernel_launch(void* const* d_in, const int* in_sizes, int n_in,
                              void* d_out, int out_size) {
    const float* hs = (const float*)d_in[0];
    const float* Wq = (const float*)d_in[1];
    const float* Wk = (const float*)d_in[2];
    const float* Wv = (const float*)d_in[3];
    const float* Wo = (const float*)d_in[4];
    float* out = (float*)d_out;
    (void)in_sizes; (void)n_in; (void)out_size;

    cudaFuncSetAttribute(g_proj,  cudaFuncAttributeMaxDynamicSharedMemorySize, DYN_SMEM);
    cudaFuncSetAttribute(g_out,   cudaFuncAttributeMaxDynamicSharedMemorySize, DYN_SMEM);
    cudaFuncSetAttribute(g_flash, cudaFuncAttributeMaxDynamicSharedMemorySize, FL_SMEM);

    // launch 1: fused conversion of all fp32 inputs
    k_split_all<<<N4_TOTAL/256, 256>>>((const float4*)hs, (const float4*)Wq,
                                       (const float4*)Wk, (const float4*)Wv,
                                       (const float4*)Wo);
    // launches 2-3: rope tables
    k_invfreq<<<1, 128>>>();
    k_ropetab<<<SEQ, 128>>>();

    // launch 4: fused QKV projection (profiled slot)
    g_proj<<<dim3(WPROWS/256, MTOT/128), 256, DYN_SMEM>>>();

    // rope conversions + vT
    float *qf_p, *kf_p;
    cudaGetSymbolAddress((void**)&qf_p, g_qf);
    cudaGetSymbolAddress((void**)&kf_p, g_kf);
    __half *qh_p, *kh_p, *kl_p;
    cudaGetSymbolAddress((void**)&qh_p, g_qh);
    cudaGetSymbolAddress((void**)&kh_p, g_kh);
    cudaGetSymbolAddress((void**)&kl_p, g_kl);
    k_rope_q<<<BATCH*NH*SEQ, 128>>>(qf_p, qh_p);
    k_rope_k<<<BATCH*NKV*SEQ, 128>>>(kf_p, kh_p, kl_p);
    k_vT<<<dim3(HD/32, SEQ/32, BATCH*NKV), dim3(32, 32)>>>();

    // fused attention
    g_flash<<<dim3(SEQ/128, BATCH*NH), 256, FL_SMEM>>>();

    // output projection
    g_out<<<dim3(HIDDEN/256, MTOT/128), 256, DYN_SMEM>>>(out);
}

// round 14
// speedup vs baseline: 1.6485x; 1.1889x over previous
#include <cuda_runtime.h>
#include <cuda_bf16.h>
#include <cuda_fp16.h>
#include <math.h>
#include <stdint.h>

#define HIDDEN 2048
#define NH 8
#define NKV 2
#define HD 256
#define BATCH 2
#define SEQ 2048
#define MTOT (BATCH*SEQ)            // 4096
#define QDIM (NH*HD)                // 2048
#define KVDIM (NKV*HD)              // 512
#define WPROWS (QDIM + 2*KVDIM)     // 3072

// ======================= PTX helpers =======================================
__device__ __forceinline__ uint32_t smem_to_u32(const void* p) {
    uint32_t a;
    asm("{ .reg .u64 t; cvta.to.shared.u64 t, %1; cvt.u32.u64 %0, t; }" : "=r"(a) : "l"(p));
    return a;
}
__device__ __forceinline__ void cp16(uint32_t dst, const void* src) {
    asm volatile("cp.async.cg.shared.global [%0], [%1], 16;" :: "r"(dst), "l"(src));
}
__device__ __forceinline__ void cp_commit() { asm volatile("cp.async.commit_group;" ::: "memory"); }
template<int N> __device__ __forceinline__ void cp_wait() {
    asm volatile("cp.async.wait_group %0;" :: "n"(N) : "memory");
}
#define LDSM_X4(r, addr) \
    asm volatile("ldmatrix.sync.aligned.m8n8.x4.shared.b16 {%0,%1,%2,%3}, [%4];" \
        : "=r"((r)[0]), "=r"((r)[1]), "=r"((r)[2]), "=r"((r)[3]) : "r"(addr))

__device__ __forceinline__ void mma16816h(float* d, const uint32_t* a, uint32_t b0, uint32_t b1) {
    asm volatile("mma.sync.aligned.m16n8k16.row.col.f32.f16.f16.f32 "
        "{%0,%1,%2,%3}, {%4,%5,%6,%7}, {%8,%9}, {%0,%1,%2,%3};"
        : "+f"(d[0]), "+f"(d[1]), "+f"(d[2]), "+f"(d[3])
        : "r"(a[0]), "r"(a[1]), "r"(a[2]), "r"(a[3]), "r"(b0), "r"(b1));
}

// ======================= scratch (device globals) ==========================
__device__ __align__(16) __half g_hsh[(size_t)MTOT*HIDDEN];                        // hs single fp16
__device__ __align__(16) __half g_wph[(size_t)WPROWS*HIDDEN], g_wpl[(size_t)WPROWS*HIDDEN];
__device__ __align__(16) __half g_woh[(size_t)HIDDEN*QDIM];                        // Wo single fp16
__device__ __align__(16) float g_qf[(size_t)MTOT*QDIM];
__device__ __align__(16) float g_kf[(size_t)BATCH*NKV*SEQ*HD];
__device__ __align__(16) float g_vf[(size_t)BATCH*NKV*SEQ*HD];
__device__ __align__(16) __half g_qh[(size_t)MTOT*QDIM];                           // q single fp16
__device__ __align__(16) __half g_kh[(size_t)BATCH*NKV*SEQ*HD];                    // k single fp16
__device__ __align__(16) __half g_vthi[(size_t)BATCH*NKV*HD*SEQ], g_vtlo[(size_t)BATCH*NKV*HD*SEQ];
__device__ __align__(16) __half g_ah[(size_t)MTOT*QDIM];                           // attn single fp16
__device__ double g_invfreq[HD/2];
__device__ float g_cos[SEQ*(HD/2)];
__device__ float g_sin[SEQ*(HD/2)];

// ======================= small kernels =====================================
__global__ void k_invfreq() {
    int i = threadIdx.x;
    if (i < HD/2) g_invfreq[i] = pow(10000.0, -2.0 * (double)i / (double)HD);
}
__global__ void k_ropetab() {
    int s = blockIdx.x, i = threadIdx.x;
    double ang = (double)s * g_invfreq[i];
    const double twopi = 6.283185307179586476925286766559;
    ang -= floor(ang / twopi) * twopi;
    float c, sn;
    sincosf((float)ang, &sn, &c);
    g_cos[s*(HD/2)+i] = c;
    g_sin[s*(HD/2)+i] = sn;
}

__device__ __forceinline__ void split1h(float x, unsigned short& h, unsigned short& l) {
    __half hh = __float2half_rn(x);
    __half ll = __float2half_rn(x - __half2float(hh));
    h = __half_as_ushort(hh);
    l = __half_as_ushort(ll);
}

// rope + single fp16 (Q and K)
__global__ void k_rope_h(const float* __restrict__ src, __half* __restrict__ dst) {
    int r = blockIdx.x, i = threadIdx.x;
    int s = r & (SEQ-1);
    float c = g_cos[s*(HD/2)+i], sn = g_sin[s*(HD/2)+i];
    const float* row = src + (size_t)r * HD;
    float x1 = row[i], x2 = row[i + HD/2];
    dst[(size_t)r*HD + i]        = __float2half_rn(x1*c - x2*sn);
    dst[(size_t)r*HD + i + HD/2] = __float2half_rn(x2*c + x1*sn);
}

// ---- fused conversion: hs/Wo -> single fp16; Wp -> fp16 hi/lo --------------
#define N4_HS (MTOT*HIDDEN/4)
#define N4_WQ (QDIM*HIDDEN/4)
#define N4_WK (KVDIM*HIDDEN/4)
#define N4_WV (KVDIM*HIDDEN/4)
#define N4_WO (HIDDEN*QDIM/4)
#define N4_TOTAL (N4_HS+N4_WQ+N4_WK+N4_WV+N4_WO)

__global__ void k_split_all(const float4* __restrict__ hs, const float4* __restrict__ wq,
                            const float4* __restrict__ wk, const float4* __restrict__ wv,
                            const float4* __restrict__ wo) {
    int i = blockIdx.x * 256 + threadIdx.x;
    if (i < N4_HS) {
        float4 v = hs[i];
        uint2 H;
        H.x = (uint32_t)__half_as_ushort(__float2half_rn(v.x)) |
              ((uint32_t)__half_as_ushort(__float2half_rn(v.y)) << 16);
        H.y = (uint32_t)__half_as_ushort(__float2half_rn(v.z)) |
              ((uint32_t)__half_as_ushort(__float2half_rn(v.w)) << 16);
        ((uint2*)g_hsh)[i] = H;
        return;
    }
    if (i >= N4_HS + N4_WQ + N4_WK + N4_WV) {   // Wo: single fp16
        int j = i - (N4_HS + N4_WQ + N4_WK + N4_WV);
        float4 v = wo[j];
        uint2 H;
        H.x = (uint32_t)__half_as_ushort(__float2half_rn(v.x)) |
              ((uint32_t)__half_as_ushort(__float2half_rn(v.y)) << 16);
        H.y = (uint32_t)__half_as_ushort(__float2half_rn(v.z)) |
              ((uint32_t)__half_as_ushort(__float2half_rn(v.w)) << 16);
        ((uint2*)g_woh)[j] = H;
        return;
    }
    const float4* src;
    uint2 *dh, *dl;
    int j;
    if (i < N4_HS + N4_WQ) {
        j = i - N4_HS; src = wq;
        dh = (uint2*)g_wph; dl = (uint2*)g_wpl;
    } else if (i < N4_HS + N4_WQ + N4_WK) {
        j = i - (N4_HS + N4_WQ); src = wk;
        dh = (uint2*)g_wph + (size_t)QDIM*HIDDEN/4;
        dl = (uint2*)g_wpl + (size_t)QDIM*HIDDEN/4;
    } else {
        j = i - (N4_HS + N4_WQ + N4_WK); src = wv;
        dh = (uint2*)g_wph + (size_t)(QDIM+KVDIM)*HIDDEN/4;
        dl = (uint2*)g_wpl + (size_t)(QDIM+KVDIM)*HIDDEN/4;
    }
    float4 v = src[j];
    unsigned short h0,h1,h2,h3,l0,l1,l2,l3;
    split1h(v.x,h0,l0); split1h(v.y,h1,l1); split1h(v.z,h2,l2); split1h(v.w,h3,l3);
    uint2 H, L;
    H.x = (uint32_t)h0 | ((uint32_t)h1 << 16); H.y = (uint32_t)h2 | ((uint32_t)h3 << 16);
    L.x = (uint32_t)l0 | ((uint32_t)l1 << 16); L.y = (uint32_t)l2 | ((uint32_t)l3 << 16);
    dh[j] = H; dl[j] = L;
}

// transpose v [z][s][d] -> vT [z][d][s] with fp16 split
__global__ void k_vT() {
    __shared__ float t[32][33];
    int z = blockIdx.z;
    int d0 = blockIdx.x * 32, s0 = blockIdx.y * 32;
    int tx = threadIdx.x, ty = threadIdx.y;
    t[ty][tx] = g_vf[((size_t)z*SEQ + s0 + ty)*HD + d0 + tx];
    __syncthreads();
    float x = t[tx][ty];
    size_t o = ((size_t)z*HD + d0 + ty)*SEQ + s0 + tx;
    unsigned short h, l;
    split1h(x, h, l);
    g_vthi[o] = __ushort_as_half(h);
    g_vtlo[o] = __ushort_as_half(l);
}

// ======================= fp16 GEMMs ========================================
#define RS 72                         // row stride elems (144B), 9 granules
#define MAT_A (128*RS*2)              // 18432
#define MAT_B (256*RS*2)              // 36864

// --- 2-product (proj): A single + B hi/lo ---
#define P_OFF_A  0
#define P_OFF_BH MAT_A
#define P_OFF_BL (MAT_A + MAT_B)
#define P_STAGE (MAT_A + 2*MAT_B)     // 92160
#define P_DYN (2*P_STAGE)             // 184320

__device__ __forceinline__ void load_chunk2(
    const __half* __restrict__ A, int lda,
    const __half* __restrict__ Bh, const __half* __restrict__ Bl, int ldb,
    int k0, uint32_t stage)
{
    int t = threadIdx.x;
    #pragma unroll
    for (int i = 0; i < 4; i++) {
        int v = t + (i << 8);
        int row = v >> 3, g = v & 7;
        uint32_t doff = (uint32_t)row * (RS*2) + (uint32_t)(g << 4);
        cp16(stage + P_OFF_A + doff, A + (size_t)row * lda + k0 + g*8);
    }
    #pragma unroll
    for (int i = 0; i < 8; i++) {
        int v = t + (i << 8);
        int row = v >> 3, g = v & 7;
        uint32_t doff = (uint32_t)row * (RS*2) + (uint32_t)(g << 4);
        const size_t rb = (size_t)row * ldb + k0 + g*8;
        cp16(stage + P_OFF_BH + doff, Bh + rb);
        cp16(stage + P_OFF_BL + doff, Bl + rb);
    }
}

template<class Epi>
__device__ __forceinline__ void gemm_body2(
    const __half* __restrict__ A, int lda,
    const __half* __restrict__ Bhi, const __half* __restrict__ Blo, int ldb,
    int K, Epi epi)
{
    extern __shared__ char dsm[];
    const uint32_t sbase = smem_to_u32(dsm);
    const int tid = threadIdx.x;
    const int wid = tid >> 5, lane = tid & 31;
    const int wm = wid & 1, wn = wid >> 1;
    const int m0 = blockIdx.y * 128, n0 = blockIdx.x * 256;

    const __half* A0 = A + (size_t)m0 * lda;
    const __half* B0 = Bhi + (size_t)n0 * ldb;
    const __half* B1 = Blo + (size_t)n0 * ldb;

    float acc[4][8][4];
    #pragma unroll
    for (int a = 0; a < 4; a++)
        #pragma unroll
        for (int b = 0; b < 8; b++)
            #pragma unroll
            for (int c = 0; c < 4; c++) acc[a][b][c] = 0.0f;

    const int nc = K >> 6;
    load_chunk2(A0, lda, B0, B1, ldb, 0, sbase);
    cp_commit();

    for (int c = 0; c < nc; c++) {
        cp_wait<0>();
        __syncthreads();
        if (c + 1 < nc) {
            load_chunk2(A0, lda, B0, B1, ldb, (c+1) << 6,
                        sbase + (uint32_t)((c+1) & 1) * P_STAGE);
            cp_commit();
        }
        const uint32_t sb = sbase + (uint32_t)(c & 1) * P_STAGE;
        #pragma unroll
        for (int kk = 0; kk < 4; kk++) {
            uint32_t ah[4][4];
            #pragma unroll
            for (int mt = 0; mt < 4; mt++) {
                int row = wm*64 + mt*16 + (lane & 15);
                uint32_t off = (uint32_t)row*(RS*2) + (uint32_t)kk*32 + ((lane >> 4) << 4);
                LDSM_X4(ah[mt], sb + P_OFF_A + off);
            }
            #pragma unroll
            for (int nt = 0; nt < 4; nt++) {
                uint32_t bh[4], bl[4];
                int g = lane >> 3;
                int row = wn*64 + nt*16 + ((g >> 1) << 3) + (lane & 7);
                uint32_t off = (uint32_t)row*(RS*2) + (uint32_t)kk*32 + ((g & 1) << 4);
                LDSM_X4(bh, sb + P_OFF_BH + off);
                LDSM_X4(bl, sb + P_OFF_BL + off);
                #pragma unroll
                for (int mt = 0; mt < 4; mt++) {
                    mma16816h(acc[mt][nt*2+0], ah[mt], bh[0], bh[1]);
                    mma16816h(acc[mt][nt*2+0], ah[mt], bl[0], bl[1]);
                    mma16816h(acc[mt][nt*2+1], ah[mt], bh[2], bh[3]);
                    mma16816h(acc[mt][nt*2+1], ah[mt], bl[2], bl[3]);
                }
            }
        }
    }

    #pragma unroll
    for (int mt = 0; mt < 4; mt++)
        #pragma unroll
        for (int nj = 0; nj < 8; nj++)
            #pragma unroll
            for (int e = 0; e < 4; e++) {
                int m = m0 + wm*64 + mt*16 + (lane >> 2) + ((e >> 1) << 3);
                int n = n0 + wn*64 + nj*8 + ((lane & 3) << 1) + (e & 1);
                epi(m, n, acc[mt][nj][e]);
            }
}

// --- 1-product (out): A single + B single ---
#define O_OFF_A  0
#define O_OFF_B  MAT_A
#define O_STAGE (MAT_A + MAT_B)       // 55296
#define O_DYN (2*O_STAGE)             // 110592

__device__ __forceinline__ void load_chunk1(
    const __half* __restrict__ A, int lda,
    const __half* __restrict__ B, int ldb,
    int k0, uint32_t stage)
{
    int t = threadIdx.x;
    #pragma unroll
    for (int i = 0; i < 4; i++) {
        int v = t + (i << 8);
        int row = v >> 3, g = v & 7;
        uint32_t doff = (uint32_t)row * (RS*2) + (uint32_t)(g << 4);
        cp16(stage + O_OFF_A + doff, A + (size_t)row * lda + k0 + g*8);
    }
    #pragma unroll
    for (int i = 0; i < 8; i++) {
        int v = t + (i << 8);
        int row = v >> 3, g = v & 7;
        uint32_t doff = (uint32_t)row * (RS*2) + (uint32_t)(g << 4);
        cp16(stage + O_OFF_B + doff, B + (size_t)row * ldb + k0 + g*8);
    }
}

template<class Epi>
__device__ __forceinline__ void gemm_body1(
    const __half* __restrict__ A, int lda,
    const __half* __restrict__ B, int ldb,
    int K, Epi epi)
{
    extern __shared__ char dsm[];
    const uint32_t sbase = smem_to_u32(dsm);
    const int tid = threadIdx.x;
    const int wid = tid >> 5, lane = tid & 31;
    const int wm = wid & 1, wn = wid >> 1;
    const int m0 = blockIdx.y * 128, n0 = blockIdx.x * 256;

    const __half* A0 = A + (size_t)m0 * lda;
    const __half* B0 = B + (size_t)n0 * ldb;

    float acc[4][8][4];
    #pragma unroll
    for (int a = 0; a < 4; a++)
        #pragma unroll
        for (int b = 0; b < 8; b++)
            #pragma unroll
            for (int c = 0; c < 4; c++) acc[a][b][c] = 0.0f;

    const int nc = K >> 6;
    load_chunk1(A0, lda, B0, ldb, 0, sbase);
    cp_commit();

    for (int c = 0; c < nc; c++) {
        cp_wait<0>();
        __syncthreads();
        if (c + 1 < nc) {
            load_chunk1(A0, lda, B0, ldb, (c+1) << 6,
                        sbase + (uint32_t)((c+1) & 1) * O_STAGE);
            cp_commit();
        }
        const uint32_t sb = sbase + (uint32_t)(c & 1) * O_STAGE;
        #pragma unroll
        for (int kk = 0; kk < 4; kk++) {
            uint32_t ah[4][4];
            #pragma unroll
            for (int mt = 0; mt < 4; mt++) {
                int row = wm*64 + mt*16 + (lane & 15);
                uint32_t off = (uint32_t)row*(RS*2) + (uint32_t)kk*32 + ((lane >> 4) << 4);
                LDSM_X4(ah[mt], sb + O_OFF_A + off);
            }
            #pragma unroll
            for (int nt = 0; nt < 4; nt++) {
                uint32_t bh[4];
                int g = lane >> 3;
                int row = wn*64 + nt*16 + ((g >> 1) << 3) + (lane & 7);
                uint32_t off = (uint32_t)row*(RS*2) + (uint32_t)kk*32 + ((g & 1) << 4);
                LDSM_X4(bh, sb + O_OFF_B + off);
                #pragma unroll
                for (int mt = 0; mt < 4; mt++) {
                    mma16816h(acc[mt][nt*2+0], ah[mt], bh[0], bh[1]);
                    mma16816h(acc[mt][nt*2+1], ah[mt], bh[2], bh[3]);
                }
            }
        }
    }

    #pragma unroll
    for (int mt = 0; mt < 4; mt++)
        #pragma unroll
        for (int nj = 0; nj < 8; nj++)
            #pragma unroll
            for (int e = 0; e < 4; e++) {
                int m = m0 + wm*64 + mt*16 + (lane >> 2) + ((e >> 1) << 3);
                int n = n0 + wn*64 + nj*8 + ((lane & 3) << 1) + (e & 1);
                epi(m, n, acc[mt][nj][e]);
            }
}

struct EpiProjFused {
    __device__ __forceinline__ void operator()(int m, int n, float v) const {
        int b = m >> 11, s = m & (SEQ-1);
        if (n < QDIM) {
            int h = n >> 8, d = n & (HD-1);
            g_qf[(((size_t)b*NH + h)*SEQ + s)*HD + d] = v;
        } else if (n < QDIM + KVDIM) {
            int nn = n - QDIM;
            int h = nn >> 8, d = nn & (HD-1);
            g_kf[(((size_t)b*NKV + h)*SEQ + s)*HD + d] = v;
        } else {
            int nn = n - QDIM - KVDIM;
            int h = nn >> 8, d = nn & (HD-1);
            g_vf[(((size_t)b*NKV + h)*SEQ + s)*HD + d] = v;
        }
    }
};
struct EpiPlain {
    float* C; int ldc;
    __device__ __forceinline__ void operator()(int m, int n, float v) const {
        C[(size_t)m*ldc + n] = v;
    }
};

__global__ void __launch_bounds__(256, 1) g_proj() {
    gemm_body2(g_hsh, HIDDEN, g_wph, g_wpl, HIDDEN, HIDDEN, EpiProjFused{});
}
__global__ void __launch_bounds__(256, 1) g_out(float* __restrict__ out) {
    gemm_body1(g_ah, QDIM, g_woh, QDIM, QDIM, EpiPlain{out, HIDDEN});
}

// ======================= flash attention ===================================
// S phase: Q single (1 mat) + K single (1 mat) -> 2 mats/stage.
#define FL_QK_STAGE 20480
#define FL_V_BASE   40960
#define FL_V_STAGE  40960
#define FL_SMEM     122880

__device__ __forceinline__ void fl_load_qk(
    const __half* __restrict__ Q, const __half* __restrict__ Kh,
    int s0, int c, uint32_t stage)
{
    int tid = threadIdx.x;
    #pragma unroll
    for (int i = 0; i < 4; i++) {
        const int mat = i >> 1;                     // 0 Q, 1 Kh
        int w = ((i & 1) << 8) + tid;
        int row = w >> 2, g = w & 3;
        uint32_t dst = stage + (uint32_t)mat*10240 + (uint32_t)row*80 + (uint32_t)(g << 4);
        size_t col = (size_t)(c*32 + g*8);
        if (mat == 0) cp16(dst, Q + (size_t)row*HD + col);
        else          cp16(dst, Kh + (size_t)(s0 + row)*HD + col);
    }
}
__device__ __forceinline__ void fl_load_v(
    const __half* __restrict__ Vh, const __half* __restrict__ Vl,
    int s0, int sl, uint32_t stage)
{
    int tid = threadIdx.x;
    #pragma unroll
    for (int i = 0; i < 8; i++) {
        const int mat = i >> 2;                     // 0 Vh, 1 Vl
        int w = ((i & 3) << 8) + tid;
        int row = w >> 2, g = w & 3;                // row 0..255 (d)
        uint32_t dst = stage + (uint32_t)mat*20480 + (uint32_t)row*80 + (uint32_t)(g << 4);
        size_t col = (size_t)(s0 + sl*32 + g*8);
        if (mat == 0) cp16(dst, Vh + (size_t)row*SEQ + col);
        else          cp16(dst, Vl + (size_t)row*SEQ + col);
    }
}

__global__ void __launch_bounds__(256, 1) g_flash() {
    extern __shared__ char dsm[];
    const uint32_t sb = smem_to_u32(dsm);
    const int tid = threadIdx.x, wid = tid >> 5, lane = tid & 31;
    const int qt = blockIdx.x, z = blockIdx.y;
    const int b = z >> 3, h = z & 7, kv = h >> 2;
    const int q0 = qt * 128;

    const __half* Q  = g_qh + (size_t)z*SEQ*HD + (size_t)q0*HD;
    const __half* Kh = g_kh + (size_t)(b*NKV+kv)*SEQ*HD;
    const __half* Vh = g_vthi + (size_t)(b*NKV+kv)*HD*SEQ;
    const __half* Vl = g_vtlo + (size_t)(b*NKV+kv)*HD*SEQ;

    float acc_o[32][4];
    #pragma unroll
    for (int i = 0; i < 32; i++)
        #pragma unroll
        for (int e = 0; e < 4; e++) acc_o[i][e] = 0.0f;
    float rm[2] = {-1e30f, -1e30f};
    float rl[2] = {0.0f, 0.0f};

    fl_load_qk(Q, Kh, 0, 0, sb);
    cp_commit();

    for (int kt = 0; kt < 16; kt++) {
        const int s0 = kt * 128;
        float acc_s[16][4];
        #pragma unroll
        for (int i = 0; i < 16; i++)
            #pragma unroll
            for (int e = 0; e < 4; e++) acc_s[i][e] = 0.0f;

        // ---- S phase: 8 d-chunks (pure fp16 1-product) ----
        for (int c = 0; c < 8; c++) {
            cp_wait<0>();
            __syncthreads();
            if (c < 7) fl_load_qk(Q, Kh, s0, c+1, sb + (uint32_t)((c+1)&1)*FL_QK_STAGE);
            else       fl_load_v(Vh, Vl, s0, 0, sb + FL_V_BASE);
            cp_commit();
            const uint32_t qkb = sb + (uint32_t)(c & 1) * FL_QK_STAGE;
            #pragma unroll
            for (int kk = 0; kk < 2; kk++) {
                uint32_t qf[4];
                uint32_t a_off = (uint32_t)(wid*16 + (lane & 15))*80 + (uint32_t)kk*32 + ((lane >> 4) << 4);
                LDSM_X4(qf, qkb + a_off);
                int g = lane >> 3;
                uint32_t c_off = (uint32_t)kk*32 + ((g & 1) << 4);
                #pragma unroll
                for (int nt2 = 0; nt2 < 8; nt2++) {
                    int row = nt2*16 + ((g >> 1) << 3) + (lane & 7);
                    uint32_t kh[4];
                    LDSM_X4(kh, qkb + 10240 + (uint32_t)row*80 + c_off);
                    mma16816h(acc_s[2*nt2],   qf, kh[0], kh[1]);
                    mma16816h(acc_s[2*nt2+1], qf, kh[2], kh[3]);
                }
            }
        }

        // ---- softmax (register-resident); P as single fp16 ----
        float mnew[2] = {-1e30f, -1e30f};
        #pragma unroll
        for (int nt = 0; nt < 16; nt++)
            #pragma unroll
            for (int e = 0; e < 4; e++) {
                float s = acc_s[nt][e];
                float y = s * 0.00125f;
                float y2 = y * y;
                float capped = s * 0.0625f * (1.0f - y2*(0.33333333f - y2*0.13333333f));
                acc_s[nt][e] = capped;
                mnew[e >> 1] = fmaxf(mnew[e >> 1], capped);
            }
        #pragma unroll
        for (int o = 1; o <= 2; o <<= 1) {
            mnew[0] = fmaxf(mnew[0], __shfl_xor_sync(0xFFFFFFFFu, mnew[0], o));
            mnew[1] = fmaxf(mnew[1], __shfl_xor_sync(0xFFFFFFFFu, mnew[1], o));
        }
        float mt[2], al[2];
        #pragma unroll
        for (int j = 0; j < 2; j++) {
            mt[j] = fmaxf(rm[j], mnew[j]);
            al[j] = __expf(rm[j] - mt[j]);
            rm[j] = mt[j];
        }
        uint32_t ph[8][4];
        float sum[2] = {0.0f, 0.0f};
        #pragma unroll
        for (int g2 = 0; g2 < 8; g2++) {
            unsigned short hh[8];
            #pragma unroll
            for (int half = 0; half < 2; half++) {
                int nt = 2*g2 + half;
                #pragma unroll
                for (int e = 0; e < 4; e++) {
                    float p = __expf(acc_s[nt][e] - mt[e >> 1]);
                    sum[e >> 1] += p;
                    hh[half*4+e] = __half_as_ushort(__float2half_rn(p));
                }
            }
            ph[g2][0] = (uint32_t)hh[0] | ((uint32_t)hh[1] << 16);
            ph[g2][1] = (uint32_t)hh[2] | ((uint32_t)hh[3] << 16);
            ph[g2][2] = (uint32_t)hh[4] | ((uint32_t)hh[5] << 16);
            ph[g2][3] = (uint32_t)hh[6] | ((uint32_t)hh[7] << 16);
        }
        #pragma unroll
        for (int o = 1; o <= 2; o <<= 1) {
            sum[0] += __shfl_xor_sync(0xFFFFFFFFu, sum[0], o);
            sum[1] += __shfl_xor_sync(0xFFFFFFFFu, sum[1], o);
        }
        rl[0] = rl[0]*al[0] + sum[0];
        rl[1] = rl[1]*al[1] + sum[1];
        #pragma unroll
        for (int nt = 0; nt < 32; nt++)
            #pragma unroll
            for (int e = 0; e < 4; e++) acc_o[nt][e] *= al[e >> 1];

        // ---- PV phase: fp16, 2 products ----
        for (int sl = 0; sl < 4; sl++) {
            cp_wait<0>();
            __syncthreads();
            if (sl < 3)       fl_load_v(Vh, Vl, s0, sl+1, sb + FL_V_BASE + (uint32_t)((sl+1)&1)*FL_V_STAGE);
            else if (kt < 15) fl_load_qk(Q, Kh, s0 + 128, 0, sb);
            cp_commit();
            const uint32_t vb = sb + FL_V_BASE + (uint32_t)(sl & 1) * FL_V_STAGE;
            #pragma unroll
            for (int kk = 0; kk < 2; kk++) {
                const int g2 = sl*2 + kk;
                int g = lane >> 3;
                uint32_t c_off = (uint32_t)kk*32 + ((g & 1) << 4);
                #pragma unroll
                for (int nt2 = 0; nt2 < 16; nt2++) {
                    int row = nt2*16 + ((g >> 1) << 3) + (lane & 7);
                    uint32_t vh[4], vl[4];
                    LDSM_X4(vh, vb + (uint32_t)row*80 + c_off);
                    LDSM_X4(vl, vb + 20480 + (uint32_t)row*80 + c_off);
                    mma16816h(acc_o[2*nt2],   ph[g2], vh[0], vh[1]);
                    mma16816h(acc_o[2*nt2],   ph[g2], vl[0], vl[1]);
                    mma16816h(acc_o[2*nt2+1], ph[g2], vh[2], vh[3]);
                    mma16816h(acc_o[2*nt2+1], ph[g2], vl[2], vl[3]);
                }
            }
        }
    }

    // ---- epilogue: normalize + single fp16 store ----
    float inv[2] = {1.0f / rl[0], 1.0f / rl[1]};
    #pragma unroll
    for (int nt = 0; nt < 32; nt++)
        #pragma unroll
        for (int j = 0; j < 2; j++) {
            int rloc = wid*16 + (lane >> 2) + j*8;
            size_t m = (size_t)b*SEQ + q0 + rloc;
            int d = nt*8 + (lane & 3)*2;
            size_t o = m*QDIM + h*HD + d;
            float v0 = acc_o[nt][2*j+0] * inv[j];
            float v1 = acc_o[nt][2*j+1] * inv[j];
            uint32_t pack = (uint32_t)__half_as_ushort(__float2half_rn(v0)) |
                            ((uint32_t)__half_as_ushort(__float2half_rn(v1)) << 16);
            *(uint32_t*)(g_ah + o) = pack;
        }
}

// ======================= launch ============================================
extern "C" void kernel_launch(void* const* d_in, const int* in_sizes, int n_in,
                              void* d_out, int out_size) {
    const float* hs = (const float*)d_in[0];
    const float* Wq = (const float*)d_in[1];
    const float* Wk = (const float*)d_in[2];
    const float* Wv = (const float*)d_in[3];
    const float* Wo = (const float*)d_in[4];
    float* out = (float*)d_out;
    (void)in_sizes; (void)n_in; (void)out_size;

    cudaFuncSetAttribute(g_proj,  cudaFuncAttributeMaxDynamicSharedMemorySize, P_DYN);
    cudaFuncSetAttribute(g_out,   cudaFuncAttributeMaxDynamicSharedMemorySize, O_DYN);
    cudaFuncSetAttribute(g_flash, cudaFuncAttributeMaxDynamicSharedMemorySize, FL_SMEM);

    // launch 1: fused conversion of all fp32 inputs
    k_split_all<<<N4_TOTAL/256, 256>>>((const float4*)hs, (const float4*)Wq,
                                       (const float4*)Wk, (const float4*)Wv,
                                       (const float4*)Wo);
    // launches 2-3: rope tables
    k_invfreq<<<1, 128>>>();
    k_ropetab<<<SEQ, 128>>>();

    // launch 4: fused QKV projection (profiled slot)
    g_proj<<<dim3(WPROWS/256, MTOT/128), 256, P_DYN>>>();

    // rope conversions + vT
    float *qf_p, *kf_p;
    cudaGetSymbolAddress((void**)&qf_p, g_qf);
    cudaGetSymbolAddress((void**)&kf_p, g_kf);
    __half *qh_p, *kh_p;
    cudaGetSymbolAddress((void**)&qh_p, g_qh);
    cudaGetSymbolAddress((void**)&kh_p, g_kh);
    k_rope_h<<<BATCH*NH*SEQ, 128>>>(qf_p, qh_p);
    k_rope_h<<<BATCH*NKV*SEQ, 128>>>(kf_p, kh_p);
    k_vT<<<dim3(HD/32, SEQ/32, BATCH*NKV), dim3(32, 32)>>>();

    // fused attention
    g_flash<<<dim3(SEQ/128, BATCH*NH), 256, FL_SMEM>>>();

    // output projection
    g_out<<<dim3(HIDDEN/256, MTOT/128), 256, O_DYN>>>(out);
}

// round 15
// speedup vs baseline: 1.8757x; 1.1378x over previous
#include <cuda_runtime.h>
#include <cuda_bf16.h>
#include <cuda_fp16.h>
#include <math.h>
#include <stdint.h>

#define HIDDEN 2048
#define NH 8
#define NKV 2
#define HD 256
#define BATCH 2
#define SEQ 2048
#define MTOT (BATCH*SEQ)            // 4096
#define QDIM (NH*HD)                // 2048
#define KVDIM (NKV*HD)              // 512
#define WPROWS (QDIM + 2*KVDIM)     // 3072

// ======================= PTX helpers =======================================
__device__ __forceinline__ uint32_t smem_to_u32(const void* p) {
    uint32_t a;
    asm("{ .reg .u64 t; cvta.to.shared.u64 t, %1; cvt.u32.u64 %0, t; }" : "=r"(a) : "l"(p));
    return a;
}
__device__ __forceinline__ void cp16(uint32_t dst, const void* src) {
    asm volatile("cp.async.cg.shared.global [%0], [%1], 16;" :: "r"(dst), "l"(src));
}
__device__ __forceinline__ void cp_commit() { asm volatile("cp.async.commit_group;" ::: "memory"); }
template<int N> __device__ __forceinline__ void cp_wait() {
    asm volatile("cp.async.wait_group %0;" :: "n"(N) : "memory");
}
#define LDSM_X4(r, addr) \
    asm volatile("ldmatrix.sync.aligned.m8n8.x4.shared.b16 {%0,%1,%2,%3}, [%4];" \
        : "=r"((r)[0]), "=r"((r)[1]), "=r"((r)[2]), "=r"((r)[3]) : "r"(addr))

__device__ __forceinline__ void mma16816h(float* d, const uint32_t* a, uint32_t b0, uint32_t b1) {
    asm volatile("mma.sync.aligned.m16n8k16.row.col.f32.f16.f16.f32 "
        "{%0,%1,%2,%3}, {%4,%5,%6,%7}, {%8,%9}, {%0,%1,%2,%3};"
        : "+f"(d[0]), "+f"(d[1]), "+f"(d[2]), "+f"(d[3])
        : "r"(a[0]), "r"(a[1]), "r"(a[2]), "r"(a[3]), "r"(b0), "r"(b1));
}

// ======================= scratch (device globals) ==========================
__device__ __align__(16) __half g_hsh[(size_t)MTOT*HIDDEN];                        // hs single fp16
__device__ __align__(16) __half g_wph[(size_t)WPROWS*HIDDEN], g_wpl[(size_t)WPROWS*HIDDEN];
__device__ __align__(16) __half g_woh[(size_t)HIDDEN*QDIM];                        // Wo single fp16
__device__ __align__(16) float g_qf[(size_t)MTOT*QDIM];
__device__ __align__(16) float g_kf[(size_t)BATCH*NKV*SEQ*HD];
__device__ __align__(16) float g_vf[(size_t)BATCH*NKV*SEQ*HD];
__device__ __align__(16) __half g_qh[(size_t)MTOT*QDIM];                           // q single fp16
__device__ __align__(16) __half g_kh[(size_t)BATCH*NKV*SEQ*HD];                    // k single fp16
__device__ __align__(16) __half g_vt[(size_t)BATCH*NKV*HD*SEQ];                    // vT single fp16
__device__ __align__(16) __half g_ah[(size_t)MTOT*QDIM];                           // attn single fp16
__device__ double g_invfreq[HD/2];
__device__ float g_cos[SEQ*(HD/2)];
__device__ float g_sin[SEQ*(HD/2)];

// ======================= small kernels =====================================
__global__ void k_invfreq() {
    int i = threadIdx.x;
    if (i < HD/2) g_invfreq[i] = pow(10000.0, -2.0 * (double)i / (double)HD);
}
__global__ void k_ropetab() {
    int s = blockIdx.x, i = threadIdx.x;
    double ang = (double)s * g_invfreq[i];
    const double twopi = 6.283185307179586476925286766559;
    ang -= floor(ang / twopi) * twopi;
    float c, sn;
    sincosf((float)ang, &sn, &c);
    g_cos[s*(HD/2)+i] = c;
    g_sin[s*(HD/2)+i] = sn;
}

__device__ __forceinline__ void split1h(float x, unsigned short& h, unsigned short& l) {
    __half hh = __float2half_rn(x);
    __half ll = __float2half_rn(x - __half2float(hh));
    h = __half_as_ushort(hh);
    l = __half_as_ushort(ll);
}

// rope + single fp16 (Q and K)
__global__ void k_rope_h(const float* __restrict__ src, __half* __restrict__ dst) {
    int r = blockIdx.x, i = threadIdx.x;
    int s = r & (SEQ-1);
    float c = g_cos[s*(HD/2)+i], sn = g_sin[s*(HD/2)+i];
    const float* row = src + (size_t)r * HD;
    float x1 = row[i], x2 = row[i + HD/2];
    dst[(size_t)r*HD + i]        = __float2half_rn(x1*c - x2*sn);
    dst[(size_t)r*HD + i + HD/2] = __float2half_rn(x2*c + x1*sn);
}

// ---- fused conversion: hs/Wo -> single fp16; Wp -> fp16 hi/lo --------------
#define N4_HS (MTOT*HIDDEN/4)
#define N4_WQ (QDIM*HIDDEN/4)
#define N4_WK (KVDIM*HIDDEN/4)
#define N4_WV (KVDIM*HIDDEN/4)
#define N4_WO (HIDDEN*QDIM/4)
#define N4_TOTAL (N4_HS+N4_WQ+N4_WK+N4_WV+N4_WO)

__global__ void k_split_all(const float4* __restrict__ hs, const float4* __restrict__ wq,
                            const float4* __restrict__ wk, const float4* __restrict__ wv,
                            const float4* __restrict__ wo) {
    int i = blockIdx.x * 256 + threadIdx.x;
    if (i < N4_HS) {
        float4 v = hs[i];
        uint2 H;
        H.x = (uint32_t)__half_as_ushort(__float2half_rn(v.x)) |
              ((uint32_t)__half_as_ushort(__float2half_rn(v.y)) << 16);
        H.y = (uint32_t)__half_as_ushort(__float2half_rn(v.z)) |
              ((uint32_t)__half_as_ushort(__float2half_rn(v.w)) << 16);
        ((uint2*)g_hsh)[i] = H;
        return;
    }
    if (i >= N4_HS + N4_WQ + N4_WK + N4_WV) {   // Wo: single fp16
        int j = i - (N4_HS + N4_WQ + N4_WK + N4_WV);
        float4 v = wo[j];
        uint2 H;
        H.x = (uint32_t)__half_as_ushort(__float2half_rn(v.x)) |
              ((uint32_t)__half_as_ushort(__float2half_rn(v.y)) << 16);
        H.y = (uint32_t)__half_as_ushort(__float2half_rn(v.z)) |
              ((uint32_t)__half_as_ushort(__float2half_rn(v.w)) << 16);
        ((uint2*)g_woh)[j] = H;
        return;
    }
    const float4* src;
    uint2 *dh, *dl;
    int j;
    if (i < N4_HS + N4_WQ) {
        j = i - N4_HS; src = wq;
        dh = (uint2*)g_wph; dl = (uint2*)g_wpl;
    } else if (i < N4_HS + N4_WQ + N4_WK) {
        j = i - (N4_HS + N4_WQ); src = wk;
        dh = (uint2*)g_wph + (size_t)QDIM*HIDDEN/4;
        dl = (uint2*)g_wpl + (size_t)QDIM*HIDDEN/4;
    } else {
        j = i - (N4_HS + N4_WQ + N4_WK); src = wv;
        dh = (uint2*)g_wph + (size_t)(QDIM+KVDIM)*HIDDEN/4;
        dl = (uint2*)g_wpl + (size_t)(QDIM+KVDIM)*HIDDEN/4;
    }
    float4 v = src[j];
    unsigned short h0,h1,h2,h3,l0,l1,l2,l3;
    split1h(v.x,h0,l0); split1h(v.y,h1,l1); split1h(v.z,h2,l2); split1h(v.w,h3,l3);
    uint2 H, L;
    H.x = (uint32_t)h0 | ((uint32_t)h1 << 16); H.y = (uint32_t)h2 | ((uint32_t)h3 << 16);
    L.x = (uint32_t)l0 | ((uint32_t)l1 << 16); L.y = (uint32_t)l2 | ((uint32_t)l3 << 16);
    dh[j] = H; dl[j] = L;
}

// transpose v [z][s][d] -> vT [z][d][s], single fp16
__global__ void k_vT() {
    __shared__ float t[32][33];
    int z = blockIdx.z;
    int d0 = blockIdx.x * 32, s0 = blockIdx.y * 32;
    int tx = threadIdx.x, ty = threadIdx.y;
    t[ty][tx] = g_vf[((size_t)z*SEQ + s0 + ty)*HD + d0 + tx];
    __syncthreads();
    float x = t[tx][ty];
    size_t o = ((size_t)z*HD + d0 + ty)*SEQ + s0 + tx;
    g_vt[o] = __float2half_rn(x);
}

// ======================= fp16 GEMMs ========================================
#define RS 72                         // row stride elems (144B), 9 granules
#define MAT_A (128*RS*2)              // 18432
#define MAT_B (256*RS*2)              // 36864

// --- 2-product (proj): A single + B hi/lo ---
#define P_OFF_A  0
#define P_OFF_BH MAT_A
#define P_OFF_BL (MAT_A + MAT_B)
#define P_STAGE (MAT_A + 2*MAT_B)     // 92160
#define P_DYN (2*P_STAGE)             // 184320

__device__ __forceinline__ void load_chunk2(
    const __half* __restrict__ A, int lda,
    const __half* __restrict__ Bh, const __half* __restrict__ Bl, int ldb,
    int k0, uint32_t stage)
{
    int t = threadIdx.x;
    #pragma unroll
    for (int i = 0; i < 4; i++) {
        int v = t + (i << 8);
        int row = v >> 3, g = v & 7;
        uint32_t doff = (uint32_t)row * (RS*2) + (uint32_t)(g << 4);
        cp16(stage + P_OFF_A + doff, A + (size_t)row * lda + k0 + g*8);
    }
    #pragma unroll
    for (int i = 0; i < 8; i++) {
        int v = t + (i << 8);
        int row = v >> 3, g = v & 7;
        uint32_t doff = (uint32_t)row * (RS*2) + (uint32_t)(g << 4);
        const size_t rb = (size_t)row * ldb + k0 + g*8;
        cp16(stage + P_OFF_BH + doff, Bh + rb);
        cp16(stage + P_OFF_BL + doff, Bl + rb);
    }
}

template<class Epi>
__device__ __forceinline__ void gemm_body2(
    const __half* __restrict__ A, int lda,
    const __half* __restrict__ Bhi, const __half* __restrict__ Blo, int ldb,
    int K, Epi epi)
{
    extern __shared__ char dsm[];
    const uint32_t sbase = smem_to_u32(dsm);
    const int tid = threadIdx.x;
    const int wid = tid >> 5, lane = tid & 31;
    const int wm = wid & 1, wn = wid >> 1;
    const int m0 = blockIdx.y * 128, n0 = blockIdx.x * 256;

    const __half* A0 = A + (size_t)m0 * lda;
    const __half* B0 = Bhi + (size_t)n0 * ldb;
    const __half* B1 = Blo + (size_t)n0 * ldb;

    float acc[4][8][4];
    #pragma unroll
    for (int a = 0; a < 4; a++)
        #pragma unroll
        for (int b = 0; b < 8; b++)
            #pragma unroll
            for (int c = 0; c < 4; c++) acc[a][b][c] = 0.0f;

    const int nc = K >> 6;
    load_chunk2(A0, lda, B0, B1, ldb, 0, sbase);
    cp_commit();

    for (int c = 0; c < nc; c++) {
        cp_wait<0>();
        __syncthreads();
        if (c + 1 < nc) {
            load_chunk2(A0, lda, B0, B1, ldb, (c+1) << 6,
                        sbase + (uint32_t)((c+1) & 1) * P_STAGE);
            cp_commit();
        }
        const uint32_t sb = sbase + (uint32_t)(c & 1) * P_STAGE;
        #pragma unroll
        for (int kk = 0; kk < 4; kk++) {
            uint32_t ah[4][4];
            #pragma unroll
            for (int mt = 0; mt < 4; mt++) {
                int row = wm*64 + mt*16 + (lane & 15);
                uint32_t off = (uint32_t)row*(RS*2) + (uint32_t)kk*32 + ((lane >> 4) << 4);
                LDSM_X4(ah[mt], sb + P_OFF_A + off);
            }
            #pragma unroll
            for (int nt = 0; nt < 4; nt++) {
                uint32_t bh[4], bl[4];
                int g = lane >> 3;
                int row = wn*64 + nt*16 + ((g >> 1) << 3) + (lane & 7);
                uint32_t off = (uint32_t)row*(RS*2) + (uint32_t)kk*32 + ((g & 1) << 4);
                LDSM_X4(bh, sb + P_OFF_BH + off);
                LDSM_X4(bl, sb + P_OFF_BL + off);
                #pragma unroll
                for (int mt = 0; mt < 4; mt++) {
                    mma16816h(acc[mt][nt*2+0], ah[mt], bh[0], bh[1]);
                    mma16816h(acc[mt][nt*2+0], ah[mt], bl[0], bl[1]);
                    mma16816h(acc[mt][nt*2+1], ah[mt], bh[2], bh[3]);
                    mma16816h(acc[mt][nt*2+1], ah[mt], bl[2], bl[3]);
                }
            }
        }
    }

    #pragma unroll
    for (int mt = 0; mt < 4; mt++)
        #pragma unroll
        for (int nj = 0; nj < 8; nj++)
            #pragma unroll
            for (int e = 0; e < 4; e++) {
                int m = m0 + wm*64 + mt*16 + (lane >> 2) + ((e >> 1) << 3);
                int n = n0 + wn*64 + nj*8 + ((lane & 3) << 1) + (e & 1);
                epi(m, n, acc[mt][nj][e]);
            }
}

// --- 1-product (out): A single + B single ---
#define O_OFF_A  0
#define O_OFF_B  MAT_A
#define O_STAGE (MAT_A + MAT_B)       // 55296
#define O_DYN (2*O_STAGE)             // 110592

__device__ __forceinline__ void load_chunk1(
    const __half* __restrict__ A, int lda,
    const __half* __restrict__ B, int ldb,
    int k0, uint32_t stage)
{
    int t = threadIdx.x;
    #pragma unroll
    for (int i = 0; i < 4; i++) {
        int v = t + (i << 8);
        int row = v >> 3, g = v & 7;
        uint32_t doff = (uint32_t)row * (RS*2) + (uint32_t)(g << 4);
        cp16(stage + O_OFF_A + doff, A + (size_t)row * lda + k0 + g*8);
    }
    #pragma unroll
    for (int i = 0; i < 8; i++) {
        int v = t + (i << 8);
        int row = v >> 3, g = v & 7;
        uint32_t doff = (uint32_t)row * (RS*2) + (uint32_t)(g << 4);
        cp16(stage + O_OFF_B + doff, B + (size_t)row * ldb + k0 + g*8);
    }
}

template<class Epi>
__device__ __forceinline__ void gemm_body1(
    const __half* __restrict__ A, int lda,
    const __half* __restrict__ B, int ldb,
    int K, Epi epi)
{
    extern __shared__ char dsm[];
    const uint32_t sbase = smem_to_u32(dsm);
    const int tid = threadIdx.x;
    const int wid = tid >> 5, lane = tid & 31;
    const int wm = wid & 1, wn = wid >> 1;
    const int m0 = blockIdx.y * 128, n0 = blockIdx.x * 256;

    const __half* A0 = A + (size_t)m0 * lda;
    const __half* B0 = B + (size_t)n0 * ldb;

    float acc[4][8][4];
    #pragma unroll
    for (int a = 0; a < 4; a++)
        #pragma unroll
        for (int b = 0; b < 8; b++)
            #pragma unroll
            for (int c = 0; c < 4; c++) acc[a][b][c] = 0.0f;

    const int nc = K >> 6;
    load_chunk1(A0, lda, B0, ldb, 0, sbase);
    cp_commit();

    for (int c = 0; c < nc; c++) {
        cp_wait<0>();
        __syncthreads();
        if (c + 1 < nc) {
            load_chunk1(A0, lda, B0, ldb, (c+1) << 6,
                        sbase + (uint32_t)((c+1) & 1) * O_STAGE);
            cp_commit();
        }
        const uint32_t sb = sbase + (uint32_t)(c & 1) * O_STAGE;
        #pragma unroll
        for (int kk = 0; kk < 4; kk++) {
            uint32_t ah[4][4];
            #pragma unroll
            for (int mt = 0; mt < 4; mt++) {
                int row = wm*64 + mt*16 + (lane & 15);
                uint32_t off = (uint32_t)row*(RS*2) + (uint32_t)kk*32 + ((lane >> 4) << 4);
                LDSM_X4(ah[mt], sb + O_OFF_A + off);
            }
            #pragma unroll
            for (int nt = 0; nt < 4; nt++) {
                uint32_t bh[4];
                int g = lane >> 3;
                int row = wn*64 + nt*16 + ((g >> 1) << 3) + (lane & 7);
                uint32_t off = (uint32_t)row*(RS*2) + (uint32_t)kk*32 + ((g & 1) << 4);
                LDSM_X4(bh, sb + O_OFF_B + off);
                #pragma unroll
                for (int mt = 0; mt < 4; mt++) {
                    mma16816h(acc[mt][nt*2+0], ah[mt], bh[0], bh[1]);
                    mma16816h(acc[mt][nt*2+1], ah[mt], bh[2], bh[3]);
                }
            }
        }
    }

    #pragma unroll
    for (int mt = 0; mt < 4; mt++)
        #pragma unroll
        for (int nj = 0; nj < 8; nj++)
            #pragma unroll
            for (int e = 0; e < 4; e++) {
                int m = m0 + wm*64 + mt*16 + (lane >> 2) + ((e >> 1) << 3);
                int n = n0 + wn*64 + nj*8 + ((lane & 3) << 1) + (e & 1);
                epi(m, n, acc[mt][nj][e]);
            }
}

struct EpiProjFused {
    __device__ __forceinline__ void operator()(int m, int n, float v) const {
        int b = m >> 11, s = m & (SEQ-1);
        if (n < QDIM) {
            int h = n >> 8, d = n & (HD-1);
            g_qf[(((size_t)b*NH + h)*SEQ + s)*HD + d] = v;
        } else if (n < QDIM + KVDIM) {
            int nn = n - QDIM;
            int h = nn >> 8, d = nn & (HD-1);
            g_kf[(((size_t)b*NKV + h)*SEQ + s)*HD + d] = v;
        } else {
            int nn = n - QDIM - KVDIM;
            int h = nn >> 8, d = nn & (HD-1);
            g_vf[(((size_t)b*NKV + h)*SEQ + s)*HD + d] = v;
        }
    }
};
struct EpiPlain {
    float* C; int ldc;
    __device__ __forceinline__ void operator()(int m, int n, float v) const {
        C[(size_t)m*ldc + n] = v;
    }
};

__global__ void __launch_bounds__(256, 1) g_proj() {
    gemm_body2(g_hsh, HIDDEN, g_wph, g_wpl, HIDDEN, HIDDEN, EpiProjFused{});
}
__global__ void __launch_bounds__(256, 1) g_out(float* __restrict__ out) {
    gemm_body1(g_ah, QDIM, g_woh, QDIM, QDIM, EpiPlain{out, HIDDEN});
}

// ======================= flash attention ===================================
// S phase: Q single + K single (2 mats/stage). V single (1 mat/stage).
#define FL_QK_STAGE 20480
#define FL_V_BASE   40960
#define FL_V_STAGE  20480
#define FL_SMEM     81920

__device__ __forceinline__ void fl_load_qk(
    const __half* __restrict__ Q, const __half* __restrict__ Kh,
    int s0, int c, uint32_t stage)
{
    int tid = threadIdx.x;
    #pragma unroll
    for (int i = 0; i < 4; i++) {
        const int mat = i >> 1;                     // 0 Q, 1 Kh
        int w = ((i & 1) << 8) + tid;
        int row = w >> 2, g = w & 3;
        uint32_t dst = stage + (uint32_t)mat*10240 + (uint32_t)row*80 + (uint32_t)(g << 4);
        size_t col = (size_t)(c*32 + g*8);
        if (mat == 0) cp16(dst, Q + (size_t)row*HD + col);
        else          cp16(dst, Kh + (size_t)(s0 + row)*HD + col);
    }
}
__device__ __forceinline__ void fl_load_v(
    const __half* __restrict__ V,
    int s0, int sl, uint32_t stage)
{
    int tid = threadIdx.x;
    #pragma unroll
    for (int i = 0; i < 4; i++) {
        int w = (i << 8) + tid;
        int row = w >> 2, g = w & 3;                // row 0..255 (d)
        uint32_t dst = stage + (uint32_t)row*80 + (uint32_t)(g << 4);
        size_t col = (size_t)(s0 + sl*32 + g*8);
        cp16(dst, V + (size_t)row*SEQ + col);
    }
}

__global__ void __launch_bounds__(256, 1) g_flash() {
    extern __shared__ char dsm[];
    const uint32_t sb = smem_to_u32(dsm);
    const int tid = threadIdx.x, wid = tid >> 5, lane = tid & 31;
    const int qt = blockIdx.x, z = blockIdx.y;
    const int b = z >> 3, h = z & 7, kv = h >> 2;
    const int q0 = qt * 128;

    const __half* Q  = g_qh + (size_t)z*SEQ*HD + (size_t)q0*HD;
    const __half* Kh = g_kh + (size_t)(b*NKV+kv)*SEQ*HD;
    const __half* V  = g_vt + (size_t)(b*NKV+kv)*HD*SEQ;

    float acc_o[32][4];
    #pragma unroll
    for (int i = 0; i < 32; i++)
        #pragma unroll
        for (int e = 0; e < 4; e++) acc_o[i][e] = 0.0f;
    float rm[2] = {-1e30f, -1e30f};
    float rl[2] = {0.0f, 0.0f};

    fl_load_qk(Q, Kh, 0, 0, sb);
    cp_commit();

    for (int kt = 0; kt < 16; kt++) {
        const int s0 = kt * 128;
        float acc_s[16][4];
        #pragma unroll
        for (int i = 0; i < 16; i++)
            #pragma unroll
            for (int e = 0; e < 4; e++) acc_s[i][e] = 0.0f;

        // ---- S phase: 8 d-chunks (pure fp16 1-product) ----
        for (int c = 0; c < 8; c++) {
            cp_wait<0>();
            __syncthreads();
            if (c < 7) fl_load_qk(Q, Kh, s0, c+1, sb + (uint32_t)((c+1)&1)*FL_QK_STAGE);
            else       fl_load_v(V, s0, 0, sb + FL_V_BASE);
            cp_commit();
            const uint32_t qkb = sb + (uint32_t)(c & 1) * FL_QK_STAGE;
            #pragma unroll
            for (int kk = 0; kk < 2; kk++) {
                uint32_t qf[4];
                uint32_t a_off = (uint32_t)(wid*16 + (lane & 15))*80 + (uint32_t)kk*32 + ((lane >> 4) << 4);
                LDSM_X4(qf, qkb + a_off);
                int g = lane >> 3;
                uint32_t c_off = (uint32_t)kk*32 + ((g & 1) << 4);
                #pragma unroll
                for (int nt2 = 0; nt2 < 8; nt2++) {
                    int row = nt2*16 + ((g >> 1) << 3) + (lane & 7);
                    uint32_t kh[4];
                    LDSM_X4(kh, qkb + 10240 + (uint32_t)row*80 + c_off);
                    mma16816h(acc_s[2*nt2],   qf, kh[0], kh[1]);
                    mma16816h(acc_s[2*nt2+1], qf, kh[2], kh[3]);
                }
            }
        }

        // ---- softmax (register-resident); P as single fp16 ----
        float mnew[2] = {-1e30f, -1e30f};
        #pragma unroll
        for (int nt = 0; nt < 16; nt++)
            #pragma unroll
            for (int e = 0; e < 4; e++) {
                float s = acc_s[nt][e];
                float y = s * 0.00125f;
                float y2 = y * y;
                float capped = s * 0.0625f * (1.0f - y2*(0.33333333f - y2*0.13333333f));
                acc_s[nt][e] = capped;
                mnew[e >> 1] = fmaxf(mnew[e >> 1], capped);
            }
        #pragma unroll
        for (int o = 1; o <= 2; o <<= 1) {
            mnew[0] = fmaxf(mnew[0], __shfl_xor_sync(0xFFFFFFFFu, mnew[0], o));
            mnew[1] = fmaxf(mnew[1], __shfl_xor_sync(0xFFFFFFFFu, mnew[1], o));
        }
        float mt[2], al[2];
        #pragma unroll
        for (int j = 0; j < 2; j++) {
            mt[j] = fmaxf(rm[j], mnew[j]);
            al[j] = __expf(rm[j] - mt[j]);
            rm[j] = mt[j];
        }
        uint32_t ph[8][4];
        float sum[2] = {0.0f, 0.0f};
        #pragma unroll
        for (int g2 = 0; g2 < 8; g2++) {
            unsigned short hh[8];
            #pragma unroll
            for (int half = 0; half < 2; half++) {
                int nt = 2*g2 + half;
                #pragma unroll
                for (int e = 0; e < 4; e++) {
                    float p = __expf(acc_s[nt][e] - mt[e >> 1]);
                    sum[e >> 1] += p;
                    hh[half*4+e] = __half_as_ushort(__float2half_rn(p));
                }
            }
            ph[g2][0] = (uint32_t)hh[0] | ((uint32_t)hh[1] << 16);
            ph[g2][1] = (uint32_t)hh[2] | ((uint32_t)hh[3] << 16);
            ph[g2][2] = (uint32_t)hh[4] | ((uint32_t)hh[5] << 16);
            ph[g2][3] = (uint32_t)hh[6] | ((uint32_t)hh[7] << 16);
        }
        #pragma unroll
        for (int o = 1; o <= 2; o <<= 1) {
            sum[0] += __shfl_xor_sync(0xFFFFFFFFu, sum[0], o);
            sum[1] += __shfl_xor_sync(0xFFFFFFFFu, sum[1], o);
        }
        rl[0] = rl[0]*al[0] + sum[0];
        rl[1] = rl[1]*al[1] + sum[1];
        #pragma unroll
        for (int nt = 0; nt < 32; nt++)
            #pragma unroll
            for (int e = 0; e < 4; e++) acc_o[nt][e] *= al[e >> 1];

        // ---- PV phase: pure fp16 1-product ----
        for (int sl = 0; sl < 4; sl++) {
            cp_wait<0>();
            __syncthreads();
            if (sl < 3)       fl_load_v(V, s0, sl+1, sb + FL_V_BASE + (uint32_t)((sl+1)&1)*FL_V_STAGE);
            else if (kt < 15) fl_load_qk(Q, Kh, s0 + 128, 0, sb);
            cp_commit();
            const uint32_t vb = sb + FL_V_BASE + (uint32_t)(sl & 1) * FL_V_STAGE;
            #pragma unroll
            for (int kk = 0; kk < 2; kk++) {
                const int g2 = sl*2 + kk;
                int g = lane >> 3;
                uint32_t c_off = (uint32_t)kk*32 + ((g & 1) << 4);
                #pragma unroll
                for (int nt2 = 0; nt2 < 16; nt2++) {
                    int row = nt2*16 + ((g >> 1) << 3) + (lane & 7);
                    uint32_t vh[4];
                    LDSM_X4(vh, vb + (uint32_t)row*80 + c_off);
                    mma16816h(acc_o[2*nt2],   ph[g2], vh[0], vh[1]);
                    mma16816h(acc_o[2*nt2+1], ph[g2], vh[2], vh[3]);
                }
            }
        }
    }

    // ---- epilogue: normalize + single fp16 store ----
    float inv[2] = {1.0f / rl[0], 1.0f / rl[1]};
    #pragma unroll
    for (int nt = 0; nt < 32; nt++)
        #pragma unroll
        for (int j = 0; j < 2; j++) {
            int rloc = wid*16 + (lane >> 2) + j*8;
            size_t m = (size_t)b*SEQ + q0 + rloc;
            int d = nt*8 + (lane & 3)*2;
            size_t o = m*QDIM + h*HD + d;
            float v0 = acc_o[nt][2*j+0] * inv[j];
            float v1 = acc_o[nt][2*j+1] * inv[j];
            uint32_t pack = (uint32_t)__half_as_ushort(__float2half_rn(v0)) |
                            ((uint32_t)__half_as_ushort(__float2half_rn(v1)) << 16);
            *(uint32_t*)(g_ah + o) = pack;
        }
}

// ======================= launch ============================================
extern "C" void kernel_launch(void* const* d_in, const int* in_sizes, int n_in,
                              void* d_out, int out_size) {
    const float* hs = (const float*)d_in[0];
    const float* Wq = (const float*)d_in[1];
    const float* Wk = (const float*)d_in[2];
    const float* Wv = (const float*)d_in[3];
    const float* Wo = (const float*)d_in[4];
    float* out = (float*)d_out;
    (void)in_sizes; (void)n_in; (void)out_size;

    cudaFuncSetAttribute(g_proj,  cudaFuncAttributeMaxDynamicSharedMemorySize, P_DYN);
    cudaFuncSetAttribute(g_out,   cudaFuncAttributeMaxDynamicSharedMemorySize, O_DYN);
    cudaFuncSetAttribute(g_flash, cudaFuncAttributeMaxDynamicSharedMemorySize, FL_SMEM);

    // launch 1: fused conversion of all fp32 inputs
    k_split_all<<<N4_TOTAL/256, 256>>>((const float4*)hs, (const float4*)Wq,
                                       (const float4*)Wk, (const float4*)Wv,
                                       (const float4*)Wo);
    // launches 2-3: rope tables
    k_invfreq<<<1, 128>>>();
    k_ropetab<<<SEQ, 128>>>();

    // launch 4: fused QKV projection (profiled slot)
    g_proj<<<dim3(WPROWS/256, MTOT/128), 256, P_DYN>>>();

    // rope conversions + vT
    float *qf_p, *kf_p;
    cudaGetSymbolAddress((void**)&qf_p, g_qf);
    cudaGetSymbolAddress((void**)&kf_p, g_kf);
    __half *qh_p, *kh_p;
    cudaGetSymbolAddress((void**)&qh_p, g_qh);
    cudaGetSymbolAddress((void**)&kh_p, g_kh);
    k_rope_h<<<BATCH*NH*SEQ, 128>>>(qf_p, qh_p);
    k_rope_h<<<BATCH*NKV*SEQ, 128>>>(kf_p, kh_p);
    k_vT<<<dim3(HD/32, SEQ/32, BATCH*NKV), dim3(32, 32)>>>();

    // fused attention
    g_flash<<<dim3(SEQ/128, BATCH*NH), 256, FL_SMEM>>>();

    // output projection
    g_out<<<dim3(HIDDEN/256, MTOT/128), 256, O_DYN>>>(out);
}

// round 16
// speedup vs baseline: 2.2394x; 1.1939x over previous
#include <cuda_runtime.h>
#include <cuda_bf16.h>
#include <cuda_fp16.h>
#include <math.h>
#include <stdint.h>

#define HIDDEN 2048
#define NH 8
#define NKV 2
#define HD 256
#define BATCH 2
#define SEQ 2048
#define MTOT (BATCH*SEQ)            // 4096
#define QDIM (NH*HD)                // 2048
#define KVDIM (NKV*HD)              // 512
#define WPROWS (QDIM + 2*KVDIM)     // 3072

// ======================= PTX helpers =======================================
__device__ __forceinline__ uint32_t smem_to_u32(const void* p) {
    uint32_t a;
    asm("{ .reg .u64 t; cvta.to.shared.u64 t, %1; cvt.u32.u64 %0, t; }" : "=r"(a) : "l"(p));
    return a;
}
__device__ __forceinline__ void cp16(uint32_t dst, const void* src) {
    asm volatile("cp.async.cg.shared.global [%0], [%1], 16;" :: "r"(dst), "l"(src));
}
__device__ __forceinline__ void cp_commit() { asm volatile("cp.async.commit_group;" ::: "memory"); }
template<int N> __device__ __forceinline__ void cp_wait() {
    asm volatile("cp.async.wait_group %0;" :: "n"(N) : "memory");
}
#define LDSM_X4(r, addr) \
    asm volatile("ldmatrix.sync.aligned.m8n8.x4.shared.b16 {%0,%1,%2,%3}, [%4];" \
        : "=r"((r)[0]), "=r"((r)[1]), "=r"((r)[2]), "=r"((r)[3]) : "r"(addr))

__device__ __forceinline__ void mma16816h(float* d, const uint32_t* a, uint32_t b0, uint32_t b1) {
    asm volatile("mma.sync.aligned.m16n8k16.row.col.f32.f16.f16.f32 "
        "{%0,%1,%2,%3}, {%4,%5,%6,%7}, {%8,%9}, {%0,%1,%2,%3};"
        : "+f"(d[0]), "+f"(d[1]), "+f"(d[2]), "+f"(d[3])
        : "r"(a[0]), "r"(a[1]), "r"(a[2]), "r"(a[3]), "r"(b0), "r"(b1));
}

// ======================= scratch (device globals) ==========================
__device__ __align__(16) __half g_hsh[(size_t)MTOT*HIDDEN];
__device__ __align__(16) __half g_wph[(size_t)WPROWS*HIDDEN];
__device__ __align__(16) __half g_woh[(size_t)HIDDEN*QDIM];
__device__ __align__(16) float g_qf[(size_t)MTOT*QDIM];
__device__ __align__(16) float g_kf[(size_t)BATCH*NKV*SEQ*HD];
__device__ __align__(16) float g_vf[(size_t)BATCH*NKV*SEQ*HD];
__device__ __align__(16) __half g_qh[(size_t)MTOT*QDIM];
__device__ __align__(16) __half g_kh[(size_t)BATCH*NKV*SEQ*HD];
__device__ __align__(16) __half g_vt[(size_t)BATCH*NKV*HD*SEQ];
__device__ __align__(16) __half g_ah[(size_t)MTOT*QDIM];
__device__ double g_invfreq[HD/2];
__device__ float g_cos[SEQ*(HD/2)];
__device__ float g_sin[SEQ*(HD/2)];

// ======================= small kernels =====================================
__global__ void k_invfreq() {
    int i = threadIdx.x;
    if (i < HD/2) g_invfreq[i] = pow(10000.0, -2.0 * (double)i / (double)HD);
}
__global__ void k_ropetab() {
    int s = blockIdx.x, i = threadIdx.x;
    double ang = (double)s * g_invfreq[i];
    const double twopi = 6.283185307179586476925286766559;
    ang -= floor(ang / twopi) * twopi;
    float c, sn;
    sincosf((float)ang, &sn, &c);
    g_cos[s*(HD/2)+i] = c;
    g_sin[s*(HD/2)+i] = sn;
}

// rope + single fp16 (Q and K)
__global__ void k_rope_h(const float* __restrict__ src, __half* __restrict__ dst) {
    int r = blockIdx.x, i = threadIdx.x;
    int s = r & (SEQ-1);
    float c = g_cos[s*(HD/2)+i], sn = g_sin[s*(HD/2)+i];
    const float* row = src + (size_t)r * HD;
    float x1 = row[i], x2 = row[i + HD/2];
    dst[(size_t)r*HD + i]        = __float2half_rn(x1*c - x2*sn);
    dst[(size_t)r*HD + i + HD/2] = __float2half_rn(x2*c + x1*sn);
}

// ---- fused conversion: everything -> single fp16, ONE launch ---------------
#define N4_HS (MTOT*HIDDEN/4)
#define N4_WQ (QDIM*HIDDEN/4)
#define N4_WK (KVDIM*HIDDEN/4)
#define N4_WV (KVDIM*HIDDEN/4)
#define N4_WO (HIDDEN*QDIM/4)
#define N4_TOTAL (N4_HS+N4_WQ+N4_WK+N4_WV+N4_WO)

__global__ void k_split_all(const float4* __restrict__ hs, const float4* __restrict__ wq,
                            const float4* __restrict__ wk, const float4* __restrict__ wv,
                            const float4* __restrict__ wo) {
    int i = blockIdx.x * 256 + threadIdx.x;
    const float4* src;
    uint2* dst;
    int j;
    if (i < N4_HS) {
        j = i; src = hs; dst = (uint2*)g_hsh;
    } else if (i < N4_HS + N4_WQ) {
        j = i - N4_HS; src = wq; dst = (uint2*)g_wph;
    } else if (i < N4_HS + N4_WQ + N4_WK) {
        j = i - (N4_HS + N4_WQ); src = wk;
        dst = (uint2*)g_wph + (size_t)QDIM*HIDDEN/4;
    } else if (i < N4_HS + N4_WQ + N4_WK + N4_WV) {
        j = i - (N4_HS + N4_WQ + N4_WK); src = wv;
        dst = (uint2*)g_wph + (size_t)(QDIM+KVDIM)*HIDDEN/4;
    } else {
        j = i - (N4_HS + N4_WQ + N4_WK + N4_WV); src = wo;
        dst = (uint2*)g_woh;
    }
    float4 v = src[j];
    uint2 H;
    H.x = (uint32_t)__half_as_ushort(__float2half_rn(v.x)) |
          ((uint32_t)__half_as_ushort(__float2half_rn(v.y)) << 16);
    H.y = (uint32_t)__half_as_ushort(__float2half_rn(v.z)) |
          ((uint32_t)__half_as_ushort(__float2half_rn(v.w)) << 16);
    dst[j] = H;
}

// transpose v [z][s][d] -> vT [z][d][s], single fp16
__global__ void k_vT() {
    __shared__ float t[32][33];
    int z = blockIdx.z;
    int d0 = blockIdx.x * 32, s0 = blockIdx.y * 32;
    int tx = threadIdx.x, ty = threadIdx.y;
    t[ty][tx] = g_vf[((size_t)z*SEQ + s0 + ty)*HD + d0 + tx];
    __syncthreads();
    float x = t[tx][ty];
    size_t o = ((size_t)z*HD + d0 + ty)*SEQ + s0 + tx;
    g_vt[o] = __float2half_rn(x);
}

// ======================= fp16 1-product GEMM ================================
#define RS 72                         // row stride elems (144B), 9 granules
#define MAT_A (128*RS*2)              // 18432
#define MAT_B (256*RS*2)              // 36864
#define O_OFF_A  0
#define O_OFF_B  MAT_A
#define O_STAGE (MAT_A + MAT_B)       // 55296
#define O_DYN (2*O_STAGE)             // 110592

__device__ __forceinline__ void load_chunk1(
    const __half* __restrict__ A, int lda,
    const __half* __restrict__ B, int ldb,
    int k0, uint32_t stage)
{
    int t = threadIdx.x;
    #pragma unroll
    for (int i = 0; i < 4; i++) {
        int v = t + (i << 8);
        int row = v >> 3, g = v & 7;
        uint32_t doff = (uint32_t)row * (RS*2) + (uint32_t)(g << 4);
        cp16(stage + O_OFF_A + doff, A + (size_t)row * lda + k0 + g*8);
    }
    #pragma unroll
    for (int i = 0; i < 8; i++) {
        int v = t + (i << 8);
        int row = v >> 3, g = v & 7;
        uint32_t doff = (uint32_t)row * (RS*2) + (uint32_t)(g << 4);
        cp16(stage + O_OFF_B + doff, B + (size_t)row * ldb + k0 + g*8);
    }
}

template<class Epi>
__device__ __forceinline__ void gemm_body1(
    const __half* __restrict__ A, int lda,
    const __half* __restrict__ B, int ldb,
    int K, Epi epi)
{
    extern __shared__ char dsm[];
    const uint32_t sbase = smem_to_u32(dsm);
    const int tid = threadIdx.x;
    const int wid = tid >> 5, lane = tid & 31;
    const int wm = wid & 1, wn = wid >> 1;
    const int m0 = blockIdx.y * 128, n0 = blockIdx.x * 256;

    const __half* A0 = A + (size_t)m0 * lda;
    const __half* B0 = B + (size_t)n0 * ldb;

    float acc[4][8][4];
    #pragma unroll
    for (int a = 0; a < 4; a++)
        #pragma unroll
        for (int b = 0; b < 8; b++)
            #pragma unroll
            for (int c = 0; c < 4; c++) acc[a][b][c] = 0.0f;

    const int nc = K >> 6;
    load_chunk1(A0, lda, B0, ldb, 0, sbase);
    cp_commit();

    for (int c = 0; c < nc; c++) {
        cp_wait<0>();
        __syncthreads();
        if (c + 1 < nc) {
            load_chunk1(A0, lda, B0, ldb, (c+1) << 6,
                        sbase + (uint32_t)((c+1) & 1) * O_STAGE);
            cp_commit();
        }
        const uint32_t sb = sbase + (uint32_t)(c & 1) * O_STAGE;
        #pragma unroll
        for (int kk = 0; kk < 4; kk++) {
            uint32_t ah[4][4];
            #pragma unroll
            for (int mt = 0; mt < 4; mt++) {
                int row = wm*64 + mt*16 + (lane & 15);
                uint32_t off = (uint32_t)row*(RS*2) + (uint32_t)kk*32 + ((lane >> 4) << 4);
                LDSM_X4(ah[mt], sb + O_OFF_A + off);
            }
            #pragma unroll
            for (int nt = 0; nt < 4; nt++) {
                uint32_t bh[4];
                int g = lane >> 3;
                int row = wn*64 + nt*16 + ((g >> 1) << 3) + (lane & 7);
                uint32_t off = (uint32_t)row*(RS*2) + (uint32_t)kk*32 + ((g & 1) << 4);
                LDSM_X4(bh, sb + O_OFF_B + off);
                #pragma unroll
                for (int mt = 0; mt < 4; mt++) {
                    mma16816h(acc[mt][nt*2+0], ah[mt], bh[0], bh[1]);
                    mma16816h(acc[mt][nt*2+1], ah[mt], bh[2], bh[3]);
                }
            }
        }
    }

    #pragma unroll
    for (int mt = 0; mt < 4; mt++)
        #pragma unroll
        for (int nj = 0; nj < 8; nj++)
            #pragma unroll
            for (int e = 0; e < 4; e++) {
                int m = m0 + wm*64 + mt*16 + (lane >> 2) + ((e >> 1) << 3);
                int n = n0 + wn*64 + nj*8 + ((lane & 3) << 1) + (e & 1);
                epi(m, n, acc[mt][nj][e]);
            }
}

struct EpiProjFused {
    __device__ __forceinline__ void operator()(int m, int n, float v) const {
        int b = m >> 11, s = m & (SEQ-1);
        if (n < QDIM) {
            int h = n >> 8, d = n & (HD-1);
            g_qf[(((size_t)b*NH + h)*SEQ + s)*HD + d] = v;
        } else if (n < QDIM + KVDIM) {
            int nn = n - QDIM;
            int h = nn >> 8, d = nn & (HD-1);
            g_kf[(((size_t)b*NKV + h)*SEQ + s)*HD + d] = v;
        } else {
            int nn = n - QDIM - KVDIM;
            int h = nn >> 8, d = nn & (HD-1);
            g_vf[(((size_t)b*NKV + h)*SEQ + s)*HD + d] = v;
        }
    }
};
struct EpiPlain {
    float* C; int ldc;
    __device__ __forceinline__ void operator()(int m, int n, float v) const {
        C[(size_t)m*ldc + n] = v;
    }
};

__global__ void __launch_bounds__(256, 1) g_proj() {
    gemm_body1(g_hsh, HIDDEN, g_wph, HIDDEN, HIDDEN, EpiProjFused{});
}
__global__ void __launch_bounds__(256, 1) g_out(float* __restrict__ out) {
    gemm_body1(g_ah, QDIM, g_woh, QDIM, QDIM, EpiPlain{out, HIDDEN});
}

// ======================= flash attention ===================================
#define FL_QK_STAGE 20480
#define FL_V_BASE   40960
#define FL_V_STAGE  20480
#define FL_SMEM     81920

__device__ __forceinline__ void fl_load_qk(
    const __half* __restrict__ Q, const __half* __restrict__ Kh,
    int s0, int c, uint32_t stage)
{
    int tid = threadIdx.x;
    #pragma unroll
    for (int i = 0; i < 4; i++) {
        const int mat = i >> 1;                     // 0 Q, 1 Kh
        int w = ((i & 1) << 8) + tid;
        int row = w >> 2, g = w & 3;
        uint32_t dst = stage + (uint32_t)mat*10240 + (uint32_t)row*80 + (uint32_t)(g << 4);
        size_t col = (size_t)(c*32 + g*8);
        if (mat == 0) cp16(dst, Q + (size_t)row*HD + col);
        else          cp16(dst, Kh + (size_t)(s0 + row)*HD + col);
    }
}
__device__ __forceinline__ void fl_load_v(
    const __half* __restrict__ V,
    int s0, int sl, uint32_t stage)
{
    int tid = threadIdx.x;
    #pragma unroll
    for (int i = 0; i < 4; i++) {
        int w = (i << 8) + tid;
        int row = w >> 2, g = w & 3;
        uint32_t dst = stage + (uint32_t)row*80 + (uint32_t)(g << 4);
        size_t col = (size_t)(s0 + sl*32 + g*8);
        cp16(dst, V + (size_t)row*SEQ + col);
    }
}

__global__ void __launch_bounds__(256, 1) g_flash() {
    extern __shared__ char dsm[];
    const uint32_t sb = smem_to_u32(dsm);
    const int tid = threadIdx.x, wid = tid >> 5, lane = tid & 31;
    const int qt = blockIdx.x, z = blockIdx.y;
    const int b = z >> 3, h = z & 7, kv = h >> 2;
    const int q0 = qt * 128;

    const __half* Q  = g_qh + (size_t)z*SEQ*HD + (size_t)q0*HD;
    const __half* Kh = g_kh + (size_t)(b*NKV+kv)*SEQ*HD;
    const __half* V  = g_vt + (size_t)(b*NKV+kv)*HD*SEQ;

    float acc_o[32][4];
    #pragma unroll
    for (int i = 0; i < 32; i++)
        #pragma unroll
        for (int e = 0; e < 4; e++) acc_o[i][e] = 0.0f;
    float rm[2] = {-1e30f, -1e30f};
    float rl[2] = {0.0f, 0.0f};

    fl_load_qk(Q, Kh, 0, 0, sb);
    cp_commit();

    for (int kt = 0; kt < 16; kt++) {
        const int s0 = kt * 128;
        float acc_s[16][4];
        #pragma unroll
        for (int i = 0; i < 16; i++)
            #pragma unroll
            for (int e = 0; e < 4; e++) acc_s[i][e] = 0.0f;

        // ---- S phase: 8 d-chunks (pure fp16 1-product) ----
        for (int c = 0; c < 8; c++) {
            cp_wait<0>();
            __syncthreads();
            if (c < 7) fl_load_qk(Q, Kh, s0, c+1, sb + (uint32_t)((c+1)&1)*FL_QK_STAGE);
            else       fl_load_v(V, s0, 0, sb + FL_V_BASE);
            cp_commit();
            const uint32_t qkb = sb + (uint32_t)(c & 1) * FL_QK_STAGE;
            #pragma unroll
            for (int kk = 0; kk < 2; kk++) {
                uint32_t qf[4];
                uint32_t a_off = (uint32_t)(wid*16 + (lane & 15))*80 + (uint32_t)kk*32 + ((lane >> 4) << 4);
                LDSM_X4(qf, qkb + a_off);
                int g = lane >> 3;
                uint32_t c_off = (uint32_t)kk*32 + ((g & 1) << 4);
                #pragma unroll
                for (int nt2 = 0; nt2 < 8; nt2++) {
                    int row = nt2*16 + ((g >> 1) << 3) + (lane & 7);
                    uint32_t kh[4];
                    LDSM_X4(kh, qkb + 10240 + (uint32_t)row*80 + c_off);
                    mma16816h(acc_s[2*nt2],   qf, kh[0], kh[1]);
                    mma16816h(acc_s[2*nt2+1], qf, kh[2], kh[3]);
                }
            }
        }

        // ---- softmax (register-resident); P as single fp16 ----
        float mnew[2] = {-1e30f, -1e30f};
        #pragma unroll
        for (int nt = 0; nt < 16; nt++)
            #pragma unroll
            for (int e = 0; e < 4; e++) {
                float s = acc_s[nt][e];
                float y = s * 0.00125f;
                float y2 = y * y;
                float capped = s * 0.0625f * (1.0f - y2*(0.33333333f - y2*0.13333333f));
                acc_s[nt][e] = capped;
                mnew[e >> 1] = fmaxf(mnew[e >> 1], capped);
            }
        #pragma unroll
        for (int o = 1; o <= 2; o <<= 1) {
            mnew[0] = fmaxf(mnew[0], __shfl_xor_sync(0xFFFFFFFFu, mnew[0], o));
            mnew[1] = fmaxf(mnew[1], __shfl_xor_sync(0xFFFFFFFFu, mnew[1], o));
        }
        float mt[2], al[2];
        #pragma unroll
        for (int j = 0; j < 2; j++) {
            mt[j] = fmaxf(rm[j], mnew[j]);
            al[j] = __expf(rm[j] - mt[j]);
            rm[j] = mt[j];
        }
        uint32_t ph[8][4];
        float sum[2] = {0.0f, 0.0f};
        #pragma unroll
        for (int g2 = 0; g2 < 8; g2++) {
            unsigned short hh[8];
            #pragma unroll
            for (int half = 0; half < 2; half++) {
                int nt = 2*g2 + half;
                #pragma unroll
                for (int e = 0; e < 4; e++) {
                    float p = __expf(acc_s[nt][e] - mt[e >> 1]);
                    sum[e >> 1] += p;
                    hh[half*4+e] = __half_as_ushort(__float2half_rn(p));
                }
            }
            ph[g2][0] = (uint32_t)hh[0] | ((uint32_t)hh[1] << 16);
            ph[g2][1] = (uint32_t)hh[2] | ((uint32_t)hh[3] << 16);
            ph[g2][2] = (uint32_t)hh[4] | ((uint32_t)hh[5] << 16);
            ph[g2][3] = (uint32_t)hh[6] | ((uint32_t)hh[7] << 16);
        }
        #pragma unroll
        for (int o = 1; o <= 2; o <<= 1) {
            sum[0] += __shfl_xor_sync(0xFFFFFFFFu, sum[0], o);
            sum[1] += __shfl_xor_sync(0xFFFFFFFFu, sum[1], o);
        }
        rl[0] = rl[0]*al[0] + sum[0];
        rl[1] = rl[1]*al[1] + sum[1];
        #pragma unroll
        for (int nt = 0; nt < 32; nt++)
            #pragma unroll
            for (int e = 0; e < 4; e++) acc_o[nt][e] *= al[e >> 1];

        // ---- PV phase: pure fp16 1-product ----
        for (int sl = 0; sl < 4; sl++) {
            cp_wait<0>();
            __syncthreads();
            if (sl < 3)       fl_load_v(V, s0, sl+1, sb + FL_V_BASE + (uint32_t)((sl+1)&1)*FL_V_STAGE);
            else if (kt < 15) fl_load_qk(Q, Kh, s0 + 128, 0, sb);
            cp_commit();
            const uint32_t vb = sb + FL_V_BASE + (uint32_t)(sl & 1) * FL_V_STAGE;
            #pragma unroll
            for (int kk = 0; kk < 2; kk++) {
                const int g2 = sl*2 + kk;
                int g = lane >> 3;
                uint32_t c_off = (uint32_t)kk*32 + ((g & 1) << 4);
                #pragma unroll
                for (int nt2 = 0; nt2 < 16; nt2++) {
                    int row = nt2*16 + ((g >> 1) << 3) + (lane & 7);
                    uint32_t vh[4];
                    LDSM_X4(vh, vb + (uint32_t)row*80 + c_off);
                    mma16816h(acc_o[2*nt2],   ph[g2], vh[0], vh[1]);
                    mma16816h(acc_o[2*nt2+1], ph[g2], vh[2], vh[3]);
                }
            }
        }
    }

    // ---- epilogue: normalize + single fp16 store ----
    float inv[2] = {1.0f / rl[0], 1.0f / rl[1]};
    #pragma unroll
    for (int nt = 0; nt < 32; nt++)
        #pragma unroll
        for (int j = 0; j < 2; j++) {
            int rloc = wid*16 + (lane >> 2) + j*8;
            size_t m = (size_t)b*SEQ + q0 + rloc;
            int d = nt*8 + (lane & 3)*2;
            size_t o = m*QDIM + h*HD + d;
            float v0 = acc_o[nt][2*j+0] * inv[j];
            float v1 = acc_o[nt][2*j+1] * inv[j];
            uint32_t pack = (uint32_t)__half_as_ushort(__float2half_rn(v0)) |
                            ((uint32_t)__half_as_ushort(__float2half_rn(v1)) << 16);
            *(uint32_t*)(g_ah + o) = pack;
        }
}

// ======================= launch ============================================
extern "C" void kernel_launch(void* const* d_in, const int* in_sizes, int n_in,
                              void* d_out, int out_size) {
    const float* hs = (const float*)d_in[0];
    const float* Wq = (const float*)d_in[1];
    const float* Wk = (const float*)d_in[2];
    const float* Wv = (const float*)d_in[3];
    const float* Wo = (const float*)d_in[4];
    float* out = (float*)d_out;
    (void)in_sizes; (void)n_in; (void)out_size;

    cudaFuncSetAttribute(g_proj,  cudaFuncAttributeMaxDynamicSharedMemorySize, O_DYN);
    cudaFuncSetAttribute(g_out,   cudaFuncAttributeMaxDynamicSharedMemorySize, O_DYN);
    cudaFuncSetAttribute(g_flash, cudaFuncAttributeMaxDynamicSharedMemorySize, FL_SMEM);

    // launch 1: fused fp16 conversion of all fp32 inputs
    k_split_all<<<N4_TOTAL/256, 256>>>((const float4*)hs, (const float4*)Wq,
                                       (const float4*)Wk, (const float4*)Wv,
                                       (const float4*)Wo);
    // launches 2-3: rope tables
    k_invfreq<<<1, 128>>>();
    k_ropetab<<<SEQ, 128>>>();

    // launch 4: fused QKV projection (profiled slot)
    g_proj<<<dim3(WPROWS/256, MTOT/128), 256, O_DYN>>>();

    // rope conversions + vT
    float *qf_p, *kf_p;
    cudaGetSymbolAddress((void**)&qf_p, g_qf);
    cudaGetSymbolAddress((void**)&kf_p, g_kf);
    __half *qh_p, *kh_p;
    cudaGetSymbolAddress((void**)&qh_p, g_qh);
    cudaGetSymbolAddress((void**)&kh_p, g_kh);
    k_rope_h<<<BATCH*NH*SEQ, 128>>>(qf_p, qh_p);
    k_rope_h<<<BATCH*NKV*SEQ, 128>>>(kf_p, kh_p);
    k_vT<<<dim3(HD/32, SEQ/32, BATCH*NKV), dim3(32, 32)>>>();

    // fused attention
    g_flash<<<dim3(SEQ/128, BATCH*NH), 256, FL_SMEM>>>();

    // output projection
    g_out<<<dim3(HIDDEN/256, MTOT/128), 256, O_DYN>>>(out);
}

// round 17
// speedup vs baseline: 2.3378x; 1.0440x over previous
#include <cuda_runtime.h>
#include <cuda_bf16.h>
#include <cuda_fp16.h>
#include <math.h>
#include <stdint.h>

#define HIDDEN 2048
#define NH 8
#define NKV 2
#define HD 256
#define BATCH 2
#define SEQ 2048
#define MTOT (BATCH*SEQ)            // 4096
#define QDIM (NH*HD)                // 2048
#define KVDIM (NKV*HD)              // 512
#define WPROWS (QDIM + 2*KVDIM)     // 3072

// ======================= PTX helpers =======================================
__device__ __forceinline__ uint32_t smem_to_u32(const void* p) {
    uint32_t a;
    asm("{ .reg .u64 t; cvta.to.shared.u64 t, %1; cvt.u32.u64 %0, t; }" : "=r"(a) : "l"(p));
    return a;
}
__device__ __forceinline__ void cp16(uint32_t dst, const void* src) {
    asm volatile("cp.async.cg.shared.global [%0], [%1], 16;" :: "r"(dst), "l"(src));
}
__device__ __forceinline__ void cp_commit() { asm volatile("cp.async.commit_group;" ::: "memory"); }
template<int N> __device__ __forceinline__ void cp_wait() {
    asm volatile("cp.async.wait_group %0;" :: "n"(N) : "memory");
}
#define LDSM_X4(r, addr) \
    asm volatile("ldmatrix.sync.aligned.m8n8.x4.shared.b16 {%0,%1,%2,%3}, [%4];" \
        : "=r"((r)[0]), "=r"((r)[1]), "=r"((r)[2]), "=r"((r)[3]) : "r"(addr))

__device__ __forceinline__ void mma16816h(float* d, const uint32_t* a, uint32_t b0, uint32_t b1) {
    asm volatile("mma.sync.aligned.m16n8k16.row.col.f32.f16.f16.f32 "
        "{%0,%1,%2,%3}, {%4,%5,%6,%7}, {%8,%9}, {%0,%1,%2,%3};"
        : "+f"(d[0]), "+f"(d[1]), "+f"(d[2]), "+f"(d[3])
        : "r"(a[0]), "r"(a[1]), "r"(a[2]), "r"(a[3]), "r"(b0), "r"(b1));
}

// ======================= scratch (device globals) ==========================
__device__ __align__(16) __half g_hsh[(size_t)MTOT*HIDDEN];
__device__ __align__(16) __half g_wph[(size_t)WPROWS*HIDDEN];
__device__ __align__(16) __half g_woh[(size_t)HIDDEN*QDIM];
__device__ __align__(16) float g_qf[(size_t)MTOT*QDIM];
__device__ __align__(16) float g_kf[(size_t)BATCH*NKV*SEQ*HD];
__device__ __align__(16) float g_vf[(size_t)BATCH*NKV*SEQ*HD];
__device__ __align__(16) __half g_qh[(size_t)MTOT*QDIM];
__device__ __align__(16) __half g_kh[(size_t)BATCH*NKV*SEQ*HD];
__device__ __align__(16) __half g_vt[(size_t)BATCH*NKV*HD*SEQ];
__device__ __align__(16) __half g_ah[(size_t)MTOT*QDIM];
__device__ double g_invfreq[HD/2];
__device__ float g_cos[SEQ*(HD/2)];
__device__ float g_sin[SEQ*(HD/2)];

// ======================= small kernels =====================================
__global__ void k_invfreq() {
    int i = threadIdx.x;
    if (i < HD/2) g_invfreq[i] = pow(10000.0, -2.0 * (double)i / (double)HD);
}
__global__ void k_ropetab() {
    int s = blockIdx.x, i = threadIdx.x;
    double ang = (double)s * g_invfreq[i];
    const double twopi = 6.283185307179586476925286766559;
    ang -= floor(ang / twopi) * twopi;
    float c, sn;
    sincosf((float)ang, &sn, &c);
    g_cos[s*(HD/2)+i] = c;
    g_sin[s*(HD/2)+i] = sn;
}

// rope + single fp16 (Q and K)
__global__ void k_rope_h(const float* __restrict__ src, __half* __restrict__ dst) {
    int r = blockIdx.x, i = threadIdx.x;
    int s = r & (SEQ-1);
    float c = g_cos[s*(HD/2)+i], sn = g_sin[s*(HD/2)+i];
    const float* row = src + (size_t)r * HD;
    float x1 = row[i], x2 = row[i + HD/2];
    dst[(size_t)r*HD + i]        = __float2half_rn(x1*c - x2*sn);
    dst[(size_t)r*HD + i + HD/2] = __float2half_rn(x2*c + x1*sn);
}

// ---- fused conversion: everything -> single fp16, ONE launch ---------------
#define N4_HS (MTOT*HIDDEN/4)
#define N4_WQ (QDIM*HIDDEN/4)
#define N4_WK (KVDIM*HIDDEN/4)
#define N4_WV (KVDIM*HIDDEN/4)
#define N4_WO (HIDDEN*QDIM/4)
#define N4_TOTAL (N4_HS+N4_WQ+N4_WK+N4_WV+N4_WO)

__global__ void k_split_all(const float4* __restrict__ hs, const float4* __restrict__ wq,
                            const float4* __restrict__ wk, const float4* __restrict__ wv,
                            const float4* __restrict__ wo) {
    int i = blockIdx.x * 256 + threadIdx.x;
    const float4* src;
    uint2* dst;
    int j;
    if (i < N4_HS) {
        j = i; src = hs; dst = (uint2*)g_hsh;
    } else if (i < N4_HS + N4_WQ) {
        j = i - N4_HS; src = wq; dst = (uint2*)g_wph;
    } else if (i < N4_HS + N4_WQ + N4_WK) {
        j = i - (N4_HS + N4_WQ); src = wk;
        dst = (uint2*)g_wph + (size_t)QDIM*HIDDEN/4;
    } else if (i < N4_HS + N4_WQ + N4_WK + N4_WV) {
        j = i - (N4_HS + N4_WQ + N4_WK); src = wv;
        dst = (uint2*)g_wph + (size_t)(QDIM+KVDIM)*HIDDEN/4;
    } else {
        j = i - (N4_HS + N4_WQ + N4_WK + N4_WV); src = wo;
        dst = (uint2*)g_woh;
    }
    float4 v = src[j];
    uint2 H;
    H.x = (uint32_t)__half_as_ushort(__float2half_rn(v.x)) |
          ((uint32_t)__half_as_ushort(__float2half_rn(v.y)) << 16);
    H.y = (uint32_t)__half_as_ushort(__float2half_rn(v.z)) |
          ((uint32_t)__half_as_ushort(__float2half_rn(v.w)) << 16);
    dst[j] = H;
}

// transpose v [z][s][d] -> vT [z][d][s], single fp16
__global__ void k_vT() {
    __shared__ float t[32][33];
    int z = blockIdx.z;
    int d0 = blockIdx.x * 32, s0 = blockIdx.y * 32;
    int tx = threadIdx.x, ty = threadIdx.y;
    t[ty][tx] = g_vf[((size_t)z*SEQ + s0 + ty)*HD + d0 + tx];
    __syncthreads();
    float x = t[tx][ty];
    size_t o = ((size_t)z*HD + d0 + ty)*SEQ + s0 + tx;
    g_vt[o] = __float2half_rn(x);
}

// ======================= fp16 1-product GEMM (128x128, occ 2) ===============
#define RS 72                         // row stride elems (144B), 9 granules
#define GMAT (128*RS*2)               // 18432
#define G_OFF_A  0
#define G_OFF_B  GMAT
#define G_STAGE (2*GMAT)              // 36864
#define G_DYN (2*G_STAGE)             // 73728

__device__ __forceinline__ void load_chunk1(
    const __half* __restrict__ A, int lda,
    const __half* __restrict__ B, int ldb,
    int k0, uint32_t stage)
{
    int t = threadIdx.x;
    #pragma unroll
    for (int i = 0; i < 4; i++) {            // 128 rows x 8 granules per matrix
        int v = t + (i << 8);
        int row = v >> 3, g = v & 7;
        uint32_t doff = (uint32_t)row * (RS*2) + (uint32_t)(g << 4);
        cp16(stage + G_OFF_A + doff, A + (size_t)row * lda + k0 + g*8);
        cp16(stage + G_OFF_B + doff, B + (size_t)row * ldb + k0 + g*8);
    }
}

template<class Epi>
__device__ __forceinline__ void gemm_body1(
    const __half* __restrict__ A, int lda,
    const __half* __restrict__ B, int ldb,
    int K, Epi epi)
{
    extern __shared__ char dsm[];
    const uint32_t sbase = smem_to_u32(dsm);
    const int tid = threadIdx.x;
    const int wid = tid >> 5, lane = tid & 31;
    const int wm = wid & 1, wn = wid >> 1;        // 2m x 4n, warp 64x32
    const int m0 = blockIdx.y * 128, n0 = blockIdx.x * 128;

    const __half* A0 = A + (size_t)m0 * lda;
    const __half* B0 = B + (size_t)n0 * ldb;

    float acc[4][4][4];
    #pragma unroll
    for (int a = 0; a < 4; a++)
        #pragma unroll
        for (int b = 0; b < 4; b++)
            #pragma unroll
            for (int c = 0; c < 4; c++) acc[a][b][c] = 0.0f;

    const int nc = K >> 6;
    load_chunk1(A0, lda, B0, ldb, 0, sbase);
    cp_commit();

    for (int c = 0; c < nc; c++) {
        cp_wait<0>();
        __syncthreads();
        if (c + 1 < nc) {
            load_chunk1(A0, lda, B0, ldb, (c+1) << 6,
                        sbase + (uint32_t)((c+1) & 1) * G_STAGE);
            cp_commit();
        }
        const uint32_t sb = sbase + (uint32_t)(c & 1) * G_STAGE;
        #pragma unroll
        for (int kk = 0; kk < 4; kk++) {
            uint32_t ah[4][4];
            #pragma unroll
            for (int mt = 0; mt < 4; mt++) {
                int row = wm*64 + mt*16 + (lane & 15);
                uint32_t off = (uint32_t)row*(RS*2) + (uint32_t)kk*32 + ((lane >> 4) << 4);
                LDSM_X4(ah[mt], sb + G_OFF_A + off);
            }
            #pragma unroll
            for (int nt = 0; nt < 2; nt++) {
                uint32_t bh[4];
                int g = lane >> 3;
                int row = wn*32 + nt*16 + ((g >> 1) << 3) + (lane & 7);
                uint32_t off = (uint32_t)row*(RS*2) + (uint32_t)kk*32 + ((g & 1) << 4);
                LDSM_X4(bh, sb + G_OFF_B + off);
                #pragma unroll
                for (int mt = 0; mt < 4; mt++) {
                    mma16816h(acc[mt][nt*2+0], ah[mt], bh[0], bh[1]);
                    mma16816h(acc[mt][nt*2+1], ah[mt], bh[2], bh[3]);
                }
            }
        }
    }

    #pragma unroll
    for (int mt = 0; mt < 4; mt++)
        #pragma unroll
        for (int nj = 0; nj < 4; nj++)
            #pragma unroll
            for (int e = 0; e < 4; e++) {
                int m = m0 + wm*64 + mt*16 + (lane >> 2) + ((e >> 1) << 3);
                int n = n0 + wn*32 + nj*8 + ((lane & 3) << 1) + (e & 1);
                epi(m, n, acc[mt][nj][e]);
            }
}

struct EpiProjFused {
    __device__ __forceinline__ void operator()(int m, int n, float v) const {
        int b = m >> 11, s = m & (SEQ-1);
        if (n < QDIM) {
            int h = n >> 8, d = n & (HD-1);
            g_qf[(((size_t)b*NH + h)*SEQ + s)*HD + d] = v;
        } else if (n < QDIM + KVDIM) {
            int nn = n - QDIM;
            int h = nn >> 8, d = nn & (HD-1);
            g_kf[(((size_t)b*NKV + h)*SEQ + s)*HD + d] = v;
        } else {
            int nn = n - QDIM - KVDIM;
            int h = nn >> 8, d = nn & (HD-1);
            g_vf[(((size_t)b*NKV + h)*SEQ + s)*HD + d] = v;
        }
    }
};
struct EpiPlain {
    float* C; int ldc;
    __device__ __forceinline__ void operator()(int m, int n, float v) const {
        C[(size_t)m*ldc + n] = v;
    }
};

__global__ void __launch_bounds__(256, 2) g_proj() {
    gemm_body1(g_hsh, HIDDEN, g_wph, HIDDEN, HIDDEN, EpiProjFused{});
}
__global__ void __launch_bounds__(256, 2) g_out(float* __restrict__ out) {
    gemm_body1(g_ah, QDIM, g_woh, QDIM, QDIM, EpiPlain{out, HIDDEN});
}

// ======================= flash attention ===================================
#define FL_QK_STAGE 20480
#define FL_V_BASE   40960
#define FL_V_STAGE  20480
#define FL_SMEM     81920

__device__ __forceinline__ void fl_load_qk(
    const __half* __restrict__ Q, const __half* __restrict__ Kh,
    int s0, int c, uint32_t stage)
{
    int tid = threadIdx.x;
    #pragma unroll
    for (int i = 0; i < 4; i++) {
        const int mat = i >> 1;                     // 0 Q, 1 Kh
        int w = ((i & 1) << 8) + tid;
        int row = w >> 2, g = w & 3;
        uint32_t dst = stage + (uint32_t)mat*10240 + (uint32_t)row*80 + (uint32_t)(g << 4);
        size_t col = (size_t)(c*32 + g*8);
        if (mat == 0) cp16(dst, Q + (size_t)row*HD + col);
        else          cp16(dst, Kh + (size_t)(s0 + row)*HD + col);
    }
}
__device__ __forceinline__ void fl_load_v(
    const __half* __restrict__ V,
    int s0, int sl, uint32_t stage)
{
    int tid = threadIdx.x;
    #pragma unroll
    for (int i = 0; i < 4; i++) {
        int w = (i << 8) + tid;
        int row = w >> 2, g = w & 3;
        uint32_t dst = stage + (uint32_t)row*80 + (uint32_t)(g << 4);
        size_t col = (size_t)(s0 + sl*32 + g*8);
        cp16(dst, V + (size_t)row*SEQ + col);
    }
}

__global__ void __launch_bounds__(256, 1) g_flash() {
    extern __shared__ char dsm[];
    const uint32_t sb = smem_to_u32(dsm);
    const int tid = threadIdx.x, wid = tid >> 5, lane = tid & 31;
    const int qt = blockIdx.x, z = blockIdx.y;
    const int b = z >> 3, h = z & 7, kv = h >> 2;
    const int q0 = qt * 128;

    const __half* Q  = g_qh + (size_t)z*SEQ*HD + (size_t)q0*HD;
    const __half* Kh = g_kh + (size_t)(b*NKV+kv)*SEQ*HD;
    const __half* V  = g_vt + (size_t)(b*NKV+kv)*HD*SEQ;

    float acc_o[32][4];
    #pragma unroll
    for (int i = 0; i < 32; i++)
        #pragma unroll
        for (int e = 0; e < 4; e++) acc_o[i][e] = 0.0f;
    float rm[2] = {-1e30f, -1e30f};
    float rl[2] = {0.0f, 0.0f};

    fl_load_qk(Q, Kh, 0, 0, sb);
    cp_commit();

    for (int kt = 0; kt < 16; kt++) {
        const int s0 = kt * 128;
        float acc_s[16][4];
        #pragma unroll
        for (int i = 0; i < 16; i++)
            #pragma unroll
            for (int e = 0; e < 4; e++) acc_s[i][e] = 0.0f;

        // ---- S phase: 8 d-chunks (pure fp16 1-product) ----
        for (int c = 0; c < 8; c++) {
            cp_wait<0>();
            __syncthreads();
            if (c < 7) fl_load_qk(Q, Kh, s0, c+1, sb + (uint32_t)((c+1)&1)*FL_QK_STAGE);
            else       fl_load_v(V, s0, 0, sb + FL_V_BASE);
            cp_commit();
            const uint32_t qkb = sb + (uint32_t)(c & 1) * FL_QK_STAGE;
            #pragma unroll
            for (int kk = 0; kk < 2; kk++) {
                uint32_t qf[4];
                uint32_t a_off = (uint32_t)(wid*16 + (lane & 15))*80 + (uint32_t)kk*32 + ((lane >> 4) << 4);
                LDSM_X4(qf, qkb + a_off);
                int g = lane >> 3;
                uint32_t c_off = (uint32_t)kk*32 + ((g & 1) << 4);
                #pragma unroll
                for (int nt2 = 0; nt2 < 8; nt2++) {
                    int row = nt2*16 + ((g >> 1) << 3) + (lane & 7);
                    uint32_t kh[4];
                    LDSM_X4(kh, qkb + 10240 + (uint32_t)row*80 + c_off);
                    mma16816h(acc_s[2*nt2],   qf, kh[0], kh[1]);
                    mma16816h(acc_s[2*nt2+1], qf, kh[2], kh[3]);
                }
            }
        }

        // ---- softmax (register-resident); P as single fp16 ----
        float mnew[2] = {-1e30f, -1e30f};
        #pragma unroll
        for (int nt = 0; nt < 16; nt++)
            #pragma unroll
            for (int e = 0; e < 4; e++) {
                float s = acc_s[nt][e];
                float y = s * 0.00125f;
                float y2 = y * y;
                float capped = s * 0.0625f * (1.0f - y2*(0.33333333f - y2*0.13333333f));
                acc_s[nt][e] = capped;
                mnew[e >> 1] = fmaxf(mnew[e >> 1], capped);
            }
        #pragma unroll
        for (int o = 1; o <= 2; o <<= 1) {
            mnew[0] = fmaxf(mnew[0], __shfl_xor_sync(0xFFFFFFFFu, mnew[0], o));
            mnew[1] = fmaxf(mnew[1], __shfl_xor_sync(0xFFFFFFFFu, mnew[1], o));
        }
        float mt[2], al[2];
        #pragma unroll
        for (int j = 0; j < 2; j++) {
            mt[j] = fmaxf(rm[j], mnew[j]);
            al[j] = __expf(rm[j] - mt[j]);
            rm[j] = mt[j];
        }
        uint32_t ph[8][4];
        float sum[2] = {0.0f, 0.0f};
        #pragma unroll
        for (int g2 = 0; g2 < 8; g2++) {
            unsigned short hh[8];
            #pragma unroll
            for (int half = 0; half < 2; half++) {
                int nt = 2*g2 + half;
                #pragma unroll
                for (int e = 0; e < 4; e++) {
                    float p = __expf(acc_s[nt][e] - mt[e >> 1]);
                    sum[e >> 1] += p;
                    hh[half*4+e] = __half_as_ushort(__float2half_rn(p));
                }
            }
            ph[g2][0] = (uint32_t)hh[0] | ((uint32_t)hh[1] << 16);
            ph[g2][1] = (uint32_t)hh[2] | ((uint32_t)hh[3] << 16);
            ph[g2][2] = (uint32_t)hh[4] | ((uint32_t)hh[5] << 16);
            ph[g2][3] = (uint32_t)hh[6] | ((uint32_t)hh[7] << 16);
        }
        #pragma unroll
        for (int o = 1; o <= 2; o <<= 1) {
            sum[0] += __shfl_xor_sync(0xFFFFFFFFu, sum[0], o);
            sum[1] += __shfl_xor_sync(0xFFFFFFFFu, sum[1], o);
        }
        rl[0] = rl[0]*al[0] + sum[0];
        rl[1] = rl[1]*al[1] + sum[1];
        #pragma unroll
        for (int nt = 0; nt < 32; nt++)
            #pragma unroll
            for (int e = 0; e < 4; e++) acc_o[nt][e] *= al[e >> 1];

        // ---- PV phase: pure fp16 1-product ----
        for (int sl = 0; sl < 4; sl++) {
            cp_wait<0>();
            __syncthreads();
            if (sl < 3)       fl_load_v(V, s0, sl+1, sb + FL_V_BASE + (uint32_t)((sl+1)&1)*FL_V_STAGE);
            else if (kt < 15) fl_load_qk(Q, Kh, s0 + 128, 0, sb);
            cp_commit();
            const uint32_t vb = sb + FL_V_BASE + (uint32_t)(sl & 1) * FL_V_STAGE;
            #pragma unroll
            for (int kk = 0; kk < 2; kk++) {
                const int g2 = sl*2 + kk;
                int g = lane >> 3;
                uint32_t c_off = (uint32_t)kk*32 + ((g & 1) << 4);
                #pragma unroll
                for (int nt2 = 0; nt2 < 16; nt2++) {
                    int row = nt2*16 + ((g >> 1) << 3) + (lane & 7);
                    uint32_t vh[4];
                    LDSM_X4(vh, vb + (uint32_t)row*80 + c_off);
                    mma16816h(acc_o[2*nt2],   ph[g2], vh[0], vh[1]);
                    mma16816h(acc_o[2*nt2+1], ph[g2], vh[2], vh[3]);
                }
            }
        }
    }

    // ---- epilogue: normalize + single fp16 store ----
    float inv[2] = {1.0f / rl[0], 1.0f / rl[1]};
    #pragma unroll
    for (int nt = 0; nt < 32; nt++)
        #pragma unroll
        for (int j = 0; j < 2; j++) {
            int rloc = wid*16 + (lane >> 2) + j*8;
            size_t m = (size_t)b*SEQ + q0 + rloc;
            int d = nt*8 + (lane & 3)*2;
            size_t o = m*QDIM + h*HD + d;
            float v0 = acc_o[nt][2*j+0] * inv[j];
            float v1 = acc_o[nt][2*j+1] * inv[j];
            uint32_t pack = (uint32_t)__half_as_ushort(__float2half_rn(v0)) |
                            ((uint32_t)__half_as_ushort(__float2half_rn(v1)) << 16);
            *(uint32_t*)(g_ah + o) = pack;
        }
}

// ======================= launch ============================================
extern "C" void kernel_launch(void* const* d_in, const int* in_sizes, int n_in,
                              void* d_out, int out_size) {
    const float* hs = (const float*)d_in[0];
    const float* Wq = (const float*)d_in[1];
    const float* Wk = (const float*)d_in[2];
    const float* Wv = (const float*)d_in[3];
    const float* Wo = (const float*)d_in[4];
    float* out = (float*)d_out;
    (void)in_sizes; (void)n_in; (void)out_size;

    cudaFuncSetAttribute(g_proj,  cudaFuncAttributeMaxDynamicSharedMemorySize, G_DYN);
    cudaFuncSetAttribute(g_out,   cudaFuncAttributeMaxDynamicSharedMemorySize, G_DYN);
    cudaFuncSetAttribute(g_flash, cudaFuncAttributeMaxDynamicSharedMemorySize, FL_SMEM);

    // launch 1: fused fp16 conversion of all fp32 inputs
    k_split_all<<<N4_TOTAL/256, 256>>>((const float4*)hs, (const float4*)Wq,
                                       (const float4*)Wk, (const float4*)Wv,
                                       (const float4*)Wo);
    // launches 2-3: rope tables
    k_invfreq<<<1, 128>>>();
    k_ropetab<<<SEQ, 128>>>();

    // launch 4: fused QKV projection (profiled slot)
    g_proj<<<dim3(WPROWS/128, MTOT/128), 256, G_DYN>>>();

    // rope conversions + vT
    float *qf_p, *kf_p;
    cudaGetSymbolAddress((void**)&qf_p, g_qf);
    cudaGetSymbolAddress((void**)&kf_p, g_kf);
    __half *qh_p, *kh_p;
    cudaGetSymbolAddress((void**)&qh_p, g_qh);
    cudaGetSymbolAddress((void**)&kh_p, g_kh);
    k_rope_h<<<BATCH*NH*SEQ, 128>>>(qf_p, qh_p);
    k_rope_h<<<BATCH*NKV*SEQ, 128>>>(kf_p, kh_p);
    k_vT<<<dim3(HD/32, SEQ/32, BATCH*NKV), dim3(32, 32)>>>();

    // fused attention
    g_flash<<<dim3(SEQ/128, BATCH*NH), 256, FL_SMEM>>>();

    // output projection
    g_out<<<dim3(HIDDEN/128, MTOT/128), 256, G_DYN>>>(out);
}